// round 1
// baseline (speedup 1.0000x reference)
#include <cuda_runtime.h>
#include <math.h>

#define Lseq 2048
#define Dm   1024
#define Hh   16
#define HD   64
#define Pp   128
#define PPH  8
#define DA   80      // 64 content + 8 cos + 8 sin
#define CONTENT_SCALE 0.125f
#define PHASE_SCALE   0.35355339059327373f  // 1/sqrt(8)
#define NEG_BIG (-1e30f)

// ---------- scratch (static device globals; no allocation allowed) ----------
__device__ float g_Q[Lseq*Dm];
__device__ float g_K[Lseq*Dm];
__device__ float g_V[Lseq*Dm];
__device__ float g_Qt[Lseq*Pp];
__device__ float g_Kt[Lseq*Pp];
__device__ float g_Qa[Hh*Lseq*DA];
__device__ float g_Ka[Hh*Lseq*DA];
__device__ float g_AO[Lseq*Dm];
__device__ float g_P2[Lseq*Dm];

// ---------------------------------------------------------------------------
// Generic tiled fp32 GEMM: C[M,N] = A[M,K] @ B[K,N]. M = grid.y*64 (Lseq),
// BM=BN=64, BK=16, 256 threads, 4x4 micro-tile per thread.
// Requires M%64==0, N%64==0, K%16==0 (true for all uses here).
// ---------------------------------------------------------------------------
__global__ __launch_bounds__(256)
void gemm_kernel(const float* __restrict__ A, const float* __restrict__ B,
                 float* __restrict__ C, int N, int K) {
    __shared__ float As[16][68];   // stored transposed: As[k][row]
    __shared__ float Bs[16][68];   // Bs[k][col]
    const int tid = threadIdx.x;
    const int tx = tid & 15, ty = tid >> 4;
    const int rowBase = blockIdx.y * 64;
    const int colBase = blockIdx.x * 64;

    float acc[4][4];
#pragma unroll
    for (int i = 0; i < 4; i++)
#pragma unroll
        for (int j = 0; j < 4; j++) acc[i][j] = 0.f;

    for (int k0 = 0; k0 < K; k0 += 16) {
        // load A tile 64x16 (one float4 per thread), store transposed
        {
            int r = tid >> 2, kq = tid & 3;
            float4 v = *(const float4*)(A + (long)(rowBase + r) * K + k0 + kq * 4);
            As[kq*4+0][r] = v.x; As[kq*4+1][r] = v.y;
            As[kq*4+2][r] = v.z; As[kq*4+3][r] = v.w;
        }
        // load B tile 16x64 (one float4 per thread)
        {
            int r = tid >> 4, cq = tid & 15;
            float4 v = *(const float4*)(B + (long)(k0 + r) * N + colBase + cq * 4);
            *(float4*)&Bs[r][cq*4] = v;
        }
        __syncthreads();
#pragma unroll
        for (int k = 0; k < 16; k++) {
            float4 a = *(const float4*)&As[k][ty*4];
            float4 b = *(const float4*)&Bs[k][tx*4];
            float av[4] = {a.x, a.y, a.z, a.w};
            float bv[4] = {b.x, b.y, b.z, b.w};
#pragma unroll
            for (int i = 0; i < 4; i++)
#pragma unroll
                for (int j = 0; j < 4; j++) acc[i][j] += av[i] * bv[j];
        }
        __syncthreads();
    }
#pragma unroll
    for (int i = 0; i < 4; i++) {
        float4 v = make_float4(acc[i][0], acc[i][1], acc[i][2], acc[i][3]);
        *(float4*)(C + (long)(rowBase + ty*4 + i) * N + colBase + tx*4) = v;
    }
}

// ---------------------------------------------------------------------------
// Pack content part of augmented Q/K:  Qa[h][q][0..63], Ka[h][q][0..63]
// ---------------------------------------------------------------------------
__global__ __launch_bounds__(256)
void pack_content(const float* __restrict__ Q, const float* __restrict__ K,
                  const float* __restrict__ alogit,
                  float* __restrict__ Qa, float* __restrict__ Ka) {
    int idx = blockIdx.x * blockDim.x + threadIdx.x;
    if (idx >= Lseq * Dm) return;
    int q = idx / Dm, c = idx % Dm;
    int h = c / HD, d = c % HD;
    float alpha = 1.f / (1.f + expf(-alogit[h]));
    long base = ((long)h * Lseq + q) * DA;
    Qa[base + d] = (1.f - alpha) * CONTENT_SCALE * Q[idx];
    Ka[base + d] = K[idx];
}

// ---------------------------------------------------------------------------
// Phase pack: Qt/Kt -> cos/sin with bias + positional phase, scaled, into
// Qa[h][q][64..79], Ka[h][q][64..79]
// ---------------------------------------------------------------------------
__global__ __launch_bounds__(256)
void phase_pack(const float* __restrict__ Qt, const float* __restrict__ Kt,
                const float* __restrict__ bqp, const float* __restrict__ bkp,
                const float* __restrict__ alogit,
                float* __restrict__ Qa, float* __restrict__ Ka) {
    int idx = blockIdx.x * blockDim.x + threadIdx.x;
    if (idx >= Lseq * Pp) return;
    int q = idx / Pp, j = idx % Pp;
    int h = j / PPH, i = j % PPH;
    // inv_freq = 10000^(-(j/2)/64), computed in double for accuracy
    int f = j >> 1;
    double invf = exp(-(double)f / 64.0 * log(10000.0));
    float pos = (float)((double)q * invf);
    float tq = Qt[idx] + bqp[j] + pos;
    float tk = Kt[idx] + bkp[j] + pos;
    float alpha = 1.f / (1.f + expf(-alogit[h]));
    float aps = alpha * PHASE_SCALE;
    long base = ((long)h * Lseq + q) * DA;
    Qa[base + 64 + i] = aps * cosf(tq);
    Qa[base + 72 + i] = aps * sinf(tq);
    Ka[base + 64 + i] = cosf(tk);
    Ka[base + 72 + i] = sinf(tk);
}

// ---------------------------------------------------------------------------
// Flash attention over augmented d=80 features, causal.
// Grid: (Lseq/64, H). 256 threads; 4x4 micro-tiles.
// Output written to AO[q][h*64+c] (row-major L x D for the Wo GEMM).
// ---------------------------------------------------------------------------
#define ATTN_SMEM_FLOATS (2*DA*68 + 2*64*68 + 192)
__global__ __launch_bounds__(256)
void attn_kernel(const float* __restrict__ Qa, const float* __restrict__ Ka,
                 const float* __restrict__ V, float* __restrict__ Out) {
    extern __shared__ float sm[];
    float* Qs = sm;                 // [DA][68]  (transposed: [d][row])
    float* Ks = Qs + DA * 68;       // [DA][68]  ([d][key])
    float* St = Ks + DA * 68;       // [64][68]  transposed scores [key][row]
    float* Vs = St + 64 * 68;       // [64][68]  [key][col]
    float* Mr = Vs + 64 * 68;       // [64] running max
    float* Lr = Mr + 64;            // [64] running sum
    float* Rs = Lr + 64;            // [64] rescale factor

    const int tid = threadIdx.x;
    const int h = blockIdx.y;
    const int qt = gridDim.x - 1 - blockIdx.x;  // big tiles first (load balance)
    const int q0 = qt * 64;
    const int tx = tid & 15, ty = tid >> 4;
    const int r0 = ty * 4, c0 = tx * 4;

    for (int idx = tid; idx < 64 * DA; idx += 256) {
        int r = idx / DA, d = idx % DA;
        Qs[d * 68 + r] = Qa[((long)h * Lseq + q0 + r) * DA + d];
    }
    if (tid < 64) { Mr[tid] = NEG_BIG; Lr[tid] = 0.f; }

    float acc[4][4];
#pragma unroll
    for (int i = 0; i < 4; i++)
#pragma unroll
        for (int j = 0; j < 4; j++) acc[i][j] = 0.f;
    __syncthreads();

    for (int kt = 0; kt <= qt; kt++) {
        const int k0 = kt * 64;
        for (int idx = tid; idx < 64 * DA; idx += 256) {
            int r = idx / DA, d = idx % DA;
            Ks[d * 68 + r] = Ka[((long)h * Lseq + k0 + r) * DA + d];
        }
        for (int idx = tid; idx < 64 * 64; idx += 256) {
            int r = idx >> 6, c = idx & 63;
            Vs[r * 68 + c] = V[(long)(k0 + r) * Dm + h * HD + c];
        }
        __syncthreads();

        // S = Qa_tile @ Ka_tile^T  (d = 80)
        float s[4][4];
#pragma unroll
        for (int i = 0; i < 4; i++)
#pragma unroll
            for (int j = 0; j < 4; j++) s[i][j] = 0.f;
        for (int d = 0; d < DA; d++) {
            float4 a = *(const float4*)&Qs[d * 68 + r0];
            float4 b = *(const float4*)&Ks[d * 68 + c0];
            float av[4] = {a.x, a.y, a.z, a.w};
            float bv[4] = {b.x, b.y, b.z, b.w};
#pragma unroll
            for (int i = 0; i < 4; i++)
#pragma unroll
                for (int j = 0; j < 4; j++) s[i][j] += av[i] * bv[j];
        }
        const bool last = (kt == qt);
#pragma unroll
        for (int i = 0; i < 4; i++)
#pragma unroll
            for (int j = 0; j < 4; j++) {
                float v = s[i][j];
                if (last && (c0 + j) > (r0 + i)) v = NEG_BIG;
                St[(c0 + j) * 68 + (r0 + i)] = v;
            }
        __syncthreads();

        // online softmax, one row per thread (threads 0..63)
        if (tid < 64) {
            const int r = tid;
            float mold = Mr[r];
            float mx = mold;
            for (int k = 0; k < 64; k++) mx = fmaxf(mx, St[k * 68 + r]);
            float scale = __expf(mold - mx);
            float sum = 0.f;
            for (int k = 0; k < 64; k++) {
                float p = __expf(St[k * 68 + r] - mx);
                St[k * 68 + r] = p;
                sum += p;
            }
            Mr[r] = mx;
            Lr[r] = Lr[r] * scale + sum;
            Rs[r] = scale;
        }
        __syncthreads();

        // O = O*rescale + P @ V
        float rsc[4];
#pragma unroll
        for (int i = 0; i < 4; i++) rsc[i] = Rs[r0 + i];
#pragma unroll
        for (int i = 0; i < 4; i++)
#pragma unroll
            for (int j = 0; j < 4; j++) acc[i][j] *= rsc[i];
        for (int k = 0; k < 64; k++) {
            float4 p = *(const float4*)&St[k * 68 + r0];
            float4 v = *(const float4*)&Vs[k * 68 + c0];
            float pv[4] = {p.x, p.y, p.z, p.w};
            float vv[4] = {v.x, v.y, v.z, v.w};
#pragma unroll
            for (int i = 0; i < 4; i++)
#pragma unroll
                for (int j = 0; j < 4; j++) acc[i][j] += pv[i] * vv[j];
        }
        __syncthreads();
    }

#pragma unroll
    for (int i = 0; i < 4; i++) {
        float inv = 1.f / Lr[r0 + i];
        float4 v = make_float4(acc[i][0]*inv, acc[i][1]*inv, acc[i][2]*inv, acc[i][3]*inv);
        *(float4*)(Out + (long)(q0 + r0 + i) * Dm + h * HD + c0) = v;
    }
}

// ---------------------------------------------------------------------------
// Residual + LayerNorm. One block per row.
// ---------------------------------------------------------------------------
__global__ __launch_bounds__(256)
void ln_kernel(const float* __restrict__ xr, const float* __restrict__ proj,
               const float* __restrict__ gamma, const float* __restrict__ beta,
               float* __restrict__ out) {
    const int row = blockIdx.x;
    const int tid = threadIdx.x;
    __shared__ float red[2][8];
    const float* a = xr + (long)row * Dm;
    const float* b = proj + (long)row * Dm;
    float s = 0.f, s2 = 0.f;
    for (int i = tid; i < Dm; i += 256) {
        float v = a[i] + b[i];
        s += v; s2 += v * v;
    }
#pragma unroll
    for (int o = 16; o; o >>= 1) {
        s  += __shfl_xor_sync(0xffffffffu, s,  o);
        s2 += __shfl_xor_sync(0xffffffffu, s2, o);
    }
    if ((tid & 31) == 0) { red[0][tid >> 5] = s; red[1][tid >> 5] = s2; }
    __syncthreads();
    if (tid < 32) {
        s  = (tid < 8) ? red[0][tid] : 0.f;
        s2 = (tid < 8) ? red[1][tid] : 0.f;
#pragma unroll
        for (int o = 4; o; o >>= 1) {
            s  += __shfl_xor_sync(0xffffffffu, s,  o);
            s2 += __shfl_xor_sync(0xffffffffu, s2, o);
        }
        if (tid == 0) { red[0][0] = s; red[1][0] = s2; }
    }
    __syncthreads();
    float mu = red[0][0] * (1.f / Dm);
    float var = red[1][0] * (1.f / Dm) - mu * mu;
    float rstd = rsqrtf(var + 1e-5f);
    for (int i = tid; i < Dm; i += 256) {
        float v = a[i] + b[i];
        out[(long)row * Dm + i] = (v - mu) * rstd * gamma[i] + beta[i];
    }
}

// ---------------------------------------------------------------------------
extern "C" void kernel_launch(void* const* d_in, const int* in_sizes, int n_in,
                              void* d_out, int out_size) {
    const float* x_real = (const float*)d_in[0];
    const float* x_imag = (const float*)d_in[1];
    const float* Wq     = (const float*)d_in[2];
    const float* Wk     = (const float*)d_in[3];
    const float* Wv     = (const float*)d_in[4];
    const float* Wqp    = (const float*)d_in[5];
    const float* bqp    = (const float*)d_in[6];
    const float* Wkp    = (const float*)d_in[7];
    const float* bkp    = (const float*)d_in[8];
    const float* Wo     = (const float*)d_in[9];
    const float* alogit = (const float*)d_in[10];
    const float* lng    = (const float*)d_in[11];
    const float* lnb    = (const float*)d_in[12];

    float *pQ, *pK, *pV, *pQt, *pKt, *pQa, *pKa, *pAO, *pP2;
    cudaGetSymbolAddress((void**)&pQ,  g_Q);
    cudaGetSymbolAddress((void**)&pK,  g_K);
    cudaGetSymbolAddress((void**)&pV,  g_V);
    cudaGetSymbolAddress((void**)&pQt, g_Qt);
    cudaGetSymbolAddress((void**)&pKt, g_Kt);
    cudaGetSymbolAddress((void**)&pQa, g_Qa);
    cudaGetSymbolAddress((void**)&pKa, g_Ka);
    cudaGetSymbolAddress((void**)&pAO, g_AO);
    cudaGetSymbolAddress((void**)&pP2, g_P2);

    dim3 gBig(Dm / 64, Lseq / 64);   // (16, 32)
    dim3 gPh(Pp / 64, Lseq / 64);    // (2, 32)

    gemm_kernel<<<gBig, 256>>>(x_real, Wq, pQ, Dm, Dm);
    gemm_kernel<<<gBig, 256>>>(x_real, Wk, pK, Dm, Dm);
    gemm_kernel<<<gBig, 256>>>(x_real, Wv, pV, Dm, Dm);
    gemm_kernel<<<gPh, 256>>>(x_imag, Wqp, pQt, Pp, Dm);
    gemm_kernel<<<gPh, 256>>>(x_imag, Wkp, pKt, Pp, Dm);

    pack_content<<<(Lseq * Dm) / 256, 256>>>(pQ, pK, alogit, pQa, pKa);
    phase_pack<<<(Lseq * Pp) / 256, 256>>>(pQt, pKt, bqp, bkp, alogit, pQa, pKa);

    const int smemBytes = ATTN_SMEM_FLOATS * (int)sizeof(float);
    cudaFuncSetAttribute(attn_kernel, cudaFuncAttributeMaxDynamicSharedMemorySize, smemBytes);
    attn_kernel<<<dim3(Lseq / 64, Hh), 256, smemBytes>>>(pQa, pKa, pV, pAO);

    gemm_kernel<<<gBig, 256>>>(pAO, Wo, pP2, Dm, Dm);
    ln_kernel<<<Lseq, 256>>>(x_real, pP2, lng, lnb, (float*)d_out);

    if (out_size >= 2 * Lseq * Dm) {
        cudaMemcpyAsync((float*)d_out + (long)Lseq * Dm, x_imag,
                        (size_t)Lseq * Dm * sizeof(float),
                        cudaMemcpyDeviceToDevice);
    }
}

// round 4
// speedup vs baseline: 1.1982x; 1.1982x over previous
#include <cuda_runtime.h>
#include <cuda_bf16.h>
#include <math.h>
#include <stdint.h>

#define Lseq 2048
#define Dm   1024
#define Hh   16
#define HD   64
#define Pp   128
#define PPH  8
#define DA   80
#define KP   3072      // K' = 3*1024 for bf16x3 trick
#define CONTENT_SCALE 0.125f
#define PHASE_SCALE   0.35355339059327373f
#define NEG_BIG (-1e30f)

// ---------------- scratch (static device globals) ----------------
__device__ float g_Q[Lseq*Dm];
__device__ float g_K[Lseq*Dm];
__device__ float g_V[Lseq*Dm];
__device__ float g_Qt[Lseq*Pp];
__device__ float g_Kt[Lseq*Pp];
__device__ float g_Qa[Hh*Lseq*DA];
__device__ float g_Ka[Hh*Lseq*DA];
__device__ float g_AO[Lseq*Dm];
__device__ float g_P2[Lseq*Dm];
// bf16x3 packed operands
__device__ __nv_bfloat16 g_Ab [Lseq*KP];
__device__ __nv_bfloat16 g_Aib[Lseq*KP];
__device__ __nv_bfloat16 g_AOb[Lseq*KP];
__device__ __nv_bfloat16 g_Bq [Dm*KP];
__device__ __nv_bfloat16 g_Bk [Dm*KP];
__device__ __nv_bfloat16 g_Bv [Dm*KP];
__device__ __nv_bfloat16 g_Bo [Dm*KP];
__device__ __nv_bfloat16 g_Bqp[Pp*KP];
__device__ __nv_bfloat16 g_Bkp[Pp*KP];

// ---------------- helpers ----------------
__device__ __forceinline__ uint32_t smem_u32(const void* p) {
    uint32_t a;
    asm("{ .reg .u64 t; cvta.to.shared.u64 t, %1; cvt.u32.u64 %0, t; }" : "=r"(a) : "l"(p));
    return a;
}
__device__ __forceinline__ void ldsm_x4(uint32_t& r0, uint32_t& r1, uint32_t& r2,
                                        uint32_t& r3, uint32_t addr) {
    asm volatile("ldmatrix.sync.aligned.m8n8.x4.shared.b16 {%0,%1,%2,%3}, [%4];"
                 : "=r"(r0), "=r"(r1), "=r"(r2), "=r"(r3) : "r"(addr));
}
__device__ __forceinline__ void mma_bf16(float* c, uint32_t a0, uint32_t a1,
                                         uint32_t a2, uint32_t a3,
                                         uint32_t b0, uint32_t b1) {
    asm volatile(
        "mma.sync.aligned.m16n8k16.row.col.f32.bf16.bf16.f32 "
        "{%0,%1,%2,%3}, {%4,%5,%6,%7}, {%8,%9}, {%0,%1,%2,%3};"
        : "+f"(c[0]), "+f"(c[1]), "+f"(c[2]), "+f"(c[3])
        : "r"(a0), "r"(a1), "r"(a2), "r"(a3), "r"(b0), "r"(b1));
}

// ---------------------------------------------------------------------------
// bf16x3 pack of activation X[M][1024] -> out[M][3072] = [hi | lo | hi]
// ---------------------------------------------------------------------------
__global__ __launch_bounds__(256)
void conv_a(const float* __restrict__ X, __nv_bfloat16* __restrict__ out) {
    int idx = blockIdx.x * 256 + threadIdx.x;
    if (idx >= Lseq * Dm) return;
    int m = idx >> 10, k = idx & 1023;
    float v = X[idx];
    __nv_bfloat16 hi = __float2bfloat16(v);
    __nv_bfloat16 lo = __float2bfloat16(v - __bfloat162float(hi));
    size_t r = (size_t)m * KP;
    out[r + k] = hi;
    out[r + 1024 + k] = lo;
    out[r + 2048 + k] = hi;
}
// ---------------------------------------------------------------------------
// bf16x3 pack+transpose of weight W[1024][N] -> out[N][3072] = [hi | hi | lo]
// ---------------------------------------------------------------------------
__global__ __launch_bounds__(256)
void conv_b(const float* __restrict__ W, __nv_bfloat16* __restrict__ out, int N) {
    __shared__ float t[32][33];
    int k0 = blockIdx.y * 32, n0 = blockIdx.x * 32;
    int tx = threadIdx.x & 31, ty = threadIdx.x >> 5;
#pragma unroll
    for (int i = 0; i < 32; i += 8)
        t[ty + i][tx] = W[(size_t)(k0 + ty + i) * N + n0 + tx];
    __syncthreads();
#pragma unroll
    for (int i = 0; i < 32; i += 8) {
        float v = t[tx][ty + i];
        __nv_bfloat16 hi = __float2bfloat16(v);
        __nv_bfloat16 lo = __float2bfloat16(v - __bfloat162float(hi));
        size_t r = (size_t)(n0 + ty + i) * KP;
        out[r + k0 + tx] = hi;
        out[r + 1024 + k0 + tx] = hi;
        out[r + 2048 + k0 + tx] = lo;
    }
}

// ---------------------------------------------------------------------------
// mma.sync bf16 GEMM: C[M, N] = A'[M, 3072] @ B'[N, 3072]^T (fp32 accum).
// CTA tile 128x128, BK=32, 8 warps (2x4), warp tile 64x32.
// Smem stride 40 bf16 (80B) -> conflict-free ldmatrix (r*5 mod 8 bijective).
// ---------------------------------------------------------------------------
#define LDA 40
__global__ __launch_bounds__(256, 2)
void tgemm(const __nv_bfloat16* __restrict__ A, const __nv_bfloat16* __restrict__ B,
           float* __restrict__ C, int N) {
    __shared__ __align__(16) __nv_bfloat16 As[2][128 * LDA];
    __shared__ __align__(16) __nv_bfloat16 Bs[2][128 * LDA];

    const int tid = threadIdx.x;
    const int wid = tid >> 5, lane = tid & 31;
    const int m0 = blockIdx.y * 128, n0 = blockIdx.x * 128;
    const int wm = (wid >> 2) * 64, wn = (wid & 3) * 32;

    // global load mapping: thread -> row = tid/2, 32B half = (tid&1)*16 bf16
    const int lr = tid >> 1, lc = (tid & 1) * 16;
    const __nv_bfloat16* Ag = A + (size_t)(m0 + lr) * KP + lc;
    const __nv_bfloat16* Bg = B + (size_t)(n0 + lr) * KP + lc;
    const int soff = lr * LDA + lc;

    float acc[4][4][4];
#pragma unroll
    for (int i = 0; i < 4; i++)
#pragma unroll
        for (int j = 0; j < 4; j++)
#pragma unroll
            for (int k = 0; k < 4; k++) acc[i][j][k] = 0.f;

    // preload tile 0 (full 32 bf16 per row: two uint4 per thread per array)
    *(uint4*)&As[0][soff]     = *(const uint4*)(Ag);
    *(uint4*)&As[0][soff + 8] = *(const uint4*)(Ag + 8);
    *(uint4*)&Bs[0][soff]     = *(const uint4*)(Bg);
    *(uint4*)&Bs[0][soff + 8] = *(const uint4*)(Bg + 8);
    __syncthreads();

    // ldmatrix lane addressing
    const int a_row = (lane & 15);                      // + mt*16 + wm
    const int a_koff = (lane >> 4) * 8;
    const int b_row = (lane & 7) + ((lane & 16) >> 1);  // + nt2*16 + wn
    const int b_koff = ((lane >> 3) & 1) * 8;

    const int NKT = KP / 32;                 // 96
    for (int kt = 0; kt < NKT; kt++) {
        const int cur = kt & 1;
        uint4 ra0, ra1, rb0, rb1;
        if (kt < NKT - 1) {
            const __nv_bfloat16* An = Ag + (size_t)(kt + 1) * 32;
            const __nv_bfloat16* Bn = Bg + (size_t)(kt + 1) * 32;
            ra0 = *(const uint4*)(An);
            ra1 = *(const uint4*)(An + 8);
            rb0 = *(const uint4*)(Bn);
            rb1 = *(const uint4*)(Bn + 8);
        }
        const uint32_t aBase = smem_u32(&As[cur][0]);
        const uint32_t bBase = smem_u32(&Bs[cur][0]);
#pragma unroll
        for (int ks = 0; ks < 2; ks++) {
            const int k0 = ks * 16;
            uint32_t af[4][4];
#pragma unroll
            for (int mt = 0; mt < 4; mt++) {
                uint32_t ad = aBase + ((wm + mt * 16 + a_row) * LDA + k0 + a_koff) * 2;
                ldsm_x4(af[mt][0], af[mt][1], af[mt][2], af[mt][3], ad);
            }
            uint32_t bf[2][4];
#pragma unroll
            for (int nt2 = 0; nt2 < 2; nt2++) {
                uint32_t bd = bBase + ((wn + nt2 * 16 + b_row) * LDA + k0 + b_koff) * 2;
                ldsm_x4(bf[nt2][0], bf[nt2][1], bf[nt2][2], bf[nt2][3], bd);
            }
#pragma unroll
            for (int mt = 0; mt < 4; mt++)
#pragma unroll
                for (int nt = 0; nt < 4; nt++)
                    mma_bf16(acc[mt][nt], af[mt][0], af[mt][1], af[mt][2], af[mt][3],
                             bf[nt >> 1][(nt & 1) * 2], bf[nt >> 1][(nt & 1) * 2 + 1]);
        }
        // store next tile to the other buffer (safe: reads of that buffer ended
        // before the previous iteration's barrier), then ONE barrier.
        if (kt < NKT - 1) {
            *(uint4*)&As[cur ^ 1][soff]     = ra0;
            *(uint4*)&As[cur ^ 1][soff + 8] = ra1;
            *(uint4*)&Bs[cur ^ 1][soff]     = rb0;
            *(uint4*)&Bs[cur ^ 1][soff + 8] = rb1;
            __syncthreads();
        }
    }

    // epilogue: thread holds (r=lane/4, c=(lane&3)*2) within each 16x8 tile
    const int er = lane >> 2, ec = (lane & 3) * 2;
#pragma unroll
    for (int mt = 0; mt < 4; mt++) {
        const int row = m0 + wm + mt * 16 + er;
#pragma unroll
        for (int nt = 0; nt < 4; nt++) {
            const int col = n0 + wn + nt * 8 + ec;
            *(float2*)&C[(size_t)row * N + col] =
                make_float2(acc[mt][nt][0], acc[mt][nt][1]);
            *(float2*)&C[(size_t)(row + 8) * N + col] =
                make_float2(acc[mt][nt][2], acc[mt][nt][3]);
        }
    }
}

// ---------------------------------------------------------------------------
__global__ __launch_bounds__(256)
void pack_content(const float* __restrict__ Q, const float* __restrict__ K,
                  const float* __restrict__ alogit,
                  float* __restrict__ Qa, float* __restrict__ Ka) {
    int idx = blockIdx.x * blockDim.x + threadIdx.x;
    if (idx >= Lseq * Dm) return;
    int q = idx / Dm, c = idx % Dm;
    int h = c / HD, d = c % HD;
    float alpha = 1.f / (1.f + expf(-alogit[h]));
    long base = ((long)h * Lseq + q) * DA;
    Qa[base + d] = (1.f - alpha) * CONTENT_SCALE * Q[idx];
    Ka[base + d] = K[idx];
}

__global__ __launch_bounds__(256)
void phase_pack(const float* __restrict__ Qt, const float* __restrict__ Kt,
                const float* __restrict__ bqp, const float* __restrict__ bkp,
                const float* __restrict__ alogit,
                float* __restrict__ Qa, float* __restrict__ Ka) {
    int idx = blockIdx.x * blockDim.x + threadIdx.x;
    if (idx >= Lseq * Pp) return;
    int q = idx / Pp, j = idx % Pp;
    int h = j / PPH, i = j % PPH;
    int f = j >> 1;
    double invf = exp(-(double)f / 64.0 * log(10000.0));
    float pos = (float)((double)q * invf);
    float tq = Qt[idx] + bqp[j] + pos;
    float tk = Kt[idx] + bkp[j] + pos;
    float alpha = 1.f / (1.f + expf(-alogit[h]));
    float aps = alpha * PHASE_SCALE;
    long base = ((long)h * Lseq + q) * DA;
    Qa[base + 64 + i] = aps * cosf(tq);
    Qa[base + 72 + i] = aps * sinf(tq);
    Ka[base + 64 + i] = cosf(tk);
    Ka[base + 72 + i] = sinf(tk);
}

// ---------------------------------------------------------------------------
// Flash attention, augmented d=80, causal (fp32 SIMT; next-round target)
// ---------------------------------------------------------------------------
#define ATTN_SMEM_FLOATS (2*DA*68 + 2*64*68 + 192)
__global__ __launch_bounds__(256)
void attn_kernel(const float* __restrict__ Qa, const float* __restrict__ Ka,
                 const float* __restrict__ V, float* __restrict__ Out) {
    extern __shared__ float sm[];
    float* Qs = sm;
    float* Ks = Qs + DA * 68;
    float* St = Ks + DA * 68;
    float* Vs = St + 64 * 68;
    float* Mr = Vs + 64 * 68;
    float* Lr = Mr + 64;
    float* Rs = Lr + 64;

    const int tid = threadIdx.x;
    const int h = blockIdx.y;
    const int qt = gridDim.x - 1 - blockIdx.x;
    const int q0 = qt * 64;
    const int tx = tid & 15, ty = tid >> 4;
    const int r0 = ty * 4, c0 = tx * 4;

    for (int idx = tid; idx < 64 * DA; idx += 256) {
        int r = idx / DA, d = idx % DA;
        Qs[d * 68 + r] = Qa[((long)h * Lseq + q0 + r) * DA + d];
    }
    if (tid < 64) { Mr[tid] = NEG_BIG; Lr[tid] = 0.f; }

    float acc[4][4];
#pragma unroll
    for (int i = 0; i < 4; i++)
#pragma unroll
        for (int j = 0; j < 4; j++) acc[i][j] = 0.f;
    __syncthreads();

    for (int kt = 0; kt <= qt; kt++) {
        const int k0 = kt * 64;
        for (int idx = tid; idx < 64 * DA; idx += 256) {
            int r = idx / DA, d = idx % DA;
            Ks[d * 68 + r] = Ka[((long)h * Lseq + k0 + r) * DA + d];
        }
        for (int idx = tid; idx < 64 * 64; idx += 256) {
            int r = idx >> 6, c = idx & 63;
            Vs[r * 68 + c] = V[(long)(k0 + r) * Dm + h * HD + c];
        }
        __syncthreads();

        float s[4][4];
#pragma unroll
        for (int i = 0; i < 4; i++)
#pragma unroll
            for (int j = 0; j < 4; j++) s[i][j] = 0.f;
        for (int d = 0; d < DA; d++) {
            float4 a = *(const float4*)&Qs[d * 68 + r0];
            float4 b = *(const float4*)&Ks[d * 68 + c0];
            float av[4] = {a.x, a.y, a.z, a.w};
            float bv[4] = {b.x, b.y, b.z, b.w};
#pragma unroll
            for (int i = 0; i < 4; i++)
#pragma unroll
                for (int j = 0; j < 4; j++) s[i][j] += av[i] * bv[j];
        }
        const bool last = (kt == qt);
#pragma unroll
        for (int i = 0; i < 4; i++)
#pragma unroll
            for (int j = 0; j < 4; j++) {
                float v = s[i][j];
                if (last && (c0 + j) > (r0 + i)) v = NEG_BIG;
                St[(c0 + j) * 68 + (r0 + i)] = v;
            }
        __syncthreads();

        if (tid < 64) {
            const int r = tid;
            float mold = Mr[r];
            float mx = mold;
            for (int k = 0; k < 64; k++) mx = fmaxf(mx, St[k * 68 + r]);
            float scale = __expf(mold - mx);
            float sum = 0.f;
            for (int k = 0; k < 64; k++) {
                float p = __expf(St[k * 68 + r] - mx);
                St[k * 68 + r] = p;
                sum += p;
            }
            Mr[r] = mx;
            Lr[r] = Lr[r] * scale + sum;
            Rs[r] = scale;
        }
        __syncthreads();

        float rsc[4];
#pragma unroll
        for (int i = 0; i < 4; i++) rsc[i] = Rs[r0 + i];
#pragma unroll
        for (int i = 0; i < 4; i++)
#pragma unroll
            for (int j = 0; j < 4; j++) acc[i][j] *= rsc[i];
        for (int k = 0; k < 64; k++) {
            float4 p = *(const float4*)&St[k * 68 + r0];
            float4 v = *(const float4*)&Vs[k * 68 + c0];
            float pv[4] = {p.x, p.y, p.z, p.w};
            float vv[4] = {v.x, v.y, v.z, v.w};
#pragma unroll
            for (int i = 0; i < 4; i++)
#pragma unroll
                for (int j = 0; j < 4; j++) acc[i][j] += pv[i] * vv[j];
        }
        __syncthreads();
    }

#pragma unroll
    for (int i = 0; i < 4; i++) {
        float inv = 1.f / Lr[r0 + i];
        float4 v = make_float4(acc[i][0]*inv, acc[i][1]*inv, acc[i][2]*inv, acc[i][3]*inv);
        *(float4*)(Out + (long)(q0 + r0 + i) * Dm + h * HD + c0) = v;
    }
}

// ---------------------------------------------------------------------------
__global__ __launch_bounds__(256)
void ln_kernel(const float* __restrict__ xr, const float* __restrict__ proj,
               const float* __restrict__ gamma, const float* __restrict__ beta,
               float* __restrict__ out) {
    const int row = blockIdx.x;
    const int tid = threadIdx.x;
    __shared__ float red[2][8];
    const float* a = xr + (long)row * Dm;
    const float* b = proj + (long)row * Dm;
    float s = 0.f, s2 = 0.f;
    for (int i = tid; i < Dm; i += 256) {
        float v = a[i] + b[i];
        s += v; s2 += v * v;
    }
#pragma unroll
    for (int o = 16; o; o >>= 1) {
        s  += __shfl_xor_sync(0xffffffffu, s,  o);
        s2 += __shfl_xor_sync(0xffffffffu, s2, o);
    }
    if ((tid & 31) == 0) { red[0][tid >> 5] = s; red[1][tid >> 5] = s2; }
    __syncthreads();
    if (tid < 32) {
        s  = (tid < 8) ? red[0][tid] : 0.f;
        s2 = (tid < 8) ? red[1][tid] : 0.f;
#pragma unroll
        for (int o = 4; o; o >>= 1) {
            s  += __shfl_xor_sync(0xffffffffu, s,  o);
            s2 += __shfl_xor_sync(0xffffffffu, s2, o);
        }
        if (tid == 0) { red[0][0] = s; red[1][0] = s2; }
    }
    __syncthreads();
    float mu = red[0][0] * (1.f / Dm);
    float var = red[1][0] * (1.f / Dm) - mu * mu;
    float rstd = rsqrtf(var + 1e-5f);
    for (int i = tid; i < Dm; i += 256) {
        float v = a[i] + b[i];
        out[(long)row * Dm + i] = (v - mu) * rstd * gamma[i] + beta[i];
    }
}

// ---------------------------------------------------------------------------
extern "C" void kernel_launch(void* const* d_in, const int* in_sizes, int n_in,
                              void* d_out, int out_size) {
    const float* x_real = (const float*)d_in[0];
    const float* x_imag = (const float*)d_in[1];
    const float* Wq     = (const float*)d_in[2];
    const float* Wk     = (const float*)d_in[3];
    const float* Wv     = (const float*)d_in[4];
    const float* Wqp    = (const float*)d_in[5];
    const float* bqp    = (const float*)d_in[6];
    const float* Wkp    = (const float*)d_in[7];
    const float* bkp    = (const float*)d_in[8];
    const float* Wo     = (const float*)d_in[9];
    const float* alogit = (const float*)d_in[10];
    const float* lng    = (const float*)d_in[11];
    const float* lnb    = (const float*)d_in[12];

    float *pQ, *pK, *pV, *pQt, *pKt, *pQa, *pKa, *pAO, *pP2;
    __nv_bfloat16 *pAb, *pAib, *pAOb, *pBq, *pBk, *pBv, *pBo, *pBqp, *pBkp;
    cudaGetSymbolAddress((void**)&pQ,  g_Q);
    cudaGetSymbolAddress((void**)&pK,  g_K);
    cudaGetSymbolAddress((void**)&pV,  g_V);
    cudaGetSymbolAddress((void**)&pQt, g_Qt);
    cudaGetSymbolAddress((void**)&pKt, g_Kt);
    cudaGetSymbolAddress((void**)&pQa, g_Qa);
    cudaGetSymbolAddress((void**)&pKa, g_Ka);
    cudaGetSymbolAddress((void**)&pAO, g_AO);
    cudaGetSymbolAddress((void**)&pP2, g_P2);
    cudaGetSymbolAddress((void**)&pAb,  g_Ab);
    cudaGetSymbolAddress((void**)&pAib, g_Aib);
    cudaGetSymbolAddress((void**)&pAOb, g_AOb);
    cudaGetSymbolAddress((void**)&pBq,  g_Bq);
    cudaGetSymbolAddress((void**)&pBk,  g_Bk);
    cudaGetSymbolAddress((void**)&pBv,  g_Bv);
    cudaGetSymbolAddress((void**)&pBo,  g_Bo);
    cudaGetSymbolAddress((void**)&pBqp, g_Bqp);
    cudaGetSymbolAddress((void**)&pBkp, g_Bkp);

    // pack activations & weights into bf16x3
    conv_a<<<(Lseq * Dm) / 256, 256>>>(x_real, pAb);
    conv_a<<<(Lseq * Dm) / 256, 256>>>(x_imag, pAib);
    dim3 cbg(Dm / 32, Dm / 32);
    conv_b<<<cbg, 256>>>(Wq, pBq, Dm);
    conv_b<<<cbg, 256>>>(Wk, pBk, Dm);
    conv_b<<<cbg, 256>>>(Wv, pBv, Dm);
    conv_b<<<cbg, 256>>>(Wo, pBo, Dm);
    dim3 cbp(Pp / 32, Dm / 32);
    conv_b<<<cbp, 256>>>(Wqp, pBqp, Pp);
    conv_b<<<cbp, 256>>>(Wkp, pBkp, Pp);

    // tensor-core GEMMs (mma.sync bf16)
    dim3 gBig(Dm / 128, Lseq / 128);   // (8, 16)
    dim3 gPh(Pp / 128, Lseq / 128);    // (1, 16)
    tgemm<<<gBig, 256>>>(pAb,  pBq,  pQ,  Dm);
    tgemm<<<gBig, 256>>>(pAb,  pBk,  pK,  Dm);
    tgemm<<<gBig, 256>>>(pAb,  pBv,  pV,  Dm);
    tgemm<<<gPh,  256>>>(pAib, pBqp, pQt, Pp);
    tgemm<<<gPh,  256>>>(pAib, pBkp, pKt, Pp);

    pack_content<<<(Lseq * Dm) / 256, 256>>>(pQ, pK, alogit, pQa, pKa);
    phase_pack<<<(Lseq * Pp) / 256, 256>>>(pQt, pKt, bqp, bkp, alogit, pQa, pKa);

    const int smemBytes = ATTN_SMEM_FLOATS * (int)sizeof(float);
    cudaFuncSetAttribute(attn_kernel, cudaFuncAttributeMaxDynamicSharedMemorySize, smemBytes);
    attn_kernel<<<dim3(Lseq / 64, Hh), 256, smemBytes>>>(pQa, pKa, pV, pAO);

    conv_a<<<(Lseq * Dm) / 256, 256>>>(pAO, pAOb);
    tgemm<<<gBig, 256>>>(pAOb, pBo, pP2, Dm);
    ln_kernel<<<Lseq, 256>>>(x_real, pP2, lng, lnb, (float*)d_out);

    if (out_size >= 2 * Lseq * Dm) {
        cudaMemcpyAsync((float*)d_out + (long)Lseq * Dm, x_imag,
                        (size_t)Lseq * Dm * sizeof(float),
                        cudaMemcpyDeviceToDevice);
    }
}

// round 5
// speedup vs baseline: 1.3798x; 1.1516x over previous
#include <cuda_runtime.h>
#include <cuda_bf16.h>
#include <math.h>
#include <stdint.h>

#define Lseq 2048
#define Dm   1024
#define Hh   16
#define HD   64
#define Pp   128
#define PPH  8
#define DA   80
#define KQ3  240       // 3*80, bf16x3 augmented dim
#define KP   3072      // 3*1024 for projection GEMMs
#define CONTENT_SCALE 0.125f
#define PHASE_SCALE   0.35355339059327373f
#define NEG_BIG (-1e30f)

// ---------------- scratch (static device globals) ----------------
__device__ float g_Q[Lseq*Dm];
__device__ float g_K[Lseq*Dm];
__device__ float g_V[Lseq*Dm];
__device__ float g_Qt[Lseq*Pp];
__device__ float g_Kt[Lseq*Pp];
__device__ float g_AO[Lseq*Dm];
__device__ float g_P2[Lseq*Dm];
// bf16x3 packed GEMM operands
__device__ __nv_bfloat16 g_Ab [Lseq*KP];
__device__ __nv_bfloat16 g_Aib[Lseq*KP];
__device__ __nv_bfloat16 g_AOb[Lseq*KP];
__device__ __nv_bfloat16 g_Bq [Dm*KP];
__device__ __nv_bfloat16 g_Bk [Dm*KP];
__device__ __nv_bfloat16 g_Bv [Dm*KP];
__device__ __nv_bfloat16 g_Bo [Dm*KP];
__device__ __nv_bfloat16 g_Bqp[Pp*KP];
__device__ __nv_bfloat16 g_Bkp[Pp*KP];
// attention operands
__device__ __nv_bfloat16 g_Qb [Hh*Lseq*KQ3];   // [h][q][240] = [hi|lo|hi]
__device__ __nv_bfloat16 g_Kb [Hh*Lseq*KQ3];   // [h][k][240] = [hi|hi|lo]
__device__ __nv_bfloat16 g_Vth[Hh*HD*Lseq];    // [h][d][k] hi
__device__ __nv_bfloat16 g_Vtl[Hh*HD*Lseq];    // [h][d][k] lo

// ---------------- helpers ----------------
__device__ __forceinline__ uint32_t smem_u32(const void* p) {
    uint32_t a;
    asm("{ .reg .u64 t; cvta.to.shared.u64 t, %1; cvt.u32.u64 %0, t; }" : "=r"(a) : "l"(p));
    return a;
}
__device__ __forceinline__ void ldsm_x4(uint32_t& r0, uint32_t& r1, uint32_t& r2,
                                        uint32_t& r3, uint32_t addr) {
    asm volatile("ldmatrix.sync.aligned.m8n8.x4.shared.b16 {%0,%1,%2,%3}, [%4];"
                 : "=r"(r0), "=r"(r1), "=r"(r2), "=r"(r3) : "r"(addr));
}
__device__ __forceinline__ void mma_bf16(float* c, uint32_t a0, uint32_t a1,
                                         uint32_t a2, uint32_t a3,
                                         uint32_t b0, uint32_t b1) {
    asm volatile(
        "mma.sync.aligned.m16n8k16.row.col.f32.bf16.bf16.f32 "
        "{%0,%1,%2,%3}, {%4,%5,%6,%7}, {%8,%9}, {%0,%1,%2,%3};"
        : "+f"(c[0]), "+f"(c[1]), "+f"(c[2]), "+f"(c[3])
        : "r"(a0), "r"(a1), "r"(a2), "r"(a3), "r"(b0), "r"(b1));
}

// ---------------------------------------------------------------------------
// bf16x3 pack of activation X[M][1024] -> out[M][3072] = [hi | lo | hi]
// ---------------------------------------------------------------------------
__global__ __launch_bounds__(256)
void conv_a(const float* __restrict__ X, __nv_bfloat16* __restrict__ out) {
    int idx = blockIdx.x * 256 + threadIdx.x;
    if (idx >= Lseq * Dm) return;
    int m = idx >> 10, k = idx & 1023;
    float v = X[idx];
    __nv_bfloat16 hi = __float2bfloat16(v);
    __nv_bfloat16 lo = __float2bfloat16(v - __bfloat162float(hi));
    size_t r = (size_t)m * KP;
    out[r + k] = hi;
    out[r + 1024 + k] = lo;
    out[r + 2048 + k] = hi;
}
// ---------------------------------------------------------------------------
// bf16x3 pack+transpose of weight W[1024][N] -> out[N][3072] = [hi | hi | lo]
// ---------------------------------------------------------------------------
__global__ __launch_bounds__(256)
void conv_b(const float* __restrict__ W, __nv_bfloat16* __restrict__ out, int N) {
    __shared__ float t[32][33];
    int k0 = blockIdx.y * 32, n0 = blockIdx.x * 32;
    int tx = threadIdx.x & 31, ty = threadIdx.x >> 5;
#pragma unroll
    for (int i = 0; i < 32; i += 8)
        t[ty + i][tx] = W[(size_t)(k0 + ty + i) * N + n0 + tx];
    __syncthreads();
#pragma unroll
    for (int i = 0; i < 32; i += 8) {
        float v = t[tx][ty + i];
        __nv_bfloat16 hi = __float2bfloat16(v);
        __nv_bfloat16 lo = __float2bfloat16(v - __bfloat162float(hi));
        size_t r = (size_t)(n0 + ty + i) * KP;
        out[r + k0 + tx] = hi;
        out[r + 1024 + k0 + tx] = hi;
        out[r + 2048 + k0 + tx] = lo;
    }
}

// ---------------------------------------------------------------------------
// mma.sync bf16 GEMM (unchanged from R4 passing version)
// ---------------------------------------------------------------------------
#define LDA 40
__global__ __launch_bounds__(256, 2)
void tgemm(const __nv_bfloat16* __restrict__ A, const __nv_bfloat16* __restrict__ B,
           float* __restrict__ C, int N) {
    __shared__ __align__(16) __nv_bfloat16 As[2][128 * LDA];
    __shared__ __align__(16) __nv_bfloat16 Bs[2][128 * LDA];

    const int tid = threadIdx.x;
    const int wid = tid >> 5, lane = tid & 31;
    const int m0 = blockIdx.y * 128, n0 = blockIdx.x * 128;
    const int wm = (wid >> 2) * 64, wn = (wid & 3) * 32;

    const int lr = tid >> 1, lc = (tid & 1) * 16;
    const __nv_bfloat16* Ag = A + (size_t)(m0 + lr) * KP + lc;
    const __nv_bfloat16* Bg = B + (size_t)(n0 + lr) * KP + lc;
    const int soff = lr * LDA + lc;

    float acc[4][4][4];
#pragma unroll
    for (int i = 0; i < 4; i++)
#pragma unroll
        for (int j = 0; j < 4; j++)
#pragma unroll
            for (int k = 0; k < 4; k++) acc[i][j][k] = 0.f;

    *(uint4*)&As[0][soff]     = *(const uint4*)(Ag);
    *(uint4*)&As[0][soff + 8] = *(const uint4*)(Ag + 8);
    *(uint4*)&Bs[0][soff]     = *(const uint4*)(Bg);
    *(uint4*)&Bs[0][soff + 8] = *(const uint4*)(Bg + 8);
    __syncthreads();

    const int a_row = (lane & 15);
    const int a_koff = (lane >> 4) * 8;
    const int b_row = (lane & 7) + ((lane & 16) >> 1);
    const int b_koff = ((lane >> 3) & 1) * 8;

    const int NKT = KP / 32;
    for (int kt = 0; kt < NKT; kt++) {
        const int cur = kt & 1;
        uint4 ra0, ra1, rb0, rb1;
        if (kt < NKT - 1) {
            const __nv_bfloat16* An = Ag + (size_t)(kt + 1) * 32;
            const __nv_bfloat16* Bn = Bg + (size_t)(kt + 1) * 32;
            ra0 = *(const uint4*)(An);
            ra1 = *(const uint4*)(An + 8);
            rb0 = *(const uint4*)(Bn);
            rb1 = *(const uint4*)(Bn + 8);
        }
        const uint32_t aBase = smem_u32(&As[cur][0]);
        const uint32_t bBase = smem_u32(&Bs[cur][0]);
#pragma unroll
        for (int ks = 0; ks < 2; ks++) {
            const int k0 = ks * 16;
            uint32_t af[4][4];
#pragma unroll
            for (int mt = 0; mt < 4; mt++) {
                uint32_t ad = aBase + ((wm + mt * 16 + a_row) * LDA + k0 + a_koff) * 2;
                ldsm_x4(af[mt][0], af[mt][1], af[mt][2], af[mt][3], ad);
            }
            uint32_t bf[2][4];
#pragma unroll
            for (int nt2 = 0; nt2 < 2; nt2++) {
                uint32_t bd = bBase + ((wn + nt2 * 16 + b_row) * LDA + k0 + b_koff) * 2;
                ldsm_x4(bf[nt2][0], bf[nt2][1], bf[nt2][2], bf[nt2][3], bd);
            }
#pragma unroll
            for (int mt = 0; mt < 4; mt++)
#pragma unroll
                for (int nt = 0; nt < 4; nt++)
                    mma_bf16(acc[mt][nt], af[mt][0], af[mt][1], af[mt][2], af[mt][3],
                             bf[nt >> 1][(nt & 1) * 2], bf[nt >> 1][(nt & 1) * 2 + 1]);
        }
        if (kt < NKT - 1) {
            *(uint4*)&As[cur ^ 1][soff]     = ra0;
            *(uint4*)&As[cur ^ 1][soff + 8] = ra1;
            *(uint4*)&Bs[cur ^ 1][soff]     = rb0;
            *(uint4*)&Bs[cur ^ 1][soff + 8] = rb1;
            __syncthreads();
        }
    }

    const int er = lane >> 2, ec = (lane & 3) * 2;
#pragma unroll
    for (int mt = 0; mt < 4; mt++) {
        const int row = m0 + wm + mt * 16 + er;
#pragma unroll
        for (int nt = 0; nt < 4; nt++) {
            const int col = n0 + wn + nt * 8 + ec;
            *(float2*)&C[(size_t)row * N + col] =
                make_float2(acc[mt][nt][0], acc[mt][nt][1]);
            *(float2*)&C[(size_t)(row + 8) * N + col] =
                make_float2(acc[mt][nt][2], acc[mt][nt][3]);
        }
    }
}

// ---------------------------------------------------------------------------
// Pack content dims (0..63) of augmented Q/K as bf16x3 into g_Qb/g_Kb
// ---------------------------------------------------------------------------
__global__ __launch_bounds__(256)
void pack_content(const float* __restrict__ Q, const float* __restrict__ K,
                  const float* __restrict__ alogit,
                  __nv_bfloat16* __restrict__ Qb, __nv_bfloat16* __restrict__ Kb) {
    int idx = blockIdx.x * blockDim.x + threadIdx.x;
    if (idx >= Lseq * Dm) return;
    int q = idx >> 10, c = idx & 1023;
    int h = c >> 6, d = c & 63;
    float alpha = 1.f / (1.f + expf(-alogit[h]));
    float vq = (1.f - alpha) * CONTENT_SCALE * Q[idx];
    float vk = K[idx];
    size_t base = ((size_t)h * Lseq + q) * KQ3;
    __nv_bfloat16 qh = __float2bfloat16(vq);
    __nv_bfloat16 ql = __float2bfloat16(vq - __bfloat162float(qh));
    Qb[base + d] = qh; Qb[base + 80 + d] = ql; Qb[base + 160 + d] = qh;
    __nv_bfloat16 kh = __float2bfloat16(vk);
    __nv_bfloat16 kl = __float2bfloat16(vk - __bfloat162float(kh));
    Kb[base + d] = kh; Kb[base + 80 + d] = kh; Kb[base + 160 + d] = kl;
}

// ---------------------------------------------------------------------------
// Phase dims (64..79) packed bf16x3
// ---------------------------------------------------------------------------
__global__ __launch_bounds__(256)
void phase_pack(const float* __restrict__ Qt, const float* __restrict__ Kt,
                const float* __restrict__ bqp, const float* __restrict__ bkp,
                const float* __restrict__ alogit,
                __nv_bfloat16* __restrict__ Qb, __nv_bfloat16* __restrict__ Kb) {
    int idx = blockIdx.x * blockDim.x + threadIdx.x;
    if (idx >= Lseq * Pp) return;
    int q = idx >> 7, j = idx & 127;
    int h = j / PPH, i = j % PPH;
    int f = j >> 1;
    double invf = exp(-(double)f / 64.0 * log(10000.0));
    float pos = (float)((double)q * invf);
    float tq = Qt[idx] + bqp[j] + pos;
    float tk = Kt[idx] + bkp[j] + pos;
    float alpha = 1.f / (1.f + expf(-alogit[h]));
    float aps = alpha * PHASE_SCALE;
    size_t base = ((size_t)h * Lseq + q) * KQ3;
    float qv[2] = {aps * cosf(tq), aps * sinf(tq)};
    float kv[2] = {cosf(tk), sinf(tk)};
#pragma unroll
    for (int s = 0; s < 2; s++) {
        int d = 64 + s * 8 + i;
        __nv_bfloat16 qh = __float2bfloat16(qv[s]);
        __nv_bfloat16 ql = __float2bfloat16(qv[s] - __bfloat162float(qh));
        Qb[base + d] = qh; Qb[base + 80 + d] = ql; Qb[base + 160 + d] = qh;
        __nv_bfloat16 kh = __float2bfloat16(kv[s]);
        __nv_bfloat16 kl = __float2bfloat16(kv[s] - __bfloat162float(kh));
        Kb[base + d] = kh; Kb[base + 80 + d] = kh; Kb[base + 160 + d] = kl;
    }
}

// ---------------------------------------------------------------------------
// Transpose + hi/lo split of V: V[q][h*64+d] -> Vth[h][d][q], Vtl[h][d][q]
// ---------------------------------------------------------------------------
__global__ __launch_bounds__(256)
void vt_pack(const float* __restrict__ V,
             __nv_bfloat16* __restrict__ Vth, __nv_bfloat16* __restrict__ Vtl) {
    __shared__ float t[32][33];
    int q0 = blockIdx.y * 32, c0 = blockIdx.x * 32;
    int tx = threadIdx.x & 31, ty = threadIdx.x >> 5;
#pragma unroll
    for (int i = 0; i < 32; i += 8)
        t[ty + i][tx] = V[(size_t)(q0 + ty + i) * Dm + c0 + tx];
    __syncthreads();
#pragma unroll
    for (int i = 0; i < 32; i += 8) {
        float v = t[tx][ty + i];                  // = V[q0+tx][c0+ty+i]
        int c = c0 + ty + i;
        size_t o = ((size_t)c) * Lseq + q0 + tx;  // (h*64+d)*L + q
        __nv_bfloat16 hi = __float2bfloat16(v);
        Vth[o] = hi;
        Vtl[o] = __float2bfloat16(v - __bfloat162float(hi));
    }
}

// ---------------------------------------------------------------------------
// Tensor-core flash attention, augmented d (bf16x3), causal.
// Q tile 128, K tile 64. 8 warps: 4x2 grid, 32x32 warp tiles.
// Grid: (16, Hh). qt = 15 - blockIdx.x (big tiles first).
// ---------------------------------------------------------------------------
#define QS_STR 248
#define KS_STR 248
#define VS_STR 72
#define ST_STR 65
#define PS_STR 72
#define SM_QS   0
#define SM_KS   (SM_QS + 128*QS_STR*2)            // 63488
#define SM_VH   (SM_KS + 64*KS_STR*2)             // +31744
#define SM_VL   (SM_VH + 64*VS_STR*2)             // +9216
#define SM_ST   (SM_VL + 64*VS_STR*2)             // +9216
#define SM_PH   (SM_ST + 128*ST_STR*4)            // +33280
#define SM_PL   (SM_PH + 128*PS_STR*2)            // +18432
#define SM_MR   (SM_PL + 128*PS_STR*2)            // +18432
#define SM_LR   (SM_MR + 128*4)
#define SM_RS   (SM_LR + 128*4)
#define SM_TOT  (SM_RS + 128*4)                   // 185344 B

__global__ __launch_bounds__(256)
void attn2(const __nv_bfloat16* __restrict__ Qb, const __nv_bfloat16* __restrict__ Kb,
           const __nv_bfloat16* __restrict__ Vth, const __nv_bfloat16* __restrict__ Vtl,
           float* __restrict__ Out) {
    extern __shared__ char smraw[];
    __nv_bfloat16* Qs = (__nv_bfloat16*)(smraw + SM_QS);
    __nv_bfloat16* Ks = (__nv_bfloat16*)(smraw + SM_KS);
    __nv_bfloat16* Vh = (__nv_bfloat16*)(smraw + SM_VH);
    __nv_bfloat16* Vl = (__nv_bfloat16*)(smraw + SM_VL);
    float* St = (float*)(smraw + SM_ST);
    __nv_bfloat16* Ph = (__nv_bfloat16*)(smraw + SM_PH);
    __nv_bfloat16* Pl = (__nv_bfloat16*)(smraw + SM_PL);
    float* Mr = (float*)(smraw + SM_MR);
    float* Lr = (float*)(smraw + SM_LR);
    float* Rs = (float*)(smraw + SM_RS);

    const int tid = threadIdx.x;
    const int wid = tid >> 5, lane = tid & 31;
    const int h = blockIdx.y;
    const int qt = (int)gridDim.x - 1 - (int)blockIdx.x;
    const int q0 = qt * 128;
    const int wm = (wid >> 1) * 32, wn = (wid & 1) * 32;

    const int a_row = (lane & 15);
    const int a_koff = (lane >> 4) * 8;
    const int b_row = (lane & 7) + ((lane & 16) >> 1);
    const int b_koff = ((lane >> 3) & 1) * 8;
    const int er = lane >> 2, ec = (lane & 3) * 2;

    // load Q' tile (128 x 240 bf16) once
    {
        const uint4* src = (const uint4*)(Qb + ((size_t)h * Lseq + q0) * KQ3);
        for (int i = tid; i < 128 * 30; i += 256) {
            int r = i / 30, c = i % 30;
            *(uint4*)&Qs[r * QS_STR + c * 8] = src[r * 30 + c];
        }
    }
    if (tid < 128) { Mr[tid] = NEG_BIG; Lr[tid] = 0.f; }

    float acc_o[2][4][4];
#pragma unroll
    for (int a = 0; a < 2; a++)
#pragma unroll
        for (int b = 0; b < 4; b++)
#pragma unroll
            for (int c = 0; c < 4; c++) acc_o[a][b][c] = 0.f;
    __syncthreads();

    const uint32_t qsB = smem_u32(Qs);
    const uint32_t ksB = smem_u32(Ks);
    const uint32_t vhB = smem_u32(Vh);
    const uint32_t vlB = smem_u32(Vl);
    const uint32_t phB = smem_u32(Ph);
    const uint32_t plB = smem_u32(Pl);

    const int nkt = 2 * qt + 2;
    for (int kt = 0; kt < nkt; kt++) {
        const int k0 = kt * 64;
        // ---- load K' tile (64 x 240) and V hi/lo tiles (64 x 64 each) ----
        {
            const uint4* src = (const uint4*)(Kb + ((size_t)h * Lseq + k0) * KQ3);
            for (int i = tid; i < 64 * 30; i += 256) {
                int r = i / 30, c = i % 30;
                *(uint4*)&Ks[r * KS_STR + c * 8] = src[r * 30 + c];
            }
            const __nv_bfloat16* vh = Vth + ((size_t)h * HD) * Lseq + k0;
            const __nv_bfloat16* vl = Vtl + ((size_t)h * HD) * Lseq + k0;
            for (int i = tid; i < 64 * 8; i += 256) {
                int d = i >> 3, c = i & 7;
                *(uint4*)&Vh[d * VS_STR + c * 8] =
                    *(const uint4*)(vh + (size_t)d * Lseq + c * 8);
                *(uint4*)&Vl[d * VS_STR + c * 8] =
                    *(const uint4*)(vl + (size_t)d * Lseq + c * 8);
            }
        }
        __syncthreads();

        // ---- S = Q' @ K'^T  (K = 240) ----
        float acc_s[2][4][4];
#pragma unroll
        for (int a = 0; a < 2; a++)
#pragma unroll
            for (int b = 0; b < 4; b++)
#pragma unroll
                for (int c = 0; c < 4; c++) acc_s[a][b][c] = 0.f;
#pragma unroll
        for (int ks = 0; ks < 15; ks++) {
            const int kk = ks * 16;
            uint32_t af[2][4];
#pragma unroll
            for (int mt = 0; mt < 2; mt++) {
                uint32_t ad = qsB + ((wm + mt * 16 + a_row) * QS_STR + kk + a_koff) * 2;
                ldsm_x4(af[mt][0], af[mt][1], af[mt][2], af[mt][3], ad);
            }
            uint32_t bf[2][4];
#pragma unroll
            for (int nt2 = 0; nt2 < 2; nt2++) {
                uint32_t bd = ksB + ((wn + nt2 * 16 + b_row) * KS_STR + kk + b_koff) * 2;
                ldsm_x4(bf[nt2][0], bf[nt2][1], bf[nt2][2], bf[nt2][3], bd);
            }
#pragma unroll
            for (int mt = 0; mt < 2; mt++)
#pragma unroll
                for (int nt = 0; nt < 4; nt++)
                    mma_bf16(acc_s[mt][nt], af[mt][0], af[mt][1], af[mt][2], af[mt][3],
                             bf[nt >> 1][(nt & 1) * 2], bf[nt >> 1][(nt & 1) * 2 + 1]);
        }
        // ---- mask + write S to smem (fp32, [q][k]) ----
        const bool maskT = (kt >= 2 * qt);
#pragma unroll
        for (int mt = 0; mt < 2; mt++) {
            const int r0 = wm + mt * 16 + er;
#pragma unroll
            for (int nt = 0; nt < 4; nt++) {
                const int c0 = wn + nt * 8 + ec;
                float v0 = acc_s[mt][nt][0], v1 = acc_s[mt][nt][1];
                float v2 = acc_s[mt][nt][2], v3 = acc_s[mt][nt][3];
                if (maskT) {
                    if (k0 + c0     > q0 + r0)     v0 = NEG_BIG;
                    if (k0 + c0 + 1 > q0 + r0)     v1 = NEG_BIG;
                    if (k0 + c0     > q0 + r0 + 8) v2 = NEG_BIG;
                    if (k0 + c0 + 1 > q0 + r0 + 8) v3 = NEG_BIG;
                }
                St[r0 * ST_STR + c0] = v0;
                St[r0 * ST_STR + c0 + 1] = v1;
                St[(r0 + 8) * ST_STR + c0] = v2;
                St[(r0 + 8) * ST_STR + c0 + 1] = v3;
            }
        }
        __syncthreads();

        // ---- online softmax: one row per thread (threads 0..127) ----
        if (tid < 128) {
            const int r = tid;
            float mold = Mr[r];
            float mx = mold;
#pragma unroll 8
            for (int k = 0; k < 64; k++) mx = fmaxf(mx, St[r * ST_STR + k]);
            float scale = __expf(mold - mx);
            float sum = 0.f;
#pragma unroll 8
            for (int k = 0; k < 64; k++) {
                float p = __expf(St[r * ST_STR + k] - mx);
                St[r * ST_STR + k] = p;
                sum += p;
            }
            Mr[r] = mx;
            Lr[r] = Lr[r] * scale + sum;
            Rs[r] = scale;
        }
        __syncthreads();

        // ---- convert P to bf16 hi/lo ----
        for (int i = tid; i < 128 * 64; i += 256) {
            int r = i >> 6, k = i & 63;
            float p = St[r * ST_STR + k];
            __nv_bfloat16 hi = __float2bfloat16(p);
            Ph[r * PS_STR + k] = hi;
            Pl[r * PS_STR + k] = __float2bfloat16(p - __bfloat162float(hi));
        }
        __syncthreads();

        // ---- rescale O, then O += Phi@Vhi + Plo@Vhi + Phi@Vlo ----
#pragma unroll
        for (int mt = 0; mt < 2; mt++) {
            float rs0 = Rs[wm + mt * 16 + er];
            float rs1 = Rs[wm + mt * 16 + er + 8];
#pragma unroll
            for (int nt = 0; nt < 4; nt++) {
                acc_o[mt][nt][0] *= rs0; acc_o[mt][nt][1] *= rs0;
                acc_o[mt][nt][2] *= rs1; acc_o[mt][nt][3] *= rs1;
            }
        }
#pragma unroll
        for (int pass = 0; pass < 3; pass++) {
            const uint32_t pB = (pass == 1) ? plB : phB;
            const uint32_t vB = (pass == 2) ? vlB : vhB;
#pragma unroll
            for (int ks = 0; ks < 4; ks++) {
                const int kk = ks * 16;
                uint32_t af[2][4];
#pragma unroll
                for (int mt = 0; mt < 2; mt++) {
                    uint32_t ad = pB + ((wm + mt * 16 + a_row) * PS_STR + kk + a_koff) * 2;
                    ldsm_x4(af[mt][0], af[mt][1], af[mt][2], af[mt][3], ad);
                }
                uint32_t bf[2][4];
#pragma unroll
                for (int nt2 = 0; nt2 < 2; nt2++) {
                    uint32_t bd = vB + ((wn + nt2 * 16 + b_row) * VS_STR + kk + b_koff) * 2;
                    ldsm_x4(bf[nt2][0], bf[nt2][1], bf[nt2][2], bf[nt2][3], bd);
                }
#pragma unroll
                for (int mt = 0; mt < 2; mt++)
#pragma unroll
                    for (int nt = 0; nt < 4; nt++)
                        mma_bf16(acc_o[mt][nt], af[mt][0], af[mt][1], af[mt][2], af[mt][3],
                                 bf[nt >> 1][(nt & 1) * 2], bf[nt >> 1][(nt & 1) * 2 + 1]);
            }
        }
        __syncthreads();
    }

    // ---- epilogue: divide by Lr, write Out[q][h*64 + d] ----
#pragma unroll
    for (int mt = 0; mt < 2; mt++) {
        const int r0 = wm + mt * 16 + er;
        float inv0 = 1.f / Lr[r0];
        float inv1 = 1.f / Lr[r0 + 8];
#pragma unroll
        for (int nt = 0; nt < 4; nt++) {
            const int c0 = wn + nt * 8 + ec;
            *(float2*)&Out[(size_t)(q0 + r0) * Dm + h * HD + c0] =
                make_float2(acc_o[mt][nt][0] * inv0, acc_o[mt][nt][1] * inv0);
            *(float2*)&Out[(size_t)(q0 + r0 + 8) * Dm + h * HD + c0] =
                make_float2(acc_o[mt][nt][2] * inv1, acc_o[mt][nt][3] * inv1);
        }
    }
}

// ---------------------------------------------------------------------------
__global__ __launch_bounds__(256)
void ln_kernel(const float* __restrict__ xr, const float* __restrict__ proj,
               const float* __restrict__ gamma, const float* __restrict__ beta,
               float* __restrict__ out) {
    const int row = blockIdx.x;
    const int tid = threadIdx.x;
    __shared__ float red[2][8];
    const float* a = xr + (long)row * Dm;
    const float* b = proj + (long)row * Dm;
    float s = 0.f, s2 = 0.f;
    for (int i = tid; i < Dm; i += 256) {
        float v = a[i] + b[i];
        s += v; s2 += v * v;
    }
#pragma unroll
    for (int o = 16; o; o >>= 1) {
        s  += __shfl_xor_sync(0xffffffffu, s,  o);
        s2 += __shfl_xor_sync(0xffffffffu, s2, o);
    }
    if ((tid & 31) == 0) { red[0][tid >> 5] = s; red[1][tid >> 5] = s2; }
    __syncthreads();
    if (tid < 32) {
        s  = (tid < 8) ? red[0][tid] : 0.f;
        s2 = (tid < 8) ? red[1][tid] : 0.f;
#pragma unroll
        for (int o = 4; o; o >>= 1) {
            s  += __shfl_xor_sync(0xffffffffu, s,  o);
            s2 += __shfl_xor_sync(0xffffffffu, s2, o);
        }
        if (tid == 0) { red[0][0] = s; red[1][0] = s2; }
    }
    __syncthreads();
    float mu = red[0][0] * (1.f / Dm);
    float var = red[1][0] * (1.f / Dm) - mu * mu;
    float rstd = rsqrtf(var + 1e-5f);
    for (int i = tid; i < Dm; i += 256) {
        float v = a[i] + b[i];
        out[(long)row * Dm + i] = (v - mu) * rstd * gamma[i] + beta[i];
    }
}

// ---------------------------------------------------------------------------
extern "C" void kernel_launch(void* const* d_in, const int* in_sizes, int n_in,
                              void* d_out, int out_size) {
    const float* x_real = (const float*)d_in[0];
    const float* x_imag = (const float*)d_in[1];
    const float* Wq     = (const float*)d_in[2];
    const float* Wk     = (const float*)d_in[3];
    const float* Wv     = (const float*)d_in[4];
    const float* Wqp    = (const float*)d_in[5];
    const float* bqp    = (const float*)d_in[6];
    const float* Wkp    = (const float*)d_in[7];
    const float* bkp    = (const float*)d_in[8];
    const float* Wo     = (const float*)d_in[9];
    const float* alogit = (const float*)d_in[10];
    const float* lng    = (const float*)d_in[11];
    const float* lnb    = (const float*)d_in[12];

    float *pQ, *pK, *pV, *pQt, *pKt, *pAO, *pP2;
    __nv_bfloat16 *pAb, *pAib, *pAOb, *pBq, *pBk, *pBv, *pBo, *pBqp, *pBkp;
    __nv_bfloat16 *pQb, *pKb, *pVth, *pVtl;
    cudaGetSymbolAddress((void**)&pQ,  g_Q);
    cudaGetSymbolAddress((void**)&pK,  g_K);
    cudaGetSymbolAddress((void**)&pV,  g_V);
    cudaGetSymbolAddress((void**)&pQt, g_Qt);
    cudaGetSymbolAddress((void**)&pKt, g_Kt);
    cudaGetSymbolAddress((void**)&pAO, g_AO);
    cudaGetSymbolAddress((void**)&pP2, g_P2);
    cudaGetSymbolAddress((void**)&pAb,  g_Ab);
    cudaGetSymbolAddress((void**)&pAib, g_Aib);
    cudaGetSymbolAddress((void**)&pAOb, g_AOb);
    cudaGetSymbolAddress((void**)&pBq,  g_Bq);
    cudaGetSymbolAddress((void**)&pBk,  g_Bk);
    cudaGetSymbolAddress((void**)&pBv,  g_Bv);
    cudaGetSymbolAddress((void**)&pBo,  g_Bo);
    cudaGetSymbolAddress((void**)&pBqp, g_Bqp);
    cudaGetSymbolAddress((void**)&pBkp, g_Bkp);
    cudaGetSymbolAddress((void**)&pQb,  g_Qb);
    cudaGetSymbolAddress((void**)&pKb,  g_Kb);
    cudaGetSymbolAddress((void**)&pVth, g_Vth);
    cudaGetSymbolAddress((void**)&pVtl, g_Vtl);

    // pack activations & weights into bf16x3
    conv_a<<<(Lseq * Dm) / 256, 256>>>(x_real, pAb);
    conv_a<<<(Lseq * Dm) / 256, 256>>>(x_imag, pAib);
    dim3 cbg(Dm / 32, Dm / 32);
    conv_b<<<cbg, 256>>>(Wq, pBq, Dm);
    conv_b<<<cbg, 256>>>(Wk, pBk, Dm);
    conv_b<<<cbg, 256>>>(Wv, pBv, Dm);
    conv_b<<<cbg, 256>>>(Wo, pBo, Dm);
    dim3 cbp(Pp / 32, Dm / 32);
    conv_b<<<cbp, 256>>>(Wqp, pBqp, Pp);
    conv_b<<<cbp, 256>>>(Wkp, pBkp, Pp);

    // projection GEMMs (mma.sync bf16)
    dim3 gBig(Dm / 128, Lseq / 128);
    dim3 gPh(Pp / 128, Lseq / 128);
    tgemm<<<gBig, 256>>>(pAb,  pBq,  pQ,  Dm);
    tgemm<<<gBig, 256>>>(pAb,  pBk,  pK,  Dm);
    tgemm<<<gBig, 256>>>(pAb,  pBv,  pV,  Dm);
    tgemm<<<gPh,  256>>>(pAib, pBqp, pQt, Pp);
    tgemm<<<gPh,  256>>>(pAib, pBkp, pKt, Pp);

    // attention operand packing
    pack_content<<<(Lseq * Dm) / 256, 256>>>(pQ, pK, alogit, pQb, pKb);
    phase_pack<<<(Lseq * Pp) / 256, 256>>>(pQt, pKt, bqp, bkp, alogit, pQb, pKb);
    vt_pack<<<dim3(Dm / 32, Lseq / 32), 256>>>(pV, pVth, pVtl);

    // tensor-core flash attention
    cudaFuncSetAttribute(attn2, cudaFuncAttributeMaxDynamicSharedMemorySize, SM_TOT);
    attn2<<<dim3(Lseq / 128, Hh), 256, SM_TOT>>>(pQb, pKb, pVth, pVtl, pAO);

    conv_a<<<(Lseq * Dm) / 256, 256>>>(pAO, pAOb);
    tgemm<<<gBig, 256>>>(pAOb, pBo, pP2, Dm);
    ln_kernel<<<Lseq, 256>>>(x_real, pP2, lng, lnb, (float*)d_out);

    if (out_size >= 2 * Lseq * Dm) {
        cudaMemcpyAsync((float*)d_out + (long)Lseq * Dm, x_imag,
                        (size_t)Lseq * Dm * sizeof(float),
                        cudaMemcpyDeviceToDevice);
    }
}

// round 6
// speedup vs baseline: 1.8735x; 1.3578x over previous
#include <cuda_runtime.h>
#include <cuda_bf16.h>
#include <math.h>
#include <stdint.h>

#define Lseq 2048
#define Dm   1024
#define Hh   16
#define HD   64
#define Pp   128
#define PPH  8
#define DA   80
#define KQ3  240       // 3*80, bf16x3 augmented dim
#define KP   3072      // 3*1024 for projection GEMMs
#define CONTENT_SCALE 0.125f
#define PHASE_SCALE   0.35355339059327373f
#define NEG_BIG (-1e30f)

// ---------------- scratch (static device globals) ----------------
__device__ float g_QKV[Lseq*3*Dm];     // fused Q|K|V output, row stride 3072
__device__ float g_QtKt[Lseq*2*Pp];    // fused Qt|Kt output, row stride 256
__device__ float g_AO[Lseq*Dm];
__device__ float g_P2[Lseq*Dm];
// bf16x3 packed GEMM operands
__device__ __nv_bfloat16 g_Ab  [Lseq*KP];
__device__ __nv_bfloat16 g_Aib [Lseq*KP];
__device__ __nv_bfloat16 g_AOb [Lseq*KP];
__device__ __nv_bfloat16 g_Bqkv[3*Dm*KP];   // rows: 0..1023 Wq^T, 1024.. Wk^T, 2048.. Wv^T
__device__ __nv_bfloat16 g_Bp2 [2*Pp*KP];   // rows: 0..127 Wqp^T, 128..255 Wkp^T
__device__ __nv_bfloat16 g_Bo  [Dm*KP];
// attention operands
__device__ __nv_bfloat16 g_Qb [Hh*Lseq*KQ3];   // [h][q][240] = [hi|lo|hi]
__device__ __nv_bfloat16 g_Kb [Hh*Lseq*KQ3];   // [h][k][240] = [hi|hi|lo]
__device__ __nv_bfloat16 g_Vth[Hh*HD*Lseq];    // [h][d][k] hi
__device__ __nv_bfloat16 g_Vtl[Hh*HD*Lseq];    // [h][d][k] lo

// ---------------- helpers ----------------
__device__ __forceinline__ uint32_t smem_u32(const void* p) {
    uint32_t a;
    asm("{ .reg .u64 t; cvta.to.shared.u64 t, %1; cvt.u32.u64 %0, t; }" : "=r"(a) : "l"(p));
    return a;
}
__device__ __forceinline__ void ldsm_x4(uint32_t& r0, uint32_t& r1, uint32_t& r2,
                                        uint32_t& r3, uint32_t addr) {
    asm volatile("ldmatrix.sync.aligned.m8n8.x4.shared.b16 {%0,%1,%2,%3}, [%4];"
                 : "=r"(r0), "=r"(r1), "=r"(r2), "=r"(r3) : "r"(addr));
}
__device__ __forceinline__ void mma_bf16(float* c, uint32_t a0, uint32_t a1,
                                         uint32_t a2, uint32_t a3,
                                         uint32_t b0, uint32_t b1) {
    asm volatile(
        "mma.sync.aligned.m16n8k16.row.col.f32.bf16.bf16.f32 "
        "{%0,%1,%2,%3}, {%4,%5,%6,%7}, {%8,%9}, {%0,%1,%2,%3};"
        : "+f"(c[0]), "+f"(c[1]), "+f"(c[2]), "+f"(c[3])
        : "r"(a0), "r"(a1), "r"(a2), "r"(a3), "r"(b0), "r"(b1));
}
__device__ __forceinline__ uint32_t pack_bf16x2(float a, float b) {
    __nv_bfloat162 h = __floats2bfloat162_rn(a, b);
    return *(uint32_t*)&h;
}

// ---------------------------------------------------------------------------
// bf16x3 pack of activation X[M][1024] -> out[M][3072] = [hi | lo | hi]
// ---------------------------------------------------------------------------
__global__ __launch_bounds__(256)
void conv_a(const float* __restrict__ X, __nv_bfloat16* __restrict__ out) {
    int idx = blockIdx.x * 256 + threadIdx.x;
    if (idx >= Lseq * Dm) return;
    int m = idx >> 10, k = idx & 1023;
    float v = X[idx];
    __nv_bfloat16 hi = __float2bfloat16(v);
    __nv_bfloat16 lo = __float2bfloat16(v - __bfloat162float(hi));
    size_t r = (size_t)m * KP;
    out[r + k] = hi;
    out[r + 1024 + k] = lo;
    out[r + 2048 + k] = hi;
}
// ---------------------------------------------------------------------------
// bf16x3 pack+transpose of weight W[1024][N] -> out[N][3072] = [hi | hi | lo]
// ---------------------------------------------------------------------------
__global__ __launch_bounds__(256)
void conv_b(const float* __restrict__ W, __nv_bfloat16* __restrict__ out, int N) {
    __shared__ float t[32][33];
    int k0 = blockIdx.y * 32, n0 = blockIdx.x * 32;
    int tx = threadIdx.x & 31, ty = threadIdx.x >> 5;
#pragma unroll
    for (int i = 0; i < 32; i += 8)
        t[ty + i][tx] = W[(size_t)(k0 + ty + i) * N + n0 + tx];
    __syncthreads();
#pragma unroll
    for (int i = 0; i < 32; i += 8) {
        float v = t[tx][ty + i];
        __nv_bfloat16 hi = __float2bfloat16(v);
        __nv_bfloat16 lo = __float2bfloat16(v - __bfloat162float(hi));
        size_t r = (size_t)(n0 + ty + i) * KP;
        out[r + k0 + tx] = hi;
        out[r + 1024 + k0 + tx] = hi;
        out[r + 2048 + k0 + tx] = lo;
    }
}

// ---------------------------------------------------------------------------
// mma.sync bf16 GEMM: C[M,N] = A'[M,3072] @ B'[N,3072]^T (fp32 accum)
// ---------------------------------------------------------------------------
#define LDA 40
__global__ __launch_bounds__(256, 2)
void tgemm(const __nv_bfloat16* __restrict__ A, const __nv_bfloat16* __restrict__ B,
           float* __restrict__ C, int N) {
    __shared__ __align__(16) __nv_bfloat16 As[2][128 * LDA];
    __shared__ __align__(16) __nv_bfloat16 Bs[2][128 * LDA];

    const int tid = threadIdx.x;
    const int wid = tid >> 5, lane = tid & 31;
    const int m0 = blockIdx.y * 128, n0 = blockIdx.x * 128;
    const int wm = (wid >> 2) * 64, wn = (wid & 3) * 32;

    const int lr = tid >> 1, lc = (tid & 1) * 16;
    const __nv_bfloat16* Ag = A + (size_t)(m0 + lr) * KP + lc;
    const __nv_bfloat16* Bg = B + (size_t)(n0 + lr) * KP + lc;
    const int soff = lr * LDA + lc;

    float acc[4][4][4];
#pragma unroll
    for (int i = 0; i < 4; i++)
#pragma unroll
        for (int j = 0; j < 4; j++)
#pragma unroll
            for (int k = 0; k < 4; k++) acc[i][j][k] = 0.f;

    *(uint4*)&As[0][soff]     = *(const uint4*)(Ag);
    *(uint4*)&As[0][soff + 8] = *(const uint4*)(Ag + 8);
    *(uint4*)&Bs[0][soff]     = *(const uint4*)(Bg);
    *(uint4*)&Bs[0][soff + 8] = *(const uint4*)(Bg + 8);
    __syncthreads();

    const int a_row = (lane & 15);
    const int a_koff = (lane >> 4) * 8;
    const int b_row = (lane & 7) + ((lane & 16) >> 1);
    const int b_koff = ((lane >> 3) & 1) * 8;

    const int NKT = KP / 32;
    for (int kt = 0; kt < NKT; kt++) {
        const int cur = kt & 1;
        uint4 ra0, ra1, rb0, rb1;
        if (kt < NKT - 1) {
            const __nv_bfloat16* An = Ag + (size_t)(kt + 1) * 32;
            const __nv_bfloat16* Bn = Bg + (size_t)(kt + 1) * 32;
            ra0 = *(const uint4*)(An);
            ra1 = *(const uint4*)(An + 8);
            rb0 = *(const uint4*)(Bn);
            rb1 = *(const uint4*)(Bn + 8);
        }
        const uint32_t aBase = smem_u32(&As[cur][0]);
        const uint32_t bBase = smem_u32(&Bs[cur][0]);
#pragma unroll
        for (int ks = 0; ks < 2; ks++) {
            const int k0 = ks * 16;
            uint32_t af[4][4];
#pragma unroll
            for (int mt = 0; mt < 4; mt++) {
                uint32_t ad = aBase + ((wm + mt * 16 + a_row) * LDA + k0 + a_koff) * 2;
                ldsm_x4(af[mt][0], af[mt][1], af[mt][2], af[mt][3], ad);
            }
            uint32_t bf[2][4];
#pragma unroll
            for (int nt2 = 0; nt2 < 2; nt2++) {
                uint32_t bd = bBase + ((wn + nt2 * 16 + b_row) * LDA + k0 + b_koff) * 2;
                ldsm_x4(bf[nt2][0], bf[nt2][1], bf[nt2][2], bf[nt2][3], bd);
            }
#pragma unroll
            for (int mt = 0; mt < 4; mt++)
#pragma unroll
                for (int nt = 0; nt < 4; nt++)
                    mma_bf16(acc[mt][nt], af[mt][0], af[mt][1], af[mt][2], af[mt][3],
                             bf[nt >> 1][(nt & 1) * 2], bf[nt >> 1][(nt & 1) * 2 + 1]);
        }
        if (kt < NKT - 1) {
            *(uint4*)&As[cur ^ 1][soff]     = ra0;
            *(uint4*)&As[cur ^ 1][soff + 8] = ra1;
            *(uint4*)&Bs[cur ^ 1][soff]     = rb0;
            *(uint4*)&Bs[cur ^ 1][soff + 8] = rb1;
            __syncthreads();
        }
    }

    const int er = lane >> 2, ec = (lane & 3) * 2;
#pragma unroll
    for (int mt = 0; mt < 4; mt++) {
        const int row = m0 + wm + mt * 16 + er;
#pragma unroll
        for (int nt = 0; nt < 4; nt++) {
            const int col = n0 + wn + nt * 8 + ec;
            *(float2*)&C[(size_t)row * N + col] =
                make_float2(acc[mt][nt][0], acc[mt][nt][1]);
            *(float2*)&C[(size_t)(row + 8) * N + col] =
                make_float2(acc[mt][nt][2], acc[mt][nt][3]);
        }
    }
}

// ---------------------------------------------------------------------------
// Pack content dims (0..63) of augmented Q/K from fused QKV buffer
// ---------------------------------------------------------------------------
__global__ __launch_bounds__(256)
void pack_content(const float* __restrict__ QKV, const float* __restrict__ alogit,
                  __nv_bfloat16* __restrict__ Qb, __nv_bfloat16* __restrict__ Kb) {
    int idx = blockIdx.x * blockDim.x + threadIdx.x;
    if (idx >= Lseq * Dm) return;
    int q = idx >> 10, c = idx & 1023;
    int h = c >> 6, d = c & 63;
    float alpha = 1.f / (1.f + expf(-alogit[h]));
    float vq = (1.f - alpha) * CONTENT_SCALE * QKV[(size_t)q * 3072 + c];
    float vk = QKV[(size_t)q * 3072 + 1024 + c];
    size_t base = ((size_t)h * Lseq + q) * KQ3;
    __nv_bfloat16 qh = __float2bfloat16(vq);
    __nv_bfloat16 ql = __float2bfloat16(vq - __bfloat162float(qh));
    Qb[base + d] = qh; Qb[base + 80 + d] = ql; Qb[base + 160 + d] = qh;
    __nv_bfloat16 kh = __float2bfloat16(vk);
    __nv_bfloat16 kl = __float2bfloat16(vk - __bfloat162float(kh));
    Kb[base + d] = kh; Kb[base + 80 + d] = kh; Kb[base + 160 + d] = kl;
}

// ---------------------------------------------------------------------------
// Phase dims (64..79) packed bf16x3, from fused QtKt buffer (stride 256)
// ---------------------------------------------------------------------------
__global__ __launch_bounds__(256)
void phase_pack(const float* __restrict__ QtKt,
                const float* __restrict__ bqp, const float* __restrict__ bkp,
                const float* __restrict__ alogit,
                __nv_bfloat16* __restrict__ Qb, __nv_bfloat16* __restrict__ Kb) {
    int idx = blockIdx.x * blockDim.x + threadIdx.x;
    if (idx >= Lseq * Pp) return;
    int q = idx >> 7, j = idx & 127;
    int h = j / PPH, i = j % PPH;
    int f = j >> 1;
    double invf = exp(-(double)f / 64.0 * log(10000.0));
    float pos = (float)((double)q * invf);
    float tq = QtKt[(size_t)q * 256 + j] + bqp[j] + pos;
    float tk = QtKt[(size_t)q * 256 + 128 + j] + bkp[j] + pos;
    float alpha = 1.f / (1.f + expf(-alogit[h]));
    float aps = alpha * PHASE_SCALE;
    size_t base = ((size_t)h * Lseq + q) * KQ3;
    float qv[2] = {aps * cosf(tq), aps * sinf(tq)};
    float kv[2] = {cosf(tk), sinf(tk)};
#pragma unroll
    for (int s = 0; s < 2; s++) {
        int d = 64 + s * 8 + i;
        __nv_bfloat16 qh = __float2bfloat16(qv[s]);
        __nv_bfloat16 ql = __float2bfloat16(qv[s] - __bfloat162float(qh));
        Qb[base + d] = qh; Qb[base + 80 + d] = ql; Qb[base + 160 + d] = qh;
        __nv_bfloat16 kh = __float2bfloat16(kv[s]);
        __nv_bfloat16 kl = __float2bfloat16(kv[s] - __bfloat162float(kh));
        Kb[base + d] = kh; Kb[base + 80 + d] = kh; Kb[base + 160 + d] = kl;
    }
}

// ---------------------------------------------------------------------------
// Transpose + hi/lo split of V (from fused QKV, col offset 2048, stride 3072)
// ---------------------------------------------------------------------------
__global__ __launch_bounds__(256)
void vt_pack(const float* __restrict__ QKV,
             __nv_bfloat16* __restrict__ Vth, __nv_bfloat16* __restrict__ Vtl) {
    __shared__ float t[32][33];
    int q0 = blockIdx.y * 32, c0 = blockIdx.x * 32;
    int tx = threadIdx.x & 31, ty = threadIdx.x >> 5;
#pragma unroll
    for (int i = 0; i < 32; i += 8)
        t[ty + i][tx] = QKV[(size_t)(q0 + ty + i) * 3072 + 2048 + c0 + tx];
    __syncthreads();
#pragma unroll
    for (int i = 0; i < 32; i += 8) {
        float v = t[tx][ty + i];
        int c = c0 + ty + i;
        size_t o = ((size_t)c) * Lseq + q0 + tx;
        __nv_bfloat16 hi = __float2bfloat16(v);
        Vth[o] = hi;
        Vtl[o] = __float2bfloat16(v - __bfloat162float(hi));
    }
}

// ---------------------------------------------------------------------------
// Tensor-core flash attention v3: register-resident softmax (FA2 style).
// 8 warps x 16 q-rows each (full 64-k width per warp). Q tile 128, K tile 64.
// S C-fragments convert directly to P A-fragments in registers.
// ---------------------------------------------------------------------------
#define QS_STR 248
#define KS_STR 248
#define VS_STR 72
#define A3_QS  0
#define A3_KS  (A3_QS + 128*QS_STR*2)    // 63488
#define A3_VH  (A3_KS + 64*KS_STR*2)     // +31744
#define A3_VL  (A3_VH + 64*VS_STR*2)     // +9216
#define A3_TOT (A3_VL + 64*VS_STR*2)     // 113664 B

__global__ __launch_bounds__(256)
void attn3(const __nv_bfloat16* __restrict__ Qb, const __nv_bfloat16* __restrict__ Kb,
           const __nv_bfloat16* __restrict__ Vth, const __nv_bfloat16* __restrict__ Vtl,
           float* __restrict__ Out) {
    extern __shared__ char smraw[];
    __nv_bfloat16* Qs = (__nv_bfloat16*)(smraw + A3_QS);
    __nv_bfloat16* Ks = (__nv_bfloat16*)(smraw + A3_KS);
    __nv_bfloat16* Vh = (__nv_bfloat16*)(smraw + A3_VH);
    __nv_bfloat16* Vl = (__nv_bfloat16*)(smraw + A3_VL);

    const int tid = threadIdx.x;
    const int wid = tid >> 5, lane = tid & 31;
    const int h = blockIdx.y;
    const int qt = (int)gridDim.x - 1 - (int)blockIdx.x;
    const int q0 = qt * 128;
    const int wm = wid * 16;

    const int a_row = (lane & 15);
    const int a_koff = (lane >> 4) * 8;
    const int b_row = (lane & 7) + ((lane & 16) >> 1);
    const int b_koff = ((lane >> 3) & 1) * 8;
    const int er = lane >> 2, ec = (lane & 3) * 2;

    // load Q' tile (128 x 240)
    {
        const uint4* src = (const uint4*)(Qb + ((size_t)h * Lseq + q0) * KQ3);
        for (int i = tid; i < 128 * 30; i += 256) {
            int r = i / 30, c = i % 30;
            *(uint4*)&Qs[r * QS_STR + c * 8] = src[r * 30 + c];
        }
    }

    float m_run0 = NEG_BIG, m_run1 = NEG_BIG;
    float l_run0 = 0.f, l_run1 = 0.f;
    float acc_o[8][4];
#pragma unroll
    for (int d = 0; d < 8; d++)
#pragma unroll
        for (int c = 0; c < 4; c++) acc_o[d][c] = 0.f;
    __syncthreads();

    const uint32_t qsB = smem_u32(Qs);
    const uint32_t ksB = smem_u32(Ks);
    const uint32_t vhB = smem_u32(Vh);
    const uint32_t vlB = smem_u32(Vl);

    const int nkt = 2 * qt + 2;
    for (int kt = 0; kt < nkt; kt++) {
        const int k0 = kt * 64;
        // ---- load K' (64x240) and V hi/lo (64x64) tiles ----
        {
            const uint4* src = (const uint4*)(Kb + ((size_t)h * Lseq + k0) * KQ3);
            for (int i = tid; i < 64 * 30; i += 256) {
                int r = i / 30, c = i % 30;
                *(uint4*)&Ks[r * KS_STR + c * 8] = src[r * 30 + c];
            }
            const __nv_bfloat16* vh = Vth + ((size_t)h * HD) * Lseq + k0;
            const __nv_bfloat16* vl = Vtl + ((size_t)h * HD) * Lseq + k0;
            for (int i = tid; i < 64 * 8; i += 256) {
                int d = i >> 3, c = i & 7;
                *(uint4*)&Vh[d * VS_STR + c * 8] =
                    *(const uint4*)(vh + (size_t)d * Lseq + c * 8);
                *(uint4*)&Vl[d * VS_STR + c * 8] =
                    *(const uint4*)(vl + (size_t)d * Lseq + c * 8);
            }
        }
        __syncthreads();

        // ---- S = Q'(16 rows) @ K'^T(64 cols), K=240 ----
        float s[8][4];
#pragma unroll
        for (int nt = 0; nt < 8; nt++)
#pragma unroll
            for (int c = 0; c < 4; c++) s[nt][c] = 0.f;
#pragma unroll
        for (int ks = 0; ks < 15; ks++) {
            const int kk = ks * 16;
            uint32_t a0, a1, a2, a3;
            ldsm_x4(a0, a1, a2, a3, qsB + ((wm + a_row) * QS_STR + kk + a_koff) * 2);
            uint32_t bf[4][4];
#pragma unroll
            for (int nt2 = 0; nt2 < 4; nt2++)
                ldsm_x4(bf[nt2][0], bf[nt2][1], bf[nt2][2], bf[nt2][3],
                        ksB + ((nt2 * 16 + b_row) * KS_STR + kk + b_koff) * 2);
#pragma unroll
            for (int nt = 0; nt < 8; nt++)
                mma_bf16(s[nt], a0, a1, a2, a3,
                         bf[nt >> 1][(nt & 1) * 2], bf[nt >> 1][(nt & 1) * 2 + 1]);
        }

        // ---- causal mask (registers) ----
        if (kt >= 2 * qt) {
            const int r0 = q0 + wm + er, r1 = r0 + 8;
#pragma unroll
            for (int nt = 0; nt < 8; nt++) {
                const int c0 = k0 + nt * 8 + ec;
                if (c0     > r0) s[nt][0] = NEG_BIG;
                if (c0 + 1 > r0) s[nt][1] = NEG_BIG;
                if (c0     > r1) s[nt][2] = NEG_BIG;
                if (c0 + 1 > r1) s[nt][3] = NEG_BIG;
            }
        }

        // ---- row max over 64 cols: local then quad shfl ----
        float mx0 = s[0][0], mx1 = s[0][2];
#pragma unroll
        for (int nt = 0; nt < 8; nt++) {
            mx0 = fmaxf(mx0, fmaxf(s[nt][0], s[nt][1]));
            mx1 = fmaxf(mx1, fmaxf(s[nt][2], s[nt][3]));
        }
        mx0 = fmaxf(mx0, __shfl_xor_sync(0xffffffffu, mx0, 1));
        mx0 = fmaxf(mx0, __shfl_xor_sync(0xffffffffu, mx0, 2));
        mx1 = fmaxf(mx1, __shfl_xor_sync(0xffffffffu, mx1, 1));
        mx1 = fmaxf(mx1, __shfl_xor_sync(0xffffffffu, mx1, 2));
        float mnew0 = fmaxf(m_run0, mx0);
        float mnew1 = fmaxf(m_run1, mx1);
        float scale0 = __expf(m_run0 - mnew0);
        float scale1 = __expf(m_run1 - mnew1);

        // ---- exp + row sum ----
        float sum0 = 0.f, sum1 = 0.f;
#pragma unroll
        for (int nt = 0; nt < 8; nt++) {
            s[nt][0] = __expf(s[nt][0] - mnew0); sum0 += s[nt][0];
            s[nt][1] = __expf(s[nt][1] - mnew0); sum0 += s[nt][1];
            s[nt][2] = __expf(s[nt][2] - mnew1); sum1 += s[nt][2];
            s[nt][3] = __expf(s[nt][3] - mnew1); sum1 += s[nt][3];
        }
        sum0 += __shfl_xor_sync(0xffffffffu, sum0, 1);
        sum0 += __shfl_xor_sync(0xffffffffu, sum0, 2);
        sum1 += __shfl_xor_sync(0xffffffffu, sum1, 1);
        sum1 += __shfl_xor_sync(0xffffffffu, sum1, 2);
        m_run0 = mnew0; m_run1 = mnew1;
        l_run0 = l_run0 * scale0 + sum0;
        l_run1 = l_run1 * scale1 + sum1;

        // ---- rescale O ----
#pragma unroll
        for (int d = 0; d < 8; d++) {
            acc_o[d][0] *= scale0; acc_o[d][1] *= scale0;
            acc_o[d][2] *= scale1; acc_o[d][3] *= scale1;
        }

        // ---- PV: O += Phi@Vhi + Plo@Vhi + Phi@Vlo (P frags from registers) ----
#pragma unroll
        for (int kk = 0; kk < 4; kk++) {
            // A-frags: hi
            float p00 = s[2*kk][0],   p01 = s[2*kk][1];
            float p02 = s[2*kk][2],   p03 = s[2*kk][3];
            float p10 = s[2*kk+1][0], p11 = s[2*kk+1][1];
            float p12 = s[2*kk+1][2], p13 = s[2*kk+1][3];
            uint32_t ah0 = pack_bf16x2(p00, p01);
            uint32_t ah1 = pack_bf16x2(p02, p03);
            uint32_t ah2 = pack_bf16x2(p10, p11);
            uint32_t ah3 = pack_bf16x2(p12, p13);
            // lo residuals
            __nv_bfloat162* hv;
            hv = (__nv_bfloat162*)&ah0;
            uint32_t al0 = pack_bf16x2(p00 - __bfloat162float(hv->x), p01 - __bfloat162float(hv->y));
            hv = (__nv_bfloat162*)&ah1;
            uint32_t al1 = pack_bf16x2(p02 - __bfloat162float(hv->x), p03 - __bfloat162float(hv->y));
            hv = (__nv_bfloat162*)&ah2;
            uint32_t al2 = pack_bf16x2(p10 - __bfloat162float(hv->x), p11 - __bfloat162float(hv->y));
            hv = (__nv_bfloat162*)&ah3;
            uint32_t al3 = pack_bf16x2(p12 - __bfloat162float(hv->x), p13 - __bfloat162float(hv->y));

            const int kko = kk * 16;
            uint32_t bh[4][4], bl[4][4];
#pragma unroll
            for (int dt2 = 0; dt2 < 4; dt2++) {
                ldsm_x4(bh[dt2][0], bh[dt2][1], bh[dt2][2], bh[dt2][3],
                        vhB + ((dt2 * 16 + b_row) * VS_STR + kko + b_koff) * 2);
                ldsm_x4(bl[dt2][0], bl[dt2][1], bl[dt2][2], bl[dt2][3],
                        vlB + ((dt2 * 16 + b_row) * VS_STR + kko + b_koff) * 2);
            }
#pragma unroll
            for (int dt = 0; dt < 8; dt++) {
                uint32_t b0h = bh[dt >> 1][(dt & 1) * 2], b1h = bh[dt >> 1][(dt & 1) * 2 + 1];
                uint32_t b0l = bl[dt >> 1][(dt & 1) * 2], b1l = bl[dt >> 1][(dt & 1) * 2 + 1];
                mma_bf16(acc_o[dt], ah0, ah1, ah2, ah3, b0h, b1h);
                mma_bf16(acc_o[dt], al0, al1, al2, al3, b0h, b1h);
                mma_bf16(acc_o[dt], ah0, ah1, ah2, ah3, b0l, b1l);
            }
        }
        __syncthreads();   // protect Ks/Vh/Vl before next tile's loads
    }

    // ---- epilogue ----
    const float inv0 = 1.f / l_run0;
    const float inv1 = 1.f / l_run1;
    const int row0 = q0 + wm + er;
#pragma unroll
    for (int dt = 0; dt < 8; dt++) {
        const int col = h * HD + dt * 8 + ec;
        *(float2*)&Out[(size_t)row0 * Dm + col] =
            make_float2(acc_o[dt][0] * inv0, acc_o[dt][1] * inv0);
        *(float2*)&Out[(size_t)(row0 + 8) * Dm + col] =
            make_float2(acc_o[dt][2] * inv1, acc_o[dt][3] * inv1);
    }
}

// ---------------------------------------------------------------------------
__global__ __launch_bounds__(256)
void ln_kernel(const float* __restrict__ xr, const float* __restrict__ proj,
               const float* __restrict__ gamma, const float* __restrict__ beta,
               float* __restrict__ out) {
    const int row = blockIdx.x;
    const int tid = threadIdx.x;
    __shared__ float red[2][8];
    const float* a = xr + (long)row * Dm;
    const float* b = proj + (long)row * Dm;
    float s = 0.f, s2 = 0.f;
    for (int i = tid; i < Dm; i += 256) {
        float v = a[i] + b[i];
        s += v; s2 += v * v;
    }
#pragma unroll
    for (int o = 16; o; o >>= 1) {
        s  += __shfl_xor_sync(0xffffffffu, s,  o);
        s2 += __shfl_xor_sync(0xffffffffu, s2, o);
    }
    if ((tid & 31) == 0) { red[0][tid >> 5] = s; red[1][tid >> 5] = s2; }
    __syncthreads();
    if (tid < 32) {
        s  = (tid < 8) ? red[0][tid] : 0.f;
        s2 = (tid < 8) ? red[1][tid] : 0.f;
#pragma unroll
        for (int o = 4; o; o >>= 1) {
            s  += __shfl_xor_sync(0xffffffffu, s,  o);
            s2 += __shfl_xor_sync(0xffffffffu, s2, o);
        }
        if (tid == 0) { red[0][0] = s; red[1][0] = s2; }
    }
    __syncthreads();
    float mu = red[0][0] * (1.f / Dm);
    float var = red[1][0] * (1.f / Dm) - mu * mu;
    float rstd = rsqrtf(var + 1e-5f);
    for (int i = tid; i < Dm; i += 256) {
        float v = a[i] + b[i];
        out[(long)row * Dm + i] = (v - mu) * rstd * gamma[i] + beta[i];
    }
}

// ---------------------------------------------------------------------------
extern "C" void kernel_launch(void* const* d_in, const int* in_sizes, int n_in,
                              void* d_out, int out_size) {
    const float* x_real = (const float*)d_in[0];
    const float* x_imag = (const float*)d_in[1];
    const float* Wq     = (const float*)d_in[2];
    const float* Wk     = (const float*)d_in[3];
    const float* Wv     = (const float*)d_in[4];
    const float* Wqp    = (const float*)d_in[5];
    const float* bqp    = (const float*)d_in[6];
    const float* Wkp    = (const float*)d_in[7];
    const float* bkp    = (const float*)d_in[8];
    const float* Wo     = (const float*)d_in[9];
    const float* alogit = (const float*)d_in[10];
    const float* lng    = (const float*)d_in[11];
    const float* lnb    = (const float*)d_in[12];

    float *pQKV, *pQtKt, *pAO, *pP2;
    __nv_bfloat16 *pAb, *pAib, *pAOb, *pBqkv, *pBp2, *pBo;
    __nv_bfloat16 *pQb, *pKb, *pVth, *pVtl;
    cudaGetSymbolAddress((void**)&pQKV,  g_QKV);
    cudaGetSymbolAddress((void**)&pQtKt, g_QtKt);
    cudaGetSymbolAddress((void**)&pAO,   g_AO);
    cudaGetSymbolAddress((void**)&pP2,   g_P2);
    cudaGetSymbolAddress((void**)&pAb,   g_Ab);
    cudaGetSymbolAddress((void**)&pAib,  g_Aib);
    cudaGetSymbolAddress((void**)&pAOb,  g_AOb);
    cudaGetSymbolAddress((void**)&pBqkv, g_Bqkv);
    cudaGetSymbolAddress((void**)&pBp2,  g_Bp2);
    cudaGetSymbolAddress((void**)&pBo,   g_Bo);
    cudaGetSymbolAddress((void**)&pQb,   g_Qb);
    cudaGetSymbolAddress((void**)&pKb,   g_Kb);
    cudaGetSymbolAddress((void**)&pVth,  g_Vth);
    cudaGetSymbolAddress((void**)&pVtl,  g_Vtl);

    // pack activations & weights into bf16x3
    conv_a<<<(Lseq * Dm) / 256, 256>>>(x_real, pAb);
    conv_a<<<(Lseq * Dm) / 256, 256>>>(x_imag, pAib);
    dim3 cbg(Dm / 32, Dm / 32);
    conv_b<<<cbg, 256>>>(Wq, pBqkv,                       Dm);
    conv_b<<<cbg, 256>>>(Wk, pBqkv + (size_t)Dm * KP,     Dm);
    conv_b<<<cbg, 256>>>(Wv, pBqkv + (size_t)2 * Dm * KP, Dm);
    conv_b<<<cbg, 256>>>(Wo, pBo, Dm);
    dim3 cbp(Pp / 32, Dm / 32);
    conv_b<<<cbp, 256>>>(Wqp, pBp2,                   Pp);
    conv_b<<<cbp, 256>>>(Wkp, pBp2 + (size_t)Pp * KP, Pp);

    // fused projection GEMMs
    tgemm<<<dim3(3 * Dm / 128, Lseq / 128), 256>>>(pAb,  pBqkv, pQKV,  3 * Dm);
    tgemm<<<dim3(2 * Pp / 128, Lseq / 128), 256>>>(pAib, pBp2,  pQtKt, 2 * Pp);

    // attention operand packing
    pack_content<<<(Lseq * Dm) / 256, 256>>>(pQKV, alogit, pQb, pKb);
    phase_pack<<<(Lseq * Pp) / 256, 256>>>(pQtKt, bqp, bkp, alogit, pQb, pKb);
    vt_pack<<<dim3(Dm / 32, Lseq / 32), 256>>>(pQKV, pVth, pVtl);

    // tensor-core flash attention (register softmax)
    cudaFuncSetAttribute(attn3, cudaFuncAttributeMaxDynamicSharedMemorySize, A3_TOT);
    attn3<<<dim3(Lseq / 128, Hh), 256, A3_TOT>>>(pQb, pKb, pVth, pVtl, pAO);

    conv_a<<<(Lseq * Dm) / 256, 256>>>(pAO, pAOb);
    tgemm<<<dim3(Dm / 128, Lseq / 128), 256>>>(pAOb, pBo, pP2, Dm);
    ln_kernel<<<Lseq, 256>>>(x_real, pP2, lng, lnb, (float*)d_out);

    if (out_size >= 2 * Lseq * Dm) {
        cudaMemcpyAsync((float*)d_out + (long)Lseq * Dm, x_imag,
                        (size_t)Lseq * Dm * sizeof(float),
                        cudaMemcpyDeviceToDevice);
    }
}

// round 7
// speedup vs baseline: 2.3248x; 1.2409x over previous
#include <cuda_runtime.h>
#include <cuda_bf16.h>
#include <math.h>
#include <stdint.h>

#define Lseq 2048
#define Dm   1024
#define Hh   16
#define HD   64
#define Pp   128
#define PPH  8
#define DA   80
#define KQ3  240       // 3*80 packed augmented dim for attention S
#define K2   2048      // [hi|lo] packed K for projection GEMMs
#define CONTENT_SCALE 0.125f
#define PHASE_SCALE   0.35355339059327373f
#define NEG_BIG (-1e30f)

// ---------------- scratch (static device globals) ----------------
__device__ float g_QKV[Lseq*3*Dm];     // fused Q|K|V, row stride 3072
__device__ float g_QtKt[Lseq*2*Pp];    // fused Qt|Kt, row stride 256
__device__ float g_AO[Lseq*Dm];
__device__ float g_P2[Lseq*Dm];
// [hi|lo] packed GEMM operands (K=2048)
__device__ __nv_bfloat16 g_Ab  [Lseq*K2];
__device__ __nv_bfloat16 g_Aib [Lseq*K2];
__device__ __nv_bfloat16 g_AOb [Lseq*K2];
__device__ __nv_bfloat16 g_Bqkv[3*Dm*K2];   // rows: Wq^T | Wk^T | Wv^T
__device__ __nv_bfloat16 g_Bp2 [2*Pp*K2];   // rows: Wqp^T | Wkp^T
__device__ __nv_bfloat16 g_Bo  [Dm*K2];
// attention operands
__device__ __nv_bfloat16 g_Qb [Hh*Lseq*KQ3];   // [h][q][240] = [hi|lo|hi]
__device__ __nv_bfloat16 g_Kb [Hh*Lseq*KQ3];   // [h][k][240] = [hi|hi|lo]
__device__ __nv_bfloat16 g_Vth[Hh*HD*Lseq];    // [h][d][k] hi
__device__ __nv_bfloat16 g_Vtl[Hh*HD*Lseq];    // [h][d][k] lo

// ---------------- helpers ----------------
__device__ __forceinline__ uint32_t smem_u32(const void* p) {
    uint32_t a;
    asm("{ .reg .u64 t; cvta.to.shared.u64 t, %1; cvt.u32.u64 %0, t; }" : "=r"(a) : "l"(p));
    return a;
}
__device__ __forceinline__ void ldsm_x4(uint32_t& r0, uint32_t& r1, uint32_t& r2,
                                        uint32_t& r3, uint32_t addr) {
    asm volatile("ldmatrix.sync.aligned.m8n8.x4.shared.b16 {%0,%1,%2,%3}, [%4];"
                 : "=r"(r0), "=r"(r1), "=r"(r2), "=r"(r3) : "r"(addr));
}
__device__ __forceinline__ void mma_bf16(float* c, uint32_t a0, uint32_t a1,
                                         uint32_t a2, uint32_t a3,
                                         uint32_t b0, uint32_t b1) {
    asm volatile(
        "mma.sync.aligned.m16n8k16.row.col.f32.bf16.bf16.f32 "
        "{%0,%1,%2,%3}, {%4,%5,%6,%7}, {%8,%9}, {%0,%1,%2,%3};"
        : "+f"(c[0]), "+f"(c[1]), "+f"(c[2]), "+f"(c[3])
        : "r"(a0), "r"(a1), "r"(a2), "r"(a3), "r"(b0), "r"(b1));
}
__device__ __forceinline__ uint32_t pack_bf16x2(float a, float b) {
    __nv_bfloat162 h = __floats2bfloat162_rn(a, b);
    return *(uint32_t*)&h;
}

// ---------------------------------------------------------------------------
// [hi|lo] pack of activation X[M][1024] -> out[M][2048]
// ---------------------------------------------------------------------------
__global__ __launch_bounds__(256)
void conv_a2(const float* __restrict__ X, __nv_bfloat16* __restrict__ out) {
    int idx = blockIdx.x * 256 + threadIdx.x;
    if (idx >= Lseq * Dm) return;
    int m = idx >> 10, k = idx & 1023;
    float v = X[idx];
    __nv_bfloat16 hi = __float2bfloat16(v);
    __nv_bfloat16 lo = __float2bfloat16(v - __bfloat162float(hi));
    size_t r = (size_t)m * K2;
    out[r + k] = hi;
    out[r + 1024 + k] = lo;
}
// ---------------------------------------------------------------------------
// [hi|lo] pack+transpose of weight W[1024][N] -> out[N][2048]
// ---------------------------------------------------------------------------
__global__ __launch_bounds__(256)
void conv_b2(const float* __restrict__ W, __nv_bfloat16* __restrict__ out, int N) {
    __shared__ float t[32][33];
    int k0 = blockIdx.y * 32, n0 = blockIdx.x * 32;
    int tx = threadIdx.x & 31, ty = threadIdx.x >> 5;
#pragma unroll
    for (int i = 0; i < 32; i += 8)
        t[ty + i][tx] = W[(size_t)(k0 + ty + i) * N + n0 + tx];
    __syncthreads();
#pragma unroll
    for (int i = 0; i < 32; i += 8) {
        float v = t[tx][ty + i];
        __nv_bfloat16 hi = __float2bfloat16(v);
        __nv_bfloat16 lo = __float2bfloat16(v - __bfloat162float(hi));
        size_t r = (size_t)(n0 + ty + i) * K2;
        out[r + k0 + tx] = hi;
        out[r + 1024 + k0 + tx] = lo;
    }
}

// ---------------------------------------------------------------------------
// 3-pass split GEMM: C = Ah@Bh^T + Ah@Bl^T + Al@Bh^T  (fp32 accum)
// A,B pre-packed [hi|lo], K=1024 per term. CTA 128x128, chunk 32, 8 warps.
// smem: 2 buffers x {Ah,Al,Bh,Bl} tiles of 128x32 (LDA 40) = 81920 B dynamic.
// ---------------------------------------------------------------------------
#define LDA 40
#define TG3_TILE (128*LDA)
#define TG3_BUF  (4*TG3_TILE)
#define TG3_SMEM (2*TG3_BUF*2)   // 81920 bytes
__global__ __launch_bounds__(256)
void tgemm3(const __nv_bfloat16* __restrict__ A, const __nv_bfloat16* __restrict__ B,
            float* __restrict__ C, int N) {
    extern __shared__ __nv_bfloat16 sm3[];

    const int tid = threadIdx.x;
    const int wid = tid >> 5, lane = tid & 31;
    const int m0 = blockIdx.y * 128, n0 = blockIdx.x * 128;
    const int wm = (wid >> 2) * 64, wn = (wid & 3) * 32;

    const int lr = tid >> 1, lc = (tid & 1) * 16;
    const __nv_bfloat16* Agh = A + (size_t)(m0 + lr) * K2 + lc;
    const __nv_bfloat16* Agl = Agh + 1024;
    const __nv_bfloat16* Bgh = B + (size_t)(n0 + lr) * K2 + lc;
    const __nv_bfloat16* Bgl = Bgh + 1024;
    const int soff = lr * LDA + lc;

    float acc[4][4][4];
#pragma unroll
    for (int i = 0; i < 4; i++)
#pragma unroll
        for (int j = 0; j < 4; j++)
#pragma unroll
            for (int k = 0; k < 4; k++) acc[i][j][k] = 0.f;

    // preload buffer 0 (chunk 0)
    {
        __nv_bfloat16* d = sm3;
        *(uint4*)&d[soff]                = *(const uint4*)(Agh);
        *(uint4*)&d[soff + 8]            = *(const uint4*)(Agh + 8);
        *(uint4*)&d[TG3_TILE + soff]     = *(const uint4*)(Agl);
        *(uint4*)&d[TG3_TILE + soff + 8] = *(const uint4*)(Agl + 8);
        *(uint4*)&d[2*TG3_TILE + soff]     = *(const uint4*)(Bgh);
        *(uint4*)&d[2*TG3_TILE + soff + 8] = *(const uint4*)(Bgh + 8);
        *(uint4*)&d[3*TG3_TILE + soff]     = *(const uint4*)(Bgl);
        *(uint4*)&d[3*TG3_TILE + soff + 8] = *(const uint4*)(Bgl + 8);
    }
    __syncthreads();

    const int a_row = (lane & 15);
    const int a_koff = (lane >> 4) * 8;
    const int b_row = (lane & 7) + ((lane & 16) >> 1);
    const int b_koff = ((lane >> 3) & 1) * 8;

    for (int kt = 0; kt < 32; kt++) {
        const int cur = kt & 1;
        uint4 pa0, pa1, pb0, pb1, pc0, pc1, pd0, pd1;
        if (kt < 31) {
            const int off = (kt + 1) * 32;
            pa0 = *(const uint4*)(Agh + off); pa1 = *(const uint4*)(Agh + off + 8);
            pb0 = *(const uint4*)(Agl + off); pb1 = *(const uint4*)(Agl + off + 8);
            pc0 = *(const uint4*)(Bgh + off); pc1 = *(const uint4*)(Bgh + off + 8);
            pd0 = *(const uint4*)(Bgl + off); pd1 = *(const uint4*)(Bgl + off + 8);
        }
        const uint32_t base = smem_u32(&sm3[cur * TG3_BUF]);
        const uint32_t ahB = base;
        const uint32_t alB = base + TG3_TILE * 2;
        const uint32_t bhB = base + 2 * TG3_TILE * 2;
        const uint32_t blB = base + 3 * TG3_TILE * 2;
#pragma unroll
        for (int ks = 0; ks < 2; ks++) {
            const int k0 = ks * 16;
            uint32_t ah[4][4];
#pragma unroll
            for (int mt = 0; mt < 4; mt++)
                ldsm_x4(ah[mt][0], ah[mt][1], ah[mt][2], ah[mt][3],
                        ahB + ((wm + mt * 16 + a_row) * LDA + k0 + a_koff) * 2);
            uint32_t bh[2][4], bl[2][4];
#pragma unroll
            for (int nt2 = 0; nt2 < 2; nt2++) {
                ldsm_x4(bh[nt2][0], bh[nt2][1], bh[nt2][2], bh[nt2][3],
                        bhB + ((wn + nt2 * 16 + b_row) * LDA + k0 + b_koff) * 2);
                ldsm_x4(bl[nt2][0], bl[nt2][1], bl[nt2][2], bl[nt2][3],
                        blB + ((wn + nt2 * 16 + b_row) * LDA + k0 + b_koff) * 2);
            }
#pragma unroll
            for (int mt = 0; mt < 4; mt++)
#pragma unroll
                for (int nt = 0; nt < 4; nt++) {
                    mma_bf16(acc[mt][nt], ah[mt][0], ah[mt][1], ah[mt][2], ah[mt][3],
                             bh[nt >> 1][(nt & 1) * 2], bh[nt >> 1][(nt & 1) * 2 + 1]);
                    mma_bf16(acc[mt][nt], ah[mt][0], ah[mt][1], ah[mt][2], ah[mt][3],
                             bl[nt >> 1][(nt & 1) * 2], bl[nt >> 1][(nt & 1) * 2 + 1]);
                }
            uint32_t al[4][4];
#pragma unroll
            for (int mt = 0; mt < 4; mt++)
                ldsm_x4(al[mt][0], al[mt][1], al[mt][2], al[mt][3],
                        alB + ((wm + mt * 16 + a_row) * LDA + k0 + a_koff) * 2);
#pragma unroll
            for (int mt = 0; mt < 4; mt++)
#pragma unroll
                for (int nt = 0; nt < 4; nt++)
                    mma_bf16(acc[mt][nt], al[mt][0], al[mt][1], al[mt][2], al[mt][3],
                             bh[nt >> 1][(nt & 1) * 2], bh[nt >> 1][(nt & 1) * 2 + 1]);
        }
        if (kt < 31) {
            __nv_bfloat16* d = &sm3[(cur ^ 1) * TG3_BUF];
            *(uint4*)&d[soff]                = pa0;
            *(uint4*)&d[soff + 8]            = pa1;
            *(uint4*)&d[TG3_TILE + soff]     = pb0;
            *(uint4*)&d[TG3_TILE + soff + 8] = pb1;
            *(uint4*)&d[2*TG3_TILE + soff]     = pc0;
            *(uint4*)&d[2*TG3_TILE + soff + 8] = pc1;
            *(uint4*)&d[3*TG3_TILE + soff]     = pd0;
            *(uint4*)&d[3*TG3_TILE + soff + 8] = pd1;
            __syncthreads();
        }
    }

    const int er = lane >> 2, ec = (lane & 3) * 2;
#pragma unroll
    for (int mt = 0; mt < 4; mt++) {
        const int row = m0 + wm + mt * 16 + er;
#pragma unroll
        for (int nt = 0; nt < 4; nt++) {
            const int col = n0 + wn + nt * 8 + ec;
            *(float2*)&C[(size_t)row * N + col] =
                make_float2(acc[mt][nt][0], acc[mt][nt][1]);
            *(float2*)&C[(size_t)(row + 8) * N + col] =
                make_float2(acc[mt][nt][2], acc[mt][nt][3]);
        }
    }
}

// ---------------------------------------------------------------------------
// Pack content dims (0..63) of augmented Q/K from fused QKV buffer
// ---------------------------------------------------------------------------
__global__ __launch_bounds__(256)
void pack_content(const float* __restrict__ QKV, const float* __restrict__ alogit,
                  __nv_bfloat16* __restrict__ Qb, __nv_bfloat16* __restrict__ Kb) {
    int idx = blockIdx.x * blockDim.x + threadIdx.x;
    if (idx >= Lseq * Dm) return;
    int q = idx >> 10, c = idx & 1023;
    int h = c >> 6, d = c & 63;
    float alpha = 1.f / (1.f + expf(-alogit[h]));
    float vq = (1.f - alpha) * CONTENT_SCALE * QKV[(size_t)q * 3072 + c];
    float vk = QKV[(size_t)q * 3072 + 1024 + c];
    size_t base = ((size_t)h * Lseq + q) * KQ3;
    __nv_bfloat16 qh = __float2bfloat16(vq);
    __nv_bfloat16 ql = __float2bfloat16(vq - __bfloat162float(qh));
    Qb[base + d] = qh; Qb[base + 80 + d] = ql; Qb[base + 160 + d] = qh;
    __nv_bfloat16 kh = __float2bfloat16(vk);
    __nv_bfloat16 kl = __float2bfloat16(vk - __bfloat162float(kh));
    Kb[base + d] = kh; Kb[base + 80 + d] = kh; Kb[base + 160 + d] = kl;
}

// ---------------------------------------------------------------------------
// Phase dims (64..79) packed bf16x3, from fused QtKt buffer (stride 256)
// ---------------------------------------------------------------------------
__global__ __launch_bounds__(256)
void phase_pack(const float* __restrict__ QtKt,
                const float* __restrict__ bqp, const float* __restrict__ bkp,
                const float* __restrict__ alogit,
                __nv_bfloat16* __restrict__ Qb, __nv_bfloat16* __restrict__ Kb) {
    int idx = blockIdx.x * blockDim.x + threadIdx.x;
    if (idx >= Lseq * Pp) return;
    int q = idx >> 7, j = idx & 127;
    int h = j / PPH, i = j % PPH;
    int f = j >> 1;
    double invf = exp(-(double)f / 64.0 * log(10000.0));
    float pos = (float)((double)q * invf);
    float tq = QtKt[(size_t)q * 256 + j] + bqp[j] + pos;
    float tk = QtKt[(size_t)q * 256 + 128 + j] + bkp[j] + pos;
    float alpha = 1.f / (1.f + expf(-alogit[h]));
    float aps = alpha * PHASE_SCALE;
    size_t base = ((size_t)h * Lseq + q) * KQ3;
    float qv[2] = {aps * cosf(tq), aps * sinf(tq)};
    float kv[2] = {cosf(tk), sinf(tk)};
#pragma unroll
    for (int s = 0; s < 2; s++) {
        int d = 64 + s * 8 + i;
        __nv_bfloat16 qh = __float2bfloat16(qv[s]);
        __nv_bfloat16 ql = __float2bfloat16(qv[s] - __bfloat162float(qh));
        Qb[base + d] = qh; Qb[base + 80 + d] = ql; Qb[base + 160 + d] = qh;
        __nv_bfloat16 kh = __float2bfloat16(kv[s]);
        __nv_bfloat16 kl = __float2bfloat16(kv[s] - __bfloat162float(kh));
        Kb[base + d] = kh; Kb[base + 80 + d] = kh; Kb[base + 160 + d] = kl;
    }
}

// ---------------------------------------------------------------------------
// Transpose + hi/lo split of V (from fused QKV, col offset 2048, stride 3072)
// ---------------------------------------------------------------------------
__global__ __launch_bounds__(256)
void vt_pack(const float* __restrict__ QKV,
             __nv_bfloat16* __restrict__ Vth, __nv_bfloat16* __restrict__ Vtl) {
    __shared__ float t[32][33];
    int q0 = blockIdx.y * 32, c0 = blockIdx.x * 32;
    int tx = threadIdx.x & 31, ty = threadIdx.x >> 5;
#pragma unroll
    for (int i = 0; i < 32; i += 8)
        t[ty + i][tx] = QKV[(size_t)(q0 + ty + i) * 3072 + 2048 + c0 + tx];
    __syncthreads();
#pragma unroll
    for (int i = 0; i < 32; i += 8) {
        float v = t[tx][ty + i];
        int c = c0 + ty + i;
        size_t o = ((size_t)c) * Lseq + q0 + tx;
        __nv_bfloat16 hi = __float2bfloat16(v);
        Vth[o] = hi;
        Vtl[o] = __float2bfloat16(v - __bfloat162float(hi));
    }
}

// ---------------------------------------------------------------------------
// Tensor-core flash attention v3 (register-resident softmax, unchanged R6)
// ---------------------------------------------------------------------------
#define QS_STR 248
#define KS_STR 248
#define VS_STR 72
#define A3_QS  0
#define A3_KS  (A3_QS + 128*QS_STR*2)
#define A3_VH  (A3_KS + 64*KS_STR*2)
#define A3_VL  (A3_VH + 64*VS_STR*2)
#define A3_TOT (A3_VL + 64*VS_STR*2)

__global__ __launch_bounds__(256)
void attn3(const __nv_bfloat16* __restrict__ Qb, const __nv_bfloat16* __restrict__ Kb,
           const __nv_bfloat16* __restrict__ Vth, const __nv_bfloat16* __restrict__ Vtl,
           float* __restrict__ Out) {
    extern __shared__ char smraw[];
    __nv_bfloat16* Qs = (__nv_bfloat16*)(smraw + A3_QS);
    __nv_bfloat16* Ks = (__nv_bfloat16*)(smraw + A3_KS);
    __nv_bfloat16* Vh = (__nv_bfloat16*)(smraw + A3_VH);
    __nv_bfloat16* Vl = (__nv_bfloat16*)(smraw + A3_VL);

    const int tid = threadIdx.x;
    const int wid = tid >> 5, lane = tid & 31;
    const int h = blockIdx.y;
    const int qt = (int)gridDim.x - 1 - (int)blockIdx.x;
    const int q0 = qt * 128;
    const int wm = wid * 16;

    const int a_row = (lane & 15);
    const int a_koff = (lane >> 4) * 8;
    const int b_row = (lane & 7) + ((lane & 16) >> 1);
    const int b_koff = ((lane >> 3) & 1) * 8;
    const int er = lane >> 2, ec = (lane & 3) * 2;

    {
        const uint4* src = (const uint4*)(Qb + ((size_t)h * Lseq + q0) * KQ3);
        for (int i = tid; i < 128 * 30; i += 256) {
            int r = i / 30, c = i % 30;
            *(uint4*)&Qs[r * QS_STR + c * 8] = src[r * 30 + c];
        }
    }

    float m_run0 = NEG_BIG, m_run1 = NEG_BIG;
    float l_run0 = 0.f, l_run1 = 0.f;
    float acc_o[8][4];
#pragma unroll
    for (int d = 0; d < 8; d++)
#pragma unroll
        for (int c = 0; c < 4; c++) acc_o[d][c] = 0.f;
    __syncthreads();

    const uint32_t qsB = smem_u32(Qs);
    const uint32_t ksB = smem_u32(Ks);
    const uint32_t vhB = smem_u32(Vh);
    const uint32_t vlB = smem_u32(Vl);

    const int nkt = 2 * qt + 2;
    for (int kt = 0; kt < nkt; kt++) {
        const int k0 = kt * 64;
        {
            const uint4* src = (const uint4*)(Kb + ((size_t)h * Lseq + k0) * KQ3);
            for (int i = tid; i < 64 * 30; i += 256) {
                int r = i / 30, c = i % 30;
                *(uint4*)&Ks[r * KS_STR + c * 8] = src[r * 30 + c];
            }
            const __nv_bfloat16* vh = Vth + ((size_t)h * HD) * Lseq + k0;
            const __nv_bfloat16* vl = Vtl + ((size_t)h * HD) * Lseq + k0;
            for (int i = tid; i < 64 * 8; i += 256) {
                int d = i >> 3, c = i & 7;
                *(uint4*)&Vh[d * VS_STR + c * 8] =
                    *(const uint4*)(vh + (size_t)d * Lseq + c * 8);
                *(uint4*)&Vl[d * VS_STR + c * 8] =
                    *(const uint4*)(vl + (size_t)d * Lseq + c * 8);
            }
        }
        __syncthreads();

        float s[8][4];
#pragma unroll
        for (int nt = 0; nt < 8; nt++)
#pragma unroll
            for (int c = 0; c < 4; c++) s[nt][c] = 0.f;
#pragma unroll
        for (int ks = 0; ks < 15; ks++) {
            const int kk = ks * 16;
            uint32_t a0, a1, a2, a3;
            ldsm_x4(a0, a1, a2, a3, qsB + ((wm + a_row) * QS_STR + kk + a_koff) * 2);
            uint32_t bf[4][4];
#pragma unroll
            for (int nt2 = 0; nt2 < 4; nt2++)
                ldsm_x4(bf[nt2][0], bf[nt2][1], bf[nt2][2], bf[nt2][3],
                        ksB + ((nt2 * 16 + b_row) * KS_STR + kk + b_koff) * 2);
#pragma unroll
            for (int nt = 0; nt < 8; nt++)
                mma_bf16(s[nt], a0, a1, a2, a3,
                         bf[nt >> 1][(nt & 1) * 2], bf[nt >> 1][(nt & 1) * 2 + 1]);
        }

        if (kt >= 2 * qt) {
            const int r0 = q0 + wm + er, r1 = r0 + 8;
#pragma unroll
            for (int nt = 0; nt < 8; nt++) {
                const int c0 = k0 + nt * 8 + ec;
                if (c0     > r0) s[nt][0] = NEG_BIG;
                if (c0 + 1 > r0) s[nt][1] = NEG_BIG;
                if (c0     > r1) s[nt][2] = NEG_BIG;
                if (c0 + 1 > r1) s[nt][3] = NEG_BIG;
            }
        }

        float mx0 = s[0][0], mx1 = s[0][2];
#pragma unroll
        for (int nt = 0; nt < 8; nt++) {
            mx0 = fmaxf(mx0, fmaxf(s[nt][0], s[nt][1]));
            mx1 = fmaxf(mx1, fmaxf(s[nt][2], s[nt][3]));
        }
        mx0 = fmaxf(mx0, __shfl_xor_sync(0xffffffffu, mx0, 1));
        mx0 = fmaxf(mx0, __shfl_xor_sync(0xffffffffu, mx0, 2));
        mx1 = fmaxf(mx1, __shfl_xor_sync(0xffffffffu, mx1, 1));
        mx1 = fmaxf(mx1, __shfl_xor_sync(0xffffffffu, mx1, 2));
        float mnew0 = fmaxf(m_run0, mx0);
        float mnew1 = fmaxf(m_run1, mx1);
        float scale0 = __expf(m_run0 - mnew0);
        float scale1 = __expf(m_run1 - mnew1);

        float sum0 = 0.f, sum1 = 0.f;
#pragma unroll
        for (int nt = 0; nt < 8; nt++) {
            s[nt][0] = __expf(s[nt][0] - mnew0); sum0 += s[nt][0];
            s[nt][1] = __expf(s[nt][1] - mnew0); sum0 += s[nt][1];
            s[nt][2] = __expf(s[nt][2] - mnew1); sum1 += s[nt][2];
            s[nt][3] = __expf(s[nt][3] - mnew1); sum1 += s[nt][3];
        }
        sum0 += __shfl_xor_sync(0xffffffffu, sum0, 1);
        sum0 += __shfl_xor_sync(0xffffffffu, sum0, 2);
        sum1 += __shfl_xor_sync(0xffffffffu, sum1, 1);
        sum1 += __shfl_xor_sync(0xffffffffu, sum1, 2);
        m_run0 = mnew0; m_run1 = mnew1;
        l_run0 = l_run0 * scale0 + sum0;
        l_run1 = l_run1 * scale1 + sum1;

#pragma unroll
        for (int d = 0; d < 8; d++) {
            acc_o[d][0] *= scale0; acc_o[d][1] *= scale0;
            acc_o[d][2] *= scale1; acc_o[d][3] *= scale1;
        }

#pragma unroll
        for (int kk = 0; kk < 4; kk++) {
            float p00 = s[2*kk][0],   p01 = s[2*kk][1];
            float p02 = s[2*kk][2],   p03 = s[2*kk][3];
            float p10 = s[2*kk+1][0], p11 = s[2*kk+1][1];
            float p12 = s[2*kk+1][2], p13 = s[2*kk+1][3];
            uint32_t ah0 = pack_bf16x2(p00, p01);
            uint32_t ah1 = pack_bf16x2(p02, p03);
            uint32_t ah2 = pack_bf16x2(p10, p11);
            uint32_t ah3 = pack_bf16x2(p12, p13);
            __nv_bfloat162* hv;
            hv = (__nv_bfloat162*)&ah0;
            uint32_t al0 = pack_bf16x2(p00 - __bfloat162float(hv->x), p01 - __bfloat162float(hv->y));
            hv = (__nv_bfloat162*)&ah1;
            uint32_t al1 = pack_bf16x2(p02 - __bfloat162float(hv->x), p03 - __bfloat162float(hv->y));
            hv = (__nv_bfloat162*)&ah2;
            uint32_t al2 = pack_bf16x2(p10 - __bfloat162float(hv->x), p11 - __bfloat162float(hv->y));
            hv = (__nv_bfloat162*)&ah3;
            uint32_t al3 = pack_bf16x2(p12 - __bfloat162float(hv->x), p13 - __bfloat162float(hv->y));

            const int kko = kk * 16;
            uint32_t bh[4][4], bl[4][4];
#pragma unroll
            for (int dt2 = 0; dt2 < 4; dt2++) {
                ldsm_x4(bh[dt2][0], bh[dt2][1], bh[dt2][2], bh[dt2][3],
                        vhB + ((dt2 * 16 + b_row) * VS_STR + kko + b_koff) * 2);
                ldsm_x4(bl[dt2][0], bl[dt2][1], bl[dt2][2], bl[dt2][3],
                        vlB + ((dt2 * 16 + b_row) * VS_STR + kko + b_koff) * 2);
            }
#pragma unroll
            for (int dt = 0; dt < 8; dt++) {
                uint32_t b0h = bh[dt >> 1][(dt & 1) * 2], b1h = bh[dt >> 1][(dt & 1) * 2 + 1];
                uint32_t b0l = bl[dt >> 1][(dt & 1) * 2], b1l = bl[dt >> 1][(dt & 1) * 2 + 1];
                mma_bf16(acc_o[dt], ah0, ah1, ah2, ah3, b0h, b1h);
                mma_bf16(acc_o[dt], al0, al1, al2, al3, b0h, b1h);
                mma_bf16(acc_o[dt], ah0, ah1, ah2, ah3, b0l, b1l);
            }
        }
        __syncthreads();
    }

    const float inv0 = 1.f / l_run0;
    const float inv1 = 1.f / l_run1;
    const int row0 = q0 + wm + er;
#pragma unroll
    for (int dt = 0; dt < 8; dt++) {
        const int col = h * HD + dt * 8 + ec;
        *(float2*)&Out[(size_t)row0 * Dm + col] =
            make_float2(acc_o[dt][0] * inv0, acc_o[dt][1] * inv0);
        *(float2*)&Out[(size_t)(row0 + 8) * Dm + col] =
            make_float2(acc_o[dt][2] * inv1, acc_o[dt][3] * inv1);
    }
}

// ---------------------------------------------------------------------------
__global__ __launch_bounds__(256)
void ln_kernel(const float* __restrict__ xr, const float* __restrict__ proj,
               const float* __restrict__ gamma, const float* __restrict__ beta,
               float* __restrict__ out) {
    const int row = blockIdx.x;
    const int tid = threadIdx.x;
    __shared__ float red[2][8];
    const float* a = xr + (long)row * Dm;
    const float* b = proj + (long)row * Dm;
    float s = 0.f, s2 = 0.f;
    for (int i = tid; i < Dm; i += 256) {
        float v = a[i] + b[i];
        s += v; s2 += v * v;
    }
#pragma unroll
    for (int o = 16; o; o >>= 1) {
        s  += __shfl_xor_sync(0xffffffffu, s,  o);
        s2 += __shfl_xor_sync(0xffffffffu, s2, o);
    }
    if ((tid & 31) == 0) { red[0][tid >> 5] = s; red[1][tid >> 5] = s2; }
    __syncthreads();
    if (tid < 32) {
        s  = (tid < 8) ? red[0][tid] : 0.f;
        s2 = (tid < 8) ? red[1][tid] : 0.f;
#pragma unroll
        for (int o = 4; o; o >>= 1) {
            s  += __shfl_xor_sync(0xffffffffu, s,  o);
            s2 += __shfl_xor_sync(0xffffffffu, s2, o);
        }
        if (tid == 0) { red[0][0] = s; red[1][0] = s2; }
    }
    __syncthreads();
    float mu = red[0][0] * (1.f / Dm);
    float var = red[1][0] * (1.f / Dm) - mu * mu;
    float rstd = rsqrtf(var + 1e-5f);
    for (int i = tid; i < Dm; i += 256) {
        float v = a[i] + b[i];
        out[(long)row * Dm + i] = (v - mu) * rstd * gamma[i] + beta[i];
    }
}

// ---------------------------------------------------------------------------
extern "C" void kernel_launch(void* const* d_in, const int* in_sizes, int n_in,
                              void* d_out, int out_size) {
    const float* x_real = (const float*)d_in[0];
    const float* x_imag = (const float*)d_in[1];
    const float* Wq     = (const float*)d_in[2];
    const float* Wk     = (const float*)d_in[3];
    const float* Wv     = (const float*)d_in[4];
    const float* Wqp    = (const float*)d_in[5];
    const float* bqp    = (const float*)d_in[6];
    const float* Wkp    = (const float*)d_in[7];
    const float* bkp    = (const float*)d_in[8];
    const float* Wo     = (const float*)d_in[9];
    const float* alogit = (const float*)d_in[10];
    const float* lng    = (const float*)d_in[11];
    const float* lnb    = (const float*)d_in[12];

    float *pQKV, *pQtKt, *pAO, *pP2;
    __nv_bfloat16 *pAb, *pAib, *pAOb, *pBqkv, *pBp2, *pBo;
    __nv_bfloat16 *pQb, *pKb, *pVth, *pVtl;
    cudaGetSymbolAddress((void**)&pQKV,  g_QKV);
    cudaGetSymbolAddress((void**)&pQtKt, g_QtKt);
    cudaGetSymbolAddress((void**)&pAO,   g_AO);
    cudaGetSymbolAddress((void**)&pP2,   g_P2);
    cudaGetSymbolAddress((void**)&pAb,   g_Ab);
    cudaGetSymbolAddress((void**)&pAib,  g_Aib);
    cudaGetSymbolAddress((void**)&pAOb,  g_AOb);
    cudaGetSymbolAddress((void**)&pBqkv, g_Bqkv);
    cudaGetSymbolAddress((void**)&pBp2,  g_Bp2);
    cudaGetSymbolAddress((void**)&pBo,   g_Bo);
    cudaGetSymbolAddress((void**)&pQb,   g_Qb);
    cudaGetSymbolAddress((void**)&pKb,   g_Kb);
    cudaGetSymbolAddress((void**)&pVth,  g_Vth);
    cudaGetSymbolAddress((void**)&pVtl,  g_Vtl);

    cudaFuncSetAttribute(tgemm3, cudaFuncAttributeMaxDynamicSharedMemorySize, TG3_SMEM);
    cudaFuncSetAttribute(attn3, cudaFuncAttributeMaxDynamicSharedMemorySize, A3_TOT);

    dim3 cbg(Dm / 32, Dm / 32);
    dim3 cbp(Pp / 32, Dm / 32);

    // Launch order arranged so ncu's fixed slot (-s 5) lands on the QKV GEMM.
    conv_a2<<<(Lseq * Dm) / 256, 256>>>(x_real, pAb);                     // 0
    conv_b2<<<cbg, 256>>>(Wq, pBqkv,                      Dm);            // 1
    conv_b2<<<cbg, 256>>>(Wk, pBqkv + (size_t)Dm * K2,    Dm);            // 2
    conv_b2<<<cbg, 256>>>(Wv, pBqkv + (size_t)2 * Dm * K2, Dm);           // 3
    conv_a2<<<(Lseq * Dm) / 256, 256>>>(x_imag, pAib);                    // 4
    tgemm3<<<dim3(3 * Dm / 128, Lseq / 128), 256, TG3_SMEM>>>(pAb, pBqkv, pQKV, 3 * Dm); // 5
    conv_b2<<<cbp, 256>>>(Wqp, pBp2,                  Pp);                // 6
    conv_b2<<<cbp, 256>>>(Wkp, pBp2 + (size_t)Pp * K2, Pp);               // 7
    tgemm3<<<dim3(2 * Pp / 128, Lseq / 128), 256, TG3_SMEM>>>(pAib, pBp2, pQtKt, 2 * Pp); // 8

    pack_content<<<(Lseq * Dm) / 256, 256>>>(pQKV, alogit, pQb, pKb);
    phase_pack<<<(Lseq * Pp) / 256, 256>>>(pQtKt, bqp, bkp, alogit, pQb, pKb);
    vt_pack<<<dim3(Dm / 32, Lseq / 32), 256>>>(pQKV, pVth, pVtl);

    attn3<<<dim3(Lseq / 128, Hh), 256, A3_TOT>>>(pQb, pKb, pVth, pVtl, pAO);

    conv_b2<<<cbg, 256>>>(Wo, pBo, Dm);
    conv_a2<<<(Lseq * Dm) / 256, 256>>>(pAO, pAOb);
    tgemm3<<<dim3(Dm / 128, Lseq / 128), 256, TG3_SMEM>>>(pAOb, pBo, pP2, Dm);
    ln_kernel<<<Lseq, 256>>>(x_real, pP2, lng, lnb, (float*)d_out);

    if (out_size >= 2 * Lseq * Dm) {
        cudaMemcpyAsync((float*)d_out + (long)Lseq * Dm, x_imag,
                        (size_t)Lseq * Dm * sizeof(float),
                        cudaMemcpyDeviceToDevice);
    }
}

// round 8
// speedup vs baseline: 2.4866x; 1.0696x over previous
#include <cuda_runtime.h>
#include <cuda_bf16.h>
#include <math.h>
#include <stdint.h>

#define Lseq 2048
#define Dm   1024
#define Hh   16
#define HD   64
#define Pp   128
#define PPH  8
#define DA   80
#define KQ3  240       // 3*80 packed augmented dim for attention S
#define K2   2048      // [hi|lo] packed K for projection GEMMs
#define CONTENT_SCALE 0.125f
#define PHASE_SCALE   0.35355339059327373f
#define NEG_BIG (-1e30f)

// ---------------- scratch (static device globals) ----------------
__device__ float g_QKV[Lseq*3*Dm];
__device__ float g_QtKt[Lseq*2*Pp];
__device__ float g_AO[Lseq*Dm];
__device__ float g_P2[Lseq*Dm];
__device__ __nv_bfloat16 g_Ab  [Lseq*K2];
__device__ __nv_bfloat16 g_Aib [Lseq*K2];
__device__ __nv_bfloat16 g_AOb [Lseq*K2];
__device__ __nv_bfloat16 g_Bqkv[3*Dm*K2];
__device__ __nv_bfloat16 g_Bp2 [2*Pp*K2];
__device__ __nv_bfloat16 g_Bo  [Dm*K2];
__device__ __nv_bfloat16 g_Qb [Hh*Lseq*KQ3];
__device__ __nv_bfloat16 g_Kb [Hh*Lseq*KQ3];
__device__ __nv_bfloat16 g_Vth[Hh*HD*Lseq];
__device__ __nv_bfloat16 g_Vtl[Hh*HD*Lseq];

// ---------------- helpers ----------------
__device__ __forceinline__ uint32_t smem_u32(const void* p) {
    uint32_t a;
    asm("{ .reg .u64 t; cvta.to.shared.u64 t, %1; cvt.u32.u64 %0, t; }" : "=r"(a) : "l"(p));
    return a;
}
__device__ __forceinline__ void ldsm_x4(uint32_t& r0, uint32_t& r1, uint32_t& r2,
                                        uint32_t& r3, uint32_t addr) {
    asm volatile("ldmatrix.sync.aligned.m8n8.x4.shared.b16 {%0,%1,%2,%3}, [%4];"
                 : "=r"(r0), "=r"(r1), "=r"(r2), "=r"(r3) : "r"(addr));
}
__device__ __forceinline__ void mma_bf16(float* c, uint32_t a0, uint32_t a1,
                                         uint32_t a2, uint32_t a3,
                                         uint32_t b0, uint32_t b1) {
    asm volatile(
        "mma.sync.aligned.m16n8k16.row.col.f32.bf16.bf16.f32 "
        "{%0,%1,%2,%3}, {%4,%5,%6,%7}, {%8,%9}, {%0,%1,%2,%3};"
        : "+f"(c[0]), "+f"(c[1]), "+f"(c[2]), "+f"(c[3])
        : "r"(a0), "r"(a1), "r"(a2), "r"(a3), "r"(b0), "r"(b1));
}
__device__ __forceinline__ uint32_t pack_bf16x2(float a, float b) {
    __nv_bfloat162 h = __floats2bfloat162_rn(a, b);
    return *(uint32_t*)&h;
}
__device__ __forceinline__ void cp_async16(uint32_t dst, const void* src) {
    asm volatile("cp.async.cg.shared.global [%0], [%1], 16;" :: "r"(dst), "l"(src));
}
#define CP_COMMIT() asm volatile("cp.async.commit_group;" ::: "memory")
#define CP_WAIT0()  asm volatile("cp.async.wait_group 0;" ::: "memory")

// ---------------------------------------------------------------------------
// [hi|lo] pack of activation X[M][1024] -> out[M][2048]
// ---------------------------------------------------------------------------
__global__ __launch_bounds__(256)
void conv_a2(const float* __restrict__ X, __nv_bfloat16* __restrict__ out) {
    int idx = blockIdx.x * 256 + threadIdx.x;
    if (idx >= Lseq * Dm) return;
    int m = idx >> 10, k = idx & 1023;
    float v = X[idx];
    __nv_bfloat16 hi = __float2bfloat16(v);
    __nv_bfloat16 lo = __float2bfloat16(v - __bfloat162float(hi));
    size_t r = (size_t)m * K2;
    out[r + k] = hi;
    out[r + 1024 + k] = lo;
}
// ---------------------------------------------------------------------------
// [hi|lo] pack+transpose of weight W[1024][N] -> out[N][2048]
// ---------------------------------------------------------------------------
__global__ __launch_bounds__(256)
void conv_b2(const float* __restrict__ W, __nv_bfloat16* __restrict__ out, int N) {
    __shared__ float t[32][33];
    int k0 = blockIdx.y * 32, n0 = blockIdx.x * 32;
    int tx = threadIdx.x & 31, ty = threadIdx.x >> 5;
#pragma unroll
    for (int i = 0; i < 32; i += 8)
        t[ty + i][tx] = W[(size_t)(k0 + ty + i) * N + n0 + tx];
    __syncthreads();
#pragma unroll
    for (int i = 0; i < 32; i += 8) {
        float v = t[tx][ty + i];
        __nv_bfloat16 hi = __float2bfloat16(v);
        __nv_bfloat16 lo = __float2bfloat16(v - __bfloat162float(hi));
        size_t r = (size_t)(n0 + ty + i) * K2;
        out[r + k0 + tx] = hi;
        out[r + 1024 + k0 + tx] = lo;
    }
}

// ---------------------------------------------------------------------------
// 3-pass split GEMM with cp.async pipelining.
// C = Ah@Bh^T + Ah@Bl^T + Al@Bh^T. CTA 128x128, chunk 32, 8 warps.
// ---------------------------------------------------------------------------
#define LDA 40
#define TG3_TILE (128*LDA)
#define TG3_BUF  (4*TG3_TILE)
#define TG3_SMEM (2*TG3_BUF*2)   // 81920 bytes
__global__ __launch_bounds__(256)
void tgemm3(const __nv_bfloat16* __restrict__ A, const __nv_bfloat16* __restrict__ B,
            float* __restrict__ C, int N) {
    extern __shared__ __nv_bfloat16 sm3[];

    const int tid = threadIdx.x;
    const int wid = tid >> 5, lane = tid & 31;
    const int m0 = blockIdx.y * 128, n0 = blockIdx.x * 128;
    const int wm = (wid >> 2) * 64, wn = (wid & 3) * 32;

    const int lr = tid >> 1, lc = (tid & 1) * 16;
    const __nv_bfloat16* Agh = A + (size_t)(m0 + lr) * K2 + lc;
    const __nv_bfloat16* Agl = Agh + 1024;
    const __nv_bfloat16* Bgh = B + (size_t)(n0 + lr) * K2 + lc;
    const __nv_bfloat16* Bgl = Bgh + 1024;
    const uint32_t smB = smem_u32(sm3);
    const uint32_t so = (uint32_t)(lr * LDA + lc) * 2;

    float acc[4][4][4];
#pragma unroll
    for (int i = 0; i < 4; i++)
#pragma unroll
        for (int j = 0; j < 4; j++)
#pragma unroll
            for (int k = 0; k < 4; k++) acc[i][j][k] = 0.f;

    // cp.async chunk loader: 8 x 16B per thread
    auto ld_chunk = [&](int kt, int buf) {
        const uint32_t d = smB + (uint32_t)buf * TG3_BUF * 2;
        const int off = kt * 32;
        cp_async16(d + so,                      Agh + off);
        cp_async16(d + so + 16,                 Agh + off + 8);
        cp_async16(d + TG3_TILE*2 + so,         Agl + off);
        cp_async16(d + TG3_TILE*2 + so + 16,    Agl + off + 8);
        cp_async16(d + 2*TG3_TILE*2 + so,       Bgh + off);
        cp_async16(d + 2*TG3_TILE*2 + so + 16,  Bgh + off + 8);
        cp_async16(d + 3*TG3_TILE*2 + so,       Bgl + off);
        cp_async16(d + 3*TG3_TILE*2 + so + 16,  Bgl + off + 8);
    };

    ld_chunk(0, 0);
    CP_COMMIT();
    CP_WAIT0();
    __syncthreads();

    const int a_row = (lane & 15);
    const int a_koff = (lane >> 4) * 8;
    const int b_row = (lane & 7) + ((lane & 16) >> 1);
    const int b_koff = ((lane >> 3) & 1) * 8;

    for (int kt = 0; kt < 32; kt++) {
        const int cur = kt & 1;
        if (kt < 31) {
            ld_chunk(kt + 1, cur ^ 1);
            CP_COMMIT();
        }
        const uint32_t base = smB + (uint32_t)cur * TG3_BUF * 2;
        const uint32_t ahB = base;
        const uint32_t alB = base + TG3_TILE * 2;
        const uint32_t bhB = base + 2 * TG3_TILE * 2;
        const uint32_t blB = base + 3 * TG3_TILE * 2;
#pragma unroll
        for (int ks = 0; ks < 2; ks++) {
            const int k0 = ks * 16;
            uint32_t ah[4][4];
#pragma unroll
            for (int mt = 0; mt < 4; mt++)
                ldsm_x4(ah[mt][0], ah[mt][1], ah[mt][2], ah[mt][3],
                        ahB + ((wm + mt * 16 + a_row) * LDA + k0 + a_koff) * 2);
            uint32_t bh[2][4], bl[2][4];
#pragma unroll
            for (int nt2 = 0; nt2 < 2; nt2++) {
                ldsm_x4(bh[nt2][0], bh[nt2][1], bh[nt2][2], bh[nt2][3],
                        bhB + ((wn + nt2 * 16 + b_row) * LDA + k0 + b_koff) * 2);
                ldsm_x4(bl[nt2][0], bl[nt2][1], bl[nt2][2], bl[nt2][3],
                        blB + ((wn + nt2 * 16 + b_row) * LDA + k0 + b_koff) * 2);
            }
#pragma unroll
            for (int mt = 0; mt < 4; mt++)
#pragma unroll
                for (int nt = 0; nt < 4; nt++) {
                    mma_bf16(acc[mt][nt], ah[mt][0], ah[mt][1], ah[mt][2], ah[mt][3],
                             bh[nt >> 1][(nt & 1) * 2], bh[nt >> 1][(nt & 1) * 2 + 1]);
                    mma_bf16(acc[mt][nt], ah[mt][0], ah[mt][1], ah[mt][2], ah[mt][3],
                             bl[nt >> 1][(nt & 1) * 2], bl[nt >> 1][(nt & 1) * 2 + 1]);
                }
            uint32_t al[4][4];
#pragma unroll
            for (int mt = 0; mt < 4; mt++)
                ldsm_x4(al[mt][0], al[mt][1], al[mt][2], al[mt][3],
                        alB + ((wm + mt * 16 + a_row) * LDA + k0 + a_koff) * 2);
#pragma unroll
            for (int mt = 0; mt < 4; mt++)
#pragma unroll
                for (int nt = 0; nt < 4; nt++)
                    mma_bf16(acc[mt][nt], al[mt][0], al[mt][1], al[mt][2], al[mt][3],
                             bh[nt >> 1][(nt & 1) * 2], bh[nt >> 1][(nt & 1) * 2 + 1]);
        }
        if (kt < 31) {
            CP_WAIT0();
            __syncthreads();
        }
    }

    const int er = lane >> 2, ec = (lane & 3) * 2;
#pragma unroll
    for (int mt = 0; mt < 4; mt++) {
        const int row = m0 + wm + mt * 16 + er;
#pragma unroll
        for (int nt = 0; nt < 4; nt++) {
            const int col = n0 + wn + nt * 8 + ec;
            *(float2*)&C[(size_t)row * N + col] =
                make_float2(acc[mt][nt][0], acc[mt][nt][1]);
            *(float2*)&C[(size_t)(row + 8) * N + col] =
                make_float2(acc[mt][nt][2], acc[mt][nt][3]);
        }
    }
}

// ---------------------------------------------------------------------------
// Pack content dims (0..63) of augmented Q/K from fused QKV buffer
// ---------------------------------------------------------------------------
__global__ __launch_bounds__(256)
void pack_content(const float* __restrict__ QKV, const float* __restrict__ alogit,
                  __nv_bfloat16* __restrict__ Qb, __nv_bfloat16* __restrict__ Kb) {
    int idx = blockIdx.x * blockDim.x + threadIdx.x;
    if (idx >= Lseq * Dm) return;
    int q = idx >> 10, c = idx & 1023;
    int h = c >> 6, d = c & 63;
    float alpha = 1.f / (1.f + expf(-alogit[h]));
    float vq = (1.f - alpha) * CONTENT_SCALE * QKV[(size_t)q * 3072 + c];
    float vk = QKV[(size_t)q * 3072 + 1024 + c];
    size_t base = ((size_t)h * Lseq + q) * KQ3;
    __nv_bfloat16 qh = __float2bfloat16(vq);
    __nv_bfloat16 ql = __float2bfloat16(vq - __bfloat162float(qh));
    Qb[base + d] = qh; Qb[base + 80 + d] = ql; Qb[base + 160 + d] = qh;
    __nv_bfloat16 kh = __float2bfloat16(vk);
    __nv_bfloat16 kl = __float2bfloat16(vk - __bfloat162float(kh));
    Kb[base + d] = kh; Kb[base + 80 + d] = kh; Kb[base + 160 + d] = kl;
}

// ---------------------------------------------------------------------------
// Phase dims (64..79) packed bf16x3
// ---------------------------------------------------------------------------
__global__ __launch_bounds__(256)
void phase_pack(const float* __restrict__ QtKt,
                const float* __restrict__ bqp, const float* __restrict__ bkp,
                const float* __restrict__ alogit,
                __nv_bfloat16* __restrict__ Qb, __nv_bfloat16* __restrict__ Kb) {
    int idx = blockIdx.x * blockDim.x + threadIdx.x;
    if (idx >= Lseq * Pp) return;
    int q = idx >> 7, j = idx & 127;
    int h = j / PPH, i = j % PPH;
    int f = j >> 1;
    double invf = exp(-(double)f / 64.0 * log(10000.0));
    float pos = (float)((double)q * invf);
    float tq = QtKt[(size_t)q * 256 + j] + bqp[j] + pos;
    float tk = QtKt[(size_t)q * 256 + 128 + j] + bkp[j] + pos;
    float alpha = 1.f / (1.f + expf(-alogit[h]));
    float aps = alpha * PHASE_SCALE;
    size_t base = ((size_t)h * Lseq + q) * KQ3;
    float qv[2] = {aps * cosf(tq), aps * sinf(tq)};
    float kv[2] = {cosf(tk), sinf(tk)};
#pragma unroll
    for (int s = 0; s < 2; s++) {
        int d = 64 + s * 8 + i;
        __nv_bfloat16 qh = __float2bfloat16(qv[s]);
        __nv_bfloat16 ql = __float2bfloat16(qv[s] - __bfloat162float(qh));
        Qb[base + d] = qh; Qb[base + 80 + d] = ql; Qb[base + 160 + d] = qh;
        __nv_bfloat16 kh = __float2bfloat16(kv[s]);
        __nv_bfloat16 kl = __float2bfloat16(kv[s] - __bfloat162float(kh));
        Kb[base + d] = kh; Kb[base + 80 + d] = kh; Kb[base + 160 + d] = kl;
    }
}

// ---------------------------------------------------------------------------
// Transpose + hi/lo split of V
// ---------------------------------------------------------------------------
__global__ __launch_bounds__(256)
void vt_pack(const float* __restrict__ QKV,
             __nv_bfloat16* __restrict__ Vth, __nv_bfloat16* __restrict__ Vtl) {
    __shared__ float t[32][33];
    int q0 = blockIdx.y * 32, c0 = blockIdx.x * 32;
    int tx = threadIdx.x & 31, ty = threadIdx.x >> 5;
#pragma unroll
    for (int i = 0; i < 32; i += 8)
        t[ty + i][tx] = QKV[(size_t)(q0 + ty + i) * 3072 + 2048 + c0 + tx];
    __syncthreads();
#pragma unroll
    for (int i = 0; i < 32; i += 8) {
        float v = t[tx][ty + i];
        int c = c0 + ty + i;
        size_t o = ((size_t)c) * Lseq + q0 + tx;
        __nv_bfloat16 hi = __float2bfloat16(v);
        Vth[o] = hi;
        Vtl[o] = __float2bfloat16(v - __bfloat162float(hi));
    }
}

// ---------------------------------------------------------------------------
// Tensor-core flash attention v4: register softmax + cp.async double-buffered
// K'/V stages + Q fragments hoisted into registers.
// smem layout: [stage0: Ks|Vh|Vl][stage1: Ks|Vh|Vl][Qs]
// ---------------------------------------------------------------------------
#define QS_STR 248
#define KS_STR 248
#define VS_STR 72
#define A4B_VH (64*KS_STR*2)
#define A4B_VL (A4B_VH + 64*VS_STR*2)
#define A4B_SZ (A4B_VL + 64*VS_STR*2)      // 50176 per stage
#define A4_QS  (2*A4B_SZ)                  // 100352
#define A4_TOT (A4_QS + 128*QS_STR*2)      // 163840

__global__ __launch_bounds__(256)
void attn4(const __nv_bfloat16* __restrict__ Qb, const __nv_bfloat16* __restrict__ Kb,
           const __nv_bfloat16* __restrict__ Vth, const __nv_bfloat16* __restrict__ Vtl,
           float* __restrict__ Out) {
    extern __shared__ char smraw[];
    const uint32_t smB = smem_u32(smraw);
    __nv_bfloat16* Qs = (__nv_bfloat16*)(smraw + A4_QS);

    const int tid = threadIdx.x;
    const int wid = tid >> 5, lane = tid & 31;
    const int h = blockIdx.y;
    const int qt = (int)gridDim.x - 1 - (int)blockIdx.x;
    const int q0 = qt * 128;
    const int wm = wid * 16;

    const int a_row = (lane & 15);
    const int a_koff = (lane >> 4) * 8;
    const int b_row = (lane & 7) + ((lane & 16) >> 1);
    const int b_koff = ((lane >> 3) & 1) * 8;
    const int er = lane >> 2, ec = (lane & 3) * 2;

    const __nv_bfloat16* KbH = Kb + ((size_t)h * Lseq) * KQ3;
    const __nv_bfloat16* VhH = Vth + ((size_t)h * HD) * Lseq;
    const __nv_bfloat16* VlH = Vtl + ((size_t)h * HD) * Lseq;

    // cp.async tile loader into stage s
    auto ld_tile = [&](int kt, int s) {
        const int k0 = kt * 64;
        const uint32_t stB = smB + (uint32_t)s * A4B_SZ;
        const __nv_bfloat16* ks = KbH + (size_t)k0 * KQ3;
        for (int i = tid; i < 64 * 30; i += 256) {
            int r = i / 30, c = i % 30;
            cp_async16(stB + ((uint32_t)(r * KS_STR + c * 8) << 1), ks + r * KQ3 + c * 8);
        }
        for (int i = tid; i < 64 * 8; i += 256) {
            int d = i >> 3, c = i & 7;
            uint32_t off = (uint32_t)(d * VS_STR + c * 8) << 1;
            const size_t go = (size_t)d * Lseq + k0 + c * 8;
            cp_async16(stB + A4B_VH + off, VhH + go);
            cp_async16(stB + A4B_VL + off, VlH + go);
        }
    };

    // prologue: start tile 0; stage Q to smem
    ld_tile(0, 0);
    CP_COMMIT();
    {
        const uint4* src = (const uint4*)(Qb + ((size_t)h * Lseq + q0) * KQ3);
        for (int i = tid; i < 128 * 30; i += 256) {
            int r = i / 30, c = i % 30;
            *(uint4*)&Qs[r * QS_STR + c * 8] = src[r * 30 + c];
        }
    }
    CP_WAIT0();
    __syncthreads();

    // hoist Q A-fragments (15 k-steps) into registers
    uint32_t qf[15][4];
    {
        const uint32_t qsB = smem_u32(Qs);
#pragma unroll
        for (int ks = 0; ks < 15; ks++)
            ldsm_x4(qf[ks][0], qf[ks][1], qf[ks][2], qf[ks][3],
                    qsB + ((wm + a_row) * QS_STR + ks * 16 + a_koff) * 2);
    }

    float m_run0 = NEG_BIG, m_run1 = NEG_BIG;
    float l_run0 = 0.f, l_run1 = 0.f;
    float acc_o[8][4];
#pragma unroll
    for (int d = 0; d < 8; d++)
#pragma unroll
        for (int c = 0; c < 4; c++) acc_o[d][c] = 0.f;

    const int nkt = 2 * qt + 2;
    for (int kt = 0; kt < nkt; kt++) {
        const int k0 = kt * 64;
        const int cur = kt & 1;
        if (kt + 1 < nkt) {
            ld_tile(kt + 1, cur ^ 1);
            CP_COMMIT();
        }
        const uint32_t stB = smB + (uint32_t)cur * A4B_SZ;
        const uint32_t ksB = stB;
        const uint32_t vhB = stB + A4B_VH;
        const uint32_t vlB = stB + A4B_VL;

        // ---- S = Q'(16 rows) @ K'^T(64 cols), K=240 ----
        float s[8][4];
#pragma unroll
        for (int nt = 0; nt < 8; nt++)
#pragma unroll
            for (int c = 0; c < 4; c++) s[nt][c] = 0.f;
#pragma unroll
        for (int ks = 0; ks < 15; ks++) {
            const int kk = ks * 16;
            uint32_t bf[4][4];
#pragma unroll
            for (int nt2 = 0; nt2 < 4; nt2++)
                ldsm_x4(bf[nt2][0], bf[nt2][1], bf[nt2][2], bf[nt2][3],
                        ksB + ((nt2 * 16 + b_row) * KS_STR + kk + b_koff) * 2);
#pragma unroll
            for (int nt = 0; nt < 8; nt++)
                mma_bf16(s[nt], qf[ks][0], qf[ks][1], qf[ks][2], qf[ks][3],
                         bf[nt >> 1][(nt & 1) * 2], bf[nt >> 1][(nt & 1) * 2 + 1]);
        }

        // ---- causal mask ----
        if (kt >= 2 * qt) {
            const int r0 = q0 + wm + er, r1 = r0 + 8;
#pragma unroll
            for (int nt = 0; nt < 8; nt++) {
                const int c0 = k0 + nt * 8 + ec;
                if (c0     > r0) s[nt][0] = NEG_BIG;
                if (c0 + 1 > r0) s[nt][1] = NEG_BIG;
                if (c0     > r1) s[nt][2] = NEG_BIG;
                if (c0 + 1 > r1) s[nt][3] = NEG_BIG;
            }
        }

        // ---- online softmax (register + quad shfl) ----
        float mx0 = s[0][0], mx1 = s[0][2];
#pragma unroll
        for (int nt = 0; nt < 8; nt++) {
            mx0 = fmaxf(mx0, fmaxf(s[nt][0], s[nt][1]));
            mx1 = fmaxf(mx1, fmaxf(s[nt][2], s[nt][3]));
        }
        mx0 = fmaxf(mx0, __shfl_xor_sync(0xffffffffu, mx0, 1));
        mx0 = fmaxf(mx0, __shfl_xor_sync(0xffffffffu, mx0, 2));
        mx1 = fmaxf(mx1, __shfl_xor_sync(0xffffffffu, mx1, 1));
        mx1 = fmaxf(mx1, __shfl_xor_sync(0xffffffffu, mx1, 2));
        float mnew0 = fmaxf(m_run0, mx0);
        float mnew1 = fmaxf(m_run1, mx1);
        float scale0 = __expf(m_run0 - mnew0);
        float scale1 = __expf(m_run1 - mnew1);

        float sum0 = 0.f, sum1 = 0.f;
#pragma unroll
        for (int nt = 0; nt < 8; nt++) {
            s[nt][0] = __expf(s[nt][0] - mnew0); sum0 += s[nt][0];
            s[nt][1] = __expf(s[nt][1] - mnew0); sum0 += s[nt][1];
            s[nt][2] = __expf(s[nt][2] - mnew1); sum1 += s[nt][2];
            s[nt][3] = __expf(s[nt][3] - mnew1); sum1 += s[nt][3];
        }
        sum0 += __shfl_xor_sync(0xffffffffu, sum0, 1);
        sum0 += __shfl_xor_sync(0xffffffffu, sum0, 2);
        sum1 += __shfl_xor_sync(0xffffffffu, sum1, 1);
        sum1 += __shfl_xor_sync(0xffffffffu, sum1, 2);
        m_run0 = mnew0; m_run1 = mnew1;
        l_run0 = l_run0 * scale0 + sum0;
        l_run1 = l_run1 * scale1 + sum1;

#pragma unroll
        for (int d = 0; d < 8; d++) {
            acc_o[d][0] *= scale0; acc_o[d][1] *= scale0;
            acc_o[d][2] *= scale1; acc_o[d][3] *= scale1;
        }

        // ---- PV: O += Phi@Vhi + Plo@Vhi + Phi@Vlo ----
#pragma unroll
        for (int kk = 0; kk < 4; kk++) {
            float p00 = s[2*kk][0],   p01 = s[2*kk][1];
            float p02 = s[2*kk][2],   p03 = s[2*kk][3];
            float p10 = s[2*kk+1][0], p11 = s[2*kk+1][1];
            float p12 = s[2*kk+1][2], p13 = s[2*kk+1][3];
            uint32_t ah0 = pack_bf16x2(p00, p01);
            uint32_t ah1 = pack_bf16x2(p02, p03);
            uint32_t ah2 = pack_bf16x2(p10, p11);
            uint32_t ah3 = pack_bf16x2(p12, p13);
            __nv_bfloat162* hv;
            hv = (__nv_bfloat162*)&ah0;
            uint32_t al0 = pack_bf16x2(p00 - __bfloat162float(hv->x), p01 - __bfloat162float(hv->y));
            hv = (__nv_bfloat162*)&ah1;
            uint32_t al1 = pack_bf16x2(p02 - __bfloat162float(hv->x), p03 - __bfloat162float(hv->y));
            hv = (__nv_bfloat162*)&ah2;
            uint32_t al2 = pack_bf16x2(p10 - __bfloat162float(hv->x), p11 - __bfloat162float(hv->y));
            hv = (__nv_bfloat162*)&ah3;
            uint32_t al3 = pack_bf16x2(p12 - __bfloat162float(hv->x), p13 - __bfloat162float(hv->y));

            const int kko = kk * 16;
            uint32_t bh[4][4], bl[4][4];
#pragma unroll
            for (int dt2 = 0; dt2 < 4; dt2++) {
                ldsm_x4(bh[dt2][0], bh[dt2][1], bh[dt2][2], bh[dt2][3],
                        vhB + ((dt2 * 16 + b_row) * VS_STR + kko + b_koff) * 2);
                ldsm_x4(bl[dt2][0], bl[dt2][1], bl[dt2][2], bl[dt2][3],
                        vlB + ((dt2 * 16 + b_row) * VS_STR + kko + b_koff) * 2);
            }
#pragma unroll
            for (int dt = 0; dt < 8; dt++) {
                uint32_t b0h = bh[dt >> 1][(dt & 1) * 2], b1h = bh[dt >> 1][(dt & 1) * 2 + 1];
                uint32_t b0l = bl[dt >> 1][(dt & 1) * 2], b1l = bl[dt >> 1][(dt & 1) * 2 + 1];
                mma_bf16(acc_o[dt], ah0, ah1, ah2, ah3, b0h, b1h);
                mma_bf16(acc_o[dt], al0, al1, al2, al3, b0h, b1h);
                mma_bf16(acc_o[dt], ah0, ah1, ah2, ah3, b0l, b1l);
            }
        }
        CP_WAIT0();
        __syncthreads();
    }

    // ---- epilogue ----
    const float inv0 = 1.f / l_run0;
    const float inv1 = 1.f / l_run1;
    const int row0 = q0 + wm + er;
#pragma unroll
    for (int dt = 0; dt < 8; dt++) {
        const int col = h * HD + dt * 8 + ec;
        *(float2*)&Out[(size_t)row0 * Dm + col] =
            make_float2(acc_o[dt][0] * inv0, acc_o[dt][1] * inv0);
        *(float2*)&Out[(size_t)(row0 + 8) * Dm + col] =
            make_float2(acc_o[dt][2] * inv1, acc_o[dt][3] * inv1);
    }
}

// ---------------------------------------------------------------------------
__global__ __launch_bounds__(256)
void ln_kernel(const float* __restrict__ xr, const float* __restrict__ proj,
               const float* __restrict__ gamma, const float* __restrict__ beta,
               float* __restrict__ out) {
    const int row = blockIdx.x;
    const int tid = threadIdx.x;
    __shared__ float red[2][8];
    const float* a = xr + (long)row * Dm;
    const float* b = proj + (long)row * Dm;
    float s = 0.f, s2 = 0.f;
    for (int i = tid; i < Dm; i += 256) {
        float v = a[i] + b[i];
        s += v; s2 += v * v;
    }
#pragma unroll
    for (int o = 16; o; o >>= 1) {
        s  += __shfl_xor_sync(0xffffffffu, s,  o);
        s2 += __shfl_xor_sync(0xffffffffu, s2, o);
    }
    if ((tid & 31) == 0) { red[0][tid >> 5] = s; red[1][tid >> 5] = s2; }
    __syncthreads();
    if (tid < 32) {
        s  = (tid < 8) ? red[0][tid] : 0.f;
        s2 = (tid < 8) ? red[1][tid] : 0.f;
#pragma unroll
        for (int o = 4; o; o >>= 1) {
            s  += __shfl_xor_sync(0xffffffffu, s,  o);
            s2 += __shfl_xor_sync(0xffffffffu, s2, o);
        }
        if (tid == 0) { red[0][0] = s; red[1][0] = s2; }
    }
    __syncthreads();
    float mu = red[0][0] * (1.f / Dm);
    float var = red[1][0] * (1.f / Dm) - mu * mu;
    float rstd = rsqrtf(var + 1e-5f);
    for (int i = tid; i < Dm; i += 256) {
        float v = a[i] + b[i];
        out[(long)row * Dm + i] = (v - mu) * rstd * gamma[i] + beta[i];
    }
}

// ---------------------------------------------------------------------------
extern "C" void kernel_launch(void* const* d_in, const int* in_sizes, int n_in,
                              void* d_out, int out_size) {
    const float* x_real = (const float*)d_in[0];
    const float* x_imag = (const float*)d_in[1];
    const float* Wq     = (const float*)d_in[2];
    const float* Wk     = (const float*)d_in[3];
    const float* Wv     = (const float*)d_in[4];
    const float* Wqp    = (const float*)d_in[5];
    const float* bqp    = (const float*)d_in[6];
    const float* Wkp    = (const float*)d_in[7];
    const float* bkp    = (const float*)d_in[8];
    const float* Wo     = (const float*)d_in[9];
    const float* alogit = (const float*)d_in[10];
    const float* lng    = (const float*)d_in[11];
    const float* lnb    = (const float*)d_in[12];

    float *pQKV, *pQtKt, *pAO, *pP2;
    __nv_bfloat16 *pAb, *pAib, *pAOb, *pBqkv, *pBp2, *pBo;
    __nv_bfloat16 *pQb, *pKb, *pVth, *pVtl;
    cudaGetSymbolAddress((void**)&pQKV,  g_QKV);
    cudaGetSymbolAddress((void**)&pQtKt, g_QtKt);
    cudaGetSymbolAddress((void**)&pAO,   g_AO);
    cudaGetSymbolAddress((void**)&pP2,   g_P2);
    cudaGetSymbolAddress((void**)&pAb,   g_Ab);
    cudaGetSymbolAddress((void**)&pAib,  g_Aib);
    cudaGetSymbolAddress((void**)&pAOb,  g_AOb);
    cudaGetSymbolAddress((void**)&pBqkv, g_Bqkv);
    cudaGetSymbolAddress((void**)&pBp2,  g_Bp2);
    cudaGetSymbolAddress((void**)&pBo,   g_Bo);
    cudaGetSymbolAddress((void**)&pQb,   g_Qb);
    cudaGetSymbolAddress((void**)&pKb,   g_Kb);
    cudaGetSymbolAddress((void**)&pVth,  g_Vth);
    cudaGetSymbolAddress((void**)&pVtl,  g_Vtl);

    cudaFuncSetAttribute(tgemm3, cudaFuncAttributeMaxDynamicSharedMemorySize, TG3_SMEM);
    cudaFuncSetAttribute(attn4, cudaFuncAttributeMaxDynamicSharedMemorySize, A4_TOT);

    dim3 cbg(Dm / 32, Dm / 32);
    dim3 cbp(Pp / 32, Dm / 32);

    conv_a2<<<(Lseq * Dm) / 256, 256>>>(x_real, pAb);
    conv_b2<<<cbg, 256>>>(Wq, pBqkv,                      Dm);
    conv_b2<<<cbg, 256>>>(Wk, pBqkv + (size_t)Dm * K2,    Dm);
    conv_b2<<<cbg, 256>>>(Wv, pBqkv + (size_t)2 * Dm * K2, Dm);
    conv_a2<<<(Lseq * Dm) / 256, 256>>>(x_imag, pAib);
    tgemm3<<<dim3(3 * Dm / 128, Lseq / 128), 256, TG3_SMEM>>>(pAb, pBqkv, pQKV, 3 * Dm);
    conv_b2<<<cbp, 256>>>(Wqp, pBp2,                  Pp);
    conv_b2<<<cbp, 256>>>(Wkp, pBp2 + (size_t)Pp * K2, Pp);
    tgemm3<<<dim3(2 * Pp / 128, Lseq / 128), 256, TG3_SMEM>>>(pAib, pBp2, pQtKt, 2 * Pp);

    pack_content<<<(Lseq * Dm) / 256, 256>>>(pQKV, alogit, pQb, pKb);
    phase_pack<<<(Lseq * Pp) / 256, 256>>>(pQtKt, bqp, bkp, alogit, pQb, pKb);
    vt_pack<<<dim3(Dm / 32, Lseq / 32), 256>>>(pQKV, pVth, pVtl);

    attn4<<<dim3(Lseq / 128, Hh), 256, A4_TOT>>>(pQb, pKb, pVth, pVtl, pAO);

    conv_b2<<<cbg, 256>>>(Wo, pBo, Dm);
    conv_a2<<<(Lseq * Dm) / 256, 256>>>(pAO, pAOb);
    tgemm3<<<dim3(Dm / 128, Lseq / 128), 256, TG3_SMEM>>>(pAOb, pBo, pP2, Dm);
    ln_kernel<<<Lseq, 256>>>(x_real, pP2, lng, lnb, (float*)d_out);

    if (out_size >= 2 * Lseq * Dm) {
        cudaMemcpyAsync((float*)d_out + (long)Lseq * Dm, x_imag,
                        (size_t)Lseq * Dm * sizeof(float),
                        cudaMemcpyDeviceToDevice);
    }
}

// round 9
// speedup vs baseline: 2.5273x; 1.0164x over previous
#include <cuda_runtime.h>
#include <cuda_bf16.h>
#include <math.h>
#include <stdint.h>

#define Lseq 2048
#define Dm   1024
#define Hh   16
#define HD   64
#define Pp   128
#define PPH  8
#define DA   80
#define KQ3  240       // 3*80 packed augmented dim for attention S
#define K2   2048      // [hi|lo] packed K for projection GEMMs
#define CONTENT_SCALE 0.125f
#define PHASE_SCALE   0.35355339059327373f
#define NEG_BIG (-1e30f)

// ---------------- scratch (static device globals) ----------------
__device__ float g_QtKt[Lseq*2*Pp];
__device__ float g_P2[Lseq*Dm];
__device__ __nv_bfloat16 g_Ab  [Lseq*K2];
__device__ __nv_bfloat16 g_Aib [Lseq*K2];
__device__ __nv_bfloat16 g_AOb [Lseq*K2];
__device__ __nv_bfloat16 g_Bqkv[3*Dm*K2];
__device__ __nv_bfloat16 g_Bp2 [2*Pp*K2];
__device__ __nv_bfloat16 g_Bo  [Dm*K2];
__device__ __nv_bfloat16 g_Qb [Hh*Lseq*KQ3];
__device__ __nv_bfloat16 g_Kb [Hh*Lseq*KQ3];
__device__ __nv_bfloat16 g_Vth[Hh*HD*Lseq];
__device__ __nv_bfloat16 g_Vtl[Hh*HD*Lseq];

// ---------------- helpers ----------------
__device__ __forceinline__ uint32_t smem_u32(const void* p) {
    uint32_t a;
    asm("{ .reg .u64 t; cvta.to.shared.u64 t, %1; cvt.u32.u64 %0, t; }" : "=r"(a) : "l"(p));
    return a;
}
__device__ __forceinline__ void ldsm_x4(uint32_t& r0, uint32_t& r1, uint32_t& r2,
                                        uint32_t& r3, uint32_t addr) {
    asm volatile("ldmatrix.sync.aligned.m8n8.x4.shared.b16 {%0,%1,%2,%3}, [%4];"
                 : "=r"(r0), "=r"(r1), "=r"(r2), "=r"(r3) : "r"(addr));
}
__device__ __forceinline__ void mma_bf16(float* c, uint32_t a0, uint32_t a1,
                                         uint32_t a2, uint32_t a3,
                                         uint32_t b0, uint32_t b1) {
    asm volatile(
        "mma.sync.aligned.m16n8k16.row.col.f32.bf16.bf16.f32 "
        "{%0,%1,%2,%3}, {%4,%5,%6,%7}, {%8,%9}, {%0,%1,%2,%3};"
        : "+f"(c[0]), "+f"(c[1]), "+f"(c[2]), "+f"(c[3])
        : "r"(a0), "r"(a1), "r"(a2), "r"(a3), "r"(b0), "r"(b1));
}
__device__ __forceinline__ uint32_t pack_bf16x2(float a, float b) {
    __nv_bfloat162 h = __floats2bfloat162_rn(a, b);
    return *(uint32_t*)&h;
}
__device__ __forceinline__ void cp_async16(uint32_t dst, const void* src) {
    asm volatile("cp.async.cg.shared.global [%0], [%1], 16;" :: "r"(dst), "l"(src));
}
#define CP_COMMIT() asm volatile("cp.async.commit_group;" ::: "memory")
#define CP_WAIT0()  asm volatile("cp.async.wait_group 0;" ::: "memory")

// ---------------------------------------------------------------------------
// [hi|lo] pack of activation X[M][1024] -> out[M][2048]
// ---------------------------------------------------------------------------
__global__ __launch_bounds__(256)
void conv_a2(const float* __restrict__ X, __nv_bfloat16* __restrict__ out) {
    int idx = blockIdx.x * 256 + threadIdx.x;
    if (idx >= Lseq * Dm) return;
    int m = idx >> 10, k = idx & 1023;
    float v = X[idx];
    __nv_bfloat16 hi = __float2bfloat16(v);
    __nv_bfloat16 lo = __float2bfloat16(v - __bfloat162float(hi));
    size_t r = (size_t)m * K2;
    out[r + k] = hi;
    out[r + 1024 + k] = lo;
}
// ---------------------------------------------------------------------------
// [hi|lo] pack+transpose of weight W[1024][N] -> out[N][2048]
// ---------------------------------------------------------------------------
__global__ __launch_bounds__(256)
void conv_b2(const float* __restrict__ W, __nv_bfloat16* __restrict__ out, int N) {
    __shared__ float t[32][33];
    int k0 = blockIdx.y * 32, n0 = blockIdx.x * 32;
    int tx = threadIdx.x & 31, ty = threadIdx.x >> 5;
#pragma unroll
    for (int i = 0; i < 32; i += 8)
        t[ty + i][tx] = W[(size_t)(k0 + ty + i) * N + n0 + tx];
    __syncthreads();
#pragma unroll
    for (int i = 0; i < 32; i += 8) {
        float v = t[tx][ty + i];
        __nv_bfloat16 hi = __float2bfloat16(v);
        __nv_bfloat16 lo = __float2bfloat16(v - __bfloat162float(hi));
        size_t r = (size_t)(n0 + ty + i) * K2;
        out[r + k0 + tx] = hi;
        out[r + 1024 + k0 + tx] = lo;
    }
}

// ---------------------------------------------------------------------------
// Fused-epilogue store for the QKV GEMM: routes (row, col, v0, v1) into
// Qb ([hi|lo|hi] scaled), Kb ([hi|hi|lo]) or transposed Vth/Vtl.
// ---------------------------------------------------------------------------
__device__ __forceinline__ void qkv_store(int row, int col, float v0, float v1,
        const float* __restrict__ alogit,
        __nv_bfloat16* __restrict__ Qb, __nv_bfloat16* __restrict__ Kb,
        __nv_bfloat16* __restrict__ Vth, __nv_bfloat16* __restrict__ Vtl) {
    if (col < 2048) {
        const bool isQ = (col < 1024);
        int c = col & 1023;
        int hh = c >> 6, d = c & 63;
        if (isQ) {
            float a = 1.f / (1.f + __expf(-alogit[hh]));
            float s = (1.f - a) * CONTENT_SCALE;
            v0 *= s; v1 *= s;
        }
        size_t base = ((size_t)hh * Lseq + row) * KQ3;
        uint32_t hi = pack_bf16x2(v0, v1);
        __nv_bfloat162 h2 = *(__nv_bfloat162*)&hi;
        uint32_t lo = pack_bf16x2(v0 - __bfloat162float(h2.x),
                                  v1 - __bfloat162float(h2.y));
        __nv_bfloat16* dst = isQ ? Qb : Kb;
        *(uint32_t*)&dst[base + d]       = hi;
        *(uint32_t*)&dst[base + 80 + d]  = isQ ? lo : hi;
        *(uint32_t*)&dst[base + 160 + d] = isQ ? hi : lo;
    } else {
        int c2 = col - 2048;
        __nv_bfloat16 h0 = __float2bfloat16(v0);
        __nv_bfloat16 h1 = __float2bfloat16(v1);
        Vth[(size_t)c2 * Lseq + row]       = h0;
        Vth[(size_t)(c2 + 1) * Lseq + row] = h1;
        Vtl[(size_t)c2 * Lseq + row]       = __float2bfloat16(v0 - __bfloat162float(h0));
        Vtl[(size_t)(c2 + 1) * Lseq + row] = __float2bfloat16(v1 - __bfloat162float(h1));
    }
}

// ---------------------------------------------------------------------------
// 3-pass split GEMM with cp.async pipelining. EPI=0: fp32 C. EPI=1: fused
// QKV epilogue (writes Qb/Kb/Vth/Vtl directly; C unused).
// ---------------------------------------------------------------------------
#define LDA 40
#define TG3_TILE (128*LDA)
#define TG3_BUF  (4*TG3_TILE)
#define TG3_SMEM (2*TG3_BUF*2)   // 81920 bytes
template<int EPI>
__global__ __launch_bounds__(256)
void tgemm3(const __nv_bfloat16* __restrict__ A, const __nv_bfloat16* __restrict__ B,
            float* __restrict__ C, int N,
            const float* __restrict__ alogit,
            __nv_bfloat16* __restrict__ Qb, __nv_bfloat16* __restrict__ Kb,
            __nv_bfloat16* __restrict__ Vth, __nv_bfloat16* __restrict__ Vtl) {
    extern __shared__ __nv_bfloat16 sm3[];

    const int tid = threadIdx.x;
    const int wid = tid >> 5, lane = tid & 31;
    const int m0 = blockIdx.y * 128, n0 = blockIdx.x * 128;
    const int wm = (wid >> 2) * 64, wn = (wid & 3) * 32;

    const int lr = tid >> 1, lc = (tid & 1) * 16;
    const __nv_bfloat16* Agh = A + (size_t)(m0 + lr) * K2 + lc;
    const __nv_bfloat16* Agl = Agh + 1024;
    const __nv_bfloat16* Bgh = B + (size_t)(n0 + lr) * K2 + lc;
    const __nv_bfloat16* Bgl = Bgh + 1024;
    const uint32_t smB = smem_u32(sm3);
    const uint32_t so = (uint32_t)(lr * LDA + lc) * 2;

    float acc[4][4][4];
#pragma unroll
    for (int i = 0; i < 4; i++)
#pragma unroll
        for (int j = 0; j < 4; j++)
#pragma unroll
            for (int k = 0; k < 4; k++) acc[i][j][k] = 0.f;

    auto ld_chunk = [&](int kt, int buf) {
        const uint32_t d = smB + (uint32_t)buf * TG3_BUF * 2;
        const int off = kt * 32;
        cp_async16(d + so,                      Agh + off);
        cp_async16(d + so + 16,                 Agh + off + 8);
        cp_async16(d + TG3_TILE*2 + so,         Agl + off);
        cp_async16(d + TG3_TILE*2 + so + 16,    Agl + off + 8);
        cp_async16(d + 2*TG3_TILE*2 + so,       Bgh + off);
        cp_async16(d + 2*TG3_TILE*2 + so + 16,  Bgh + off + 8);
        cp_async16(d + 3*TG3_TILE*2 + so,       Bgl + off);
        cp_async16(d + 3*TG3_TILE*2 + so + 16,  Bgl + off + 8);
    };

    ld_chunk(0, 0);
    CP_COMMIT();
    CP_WAIT0();
    __syncthreads();

    const int a_row = (lane & 15);
    const int a_koff = (lane >> 4) * 8;
    const int b_row = (lane & 7) + ((lane & 16) >> 1);
    const int b_koff = ((lane >> 3) & 1) * 8;

    for (int kt = 0; kt < 32; kt++) {
        const int cur = kt & 1;
        if (kt < 31) {
            ld_chunk(kt + 1, cur ^ 1);
            CP_COMMIT();
        }
        const uint32_t base = smB + (uint32_t)cur * TG3_BUF * 2;
        const uint32_t ahB = base;
        const uint32_t alB = base + TG3_TILE * 2;
        const uint32_t bhB = base + 2 * TG3_TILE * 2;
        const uint32_t blB = base + 3 * TG3_TILE * 2;
#pragma unroll
        for (int ks = 0; ks < 2; ks++) {
            const int k0 = ks * 16;
            uint32_t ah[4][4];
#pragma unroll
            for (int mt = 0; mt < 4; mt++)
                ldsm_x4(ah[mt][0], ah[mt][1], ah[mt][2], ah[mt][3],
                        ahB + ((wm + mt * 16 + a_row) * LDA + k0 + a_koff) * 2);
            uint32_t bh[2][4], bl[2][4];
#pragma unroll
            for (int nt2 = 0; nt2 < 2; nt2++) {
                ldsm_x4(bh[nt2][0], bh[nt2][1], bh[nt2][2], bh[nt2][3],
                        bhB + ((wn + nt2 * 16 + b_row) * LDA + k0 + b_koff) * 2);
                ldsm_x4(bl[nt2][0], bl[nt2][1], bl[nt2][2], bl[nt2][3],
                        blB + ((wn + nt2 * 16 + b_row) * LDA + k0 + b_koff) * 2);
            }
#pragma unroll
            for (int mt = 0; mt < 4; mt++)
#pragma unroll
                for (int nt = 0; nt < 4; nt++) {
                    mma_bf16(acc[mt][nt], ah[mt][0], ah[mt][1], ah[mt][2], ah[mt][3],
                             bh[nt >> 1][(nt & 1) * 2], bh[nt >> 1][(nt & 1) * 2 + 1]);
                    mma_bf16(acc[mt][nt], ah[mt][0], ah[mt][1], ah[mt][2], ah[mt][3],
                             bl[nt >> 1][(nt & 1) * 2], bl[nt >> 1][(nt & 1) * 2 + 1]);
                }
            uint32_t al[4][4];
#pragma unroll
            for (int mt = 0; mt < 4; mt++)
                ldsm_x4(al[mt][0], al[mt][1], al[mt][2], al[mt][3],
                        alB + ((wm + mt * 16 + a_row) * LDA + k0 + a_koff) * 2);
#pragma unroll
            for (int mt = 0; mt < 4; mt++)
#pragma unroll
                for (int nt = 0; nt < 4; nt++)
                    mma_bf16(acc[mt][nt], al[mt][0], al[mt][1], al[mt][2], al[mt][3],
                             bh[nt >> 1][(nt & 1) * 2], bh[nt >> 1][(nt & 1) * 2 + 1]);
        }
        if (kt < 31) {
            CP_WAIT0();
            __syncthreads();
        }
    }

    const int er = lane >> 2, ec = (lane & 3) * 2;
#pragma unroll
    for (int mt = 0; mt < 4; mt++) {
        const int row = m0 + wm + mt * 16 + er;
#pragma unroll
        for (int nt = 0; nt < 4; nt++) {
            const int col = n0 + wn + nt * 8 + ec;
            if (EPI == 0) {
                *(float2*)&C[(size_t)row * N + col] =
                    make_float2(acc[mt][nt][0], acc[mt][nt][1]);
                *(float2*)&C[(size_t)(row + 8) * N + col] =
                    make_float2(acc[mt][nt][2], acc[mt][nt][3]);
            } else {
                qkv_store(row,     col, acc[mt][nt][0], acc[mt][nt][1],
                          alogit, Qb, Kb, Vth, Vtl);
                qkv_store(row + 8, col, acc[mt][nt][2], acc[mt][nt][3],
                          alogit, Qb, Kb, Vth, Vtl);
            }
        }
    }
}

// ---------------------------------------------------------------------------
// Phase dims (64..79) packed bf16x3
// ---------------------------------------------------------------------------
__global__ __launch_bounds__(256)
void phase_pack(const float* __restrict__ QtKt,
                const float* __restrict__ bqp, const float* __restrict__ bkp,
                const float* __restrict__ alogit,
                __nv_bfloat16* __restrict__ Qb, __nv_bfloat16* __restrict__ Kb) {
    int idx = blockIdx.x * blockDim.x + threadIdx.x;
    if (idx >= Lseq * Pp) return;
    int q = idx >> 7, j = idx & 127;
    int h = j / PPH, i = j % PPH;
    int f = j >> 1;
    double invf = exp(-(double)f / 64.0 * log(10000.0));
    float pos = (float)((double)q * invf);
    float tq = QtKt[(size_t)q * 256 + j] + bqp[j] + pos;
    float tk = QtKt[(size_t)q * 256 + 128 + j] + bkp[j] + pos;
    float alpha = 1.f / (1.f + expf(-alogit[h]));
    float aps = alpha * PHASE_SCALE;
    size_t base = ((size_t)h * Lseq + q) * KQ3;
    float qv[2] = {aps * cosf(tq), aps * sinf(tq)};
    float kv[2] = {cosf(tk), sinf(tk)};
#pragma unroll
    for (int s = 0; s < 2; s++) {
        int d = 64 + s * 8 + i;
        __nv_bfloat16 qh = __float2bfloat16(qv[s]);
        __nv_bfloat16 ql = __float2bfloat16(qv[s] - __bfloat162float(qh));
        Qb[base + d] = qh; Qb[base + 80 + d] = ql; Qb[base + 160 + d] = qh;
        __nv_bfloat16 kh = __float2bfloat16(kv[s]);
        __nv_bfloat16 kl = __float2bfloat16(kv[s] - __bfloat162float(kh));
        Kb[base + d] = kh; Kb[base + 80 + d] = kh; Kb[base + 160 + d] = kl;
    }
}

// ---------------------------------------------------------------------------
// Tensor-core flash attention v4 + fused [hi|lo] output pack (AOb direct).
// ---------------------------------------------------------------------------
#define QS_STR 248
#define KS_STR 248
#define VS_STR 72
#define A4B_VH (64*KS_STR*2)
#define A4B_VL (A4B_VH + 64*VS_STR*2)
#define A4B_SZ (A4B_VL + 64*VS_STR*2)
#define A4_QS  (2*A4B_SZ)
#define A4_TOT (A4_QS + 128*QS_STR*2)

__global__ __launch_bounds__(256)
void attn4(const __nv_bfloat16* __restrict__ Qb, const __nv_bfloat16* __restrict__ Kb,
           const __nv_bfloat16* __restrict__ Vth, const __nv_bfloat16* __restrict__ Vtl,
           __nv_bfloat16* __restrict__ AOb) {
    extern __shared__ char smraw[];
    const uint32_t smB = smem_u32(smraw);
    __nv_bfloat16* Qs = (__nv_bfloat16*)(smraw + A4_QS);

    const int tid = threadIdx.x;
    const int wid = tid >> 5, lane = tid & 31;
    const int h = blockIdx.y;
    const int qt = (int)gridDim.x - 1 - (int)blockIdx.x;
    const int q0 = qt * 128;
    const int wm = wid * 16;

    const int a_row = (lane & 15);
    const int a_koff = (lane >> 4) * 8;
    const int b_row = (lane & 7) + ((lane & 16) >> 1);
    const int b_koff = ((lane >> 3) & 1) * 8;
    const int er = lane >> 2, ec = (lane & 3) * 2;

    const __nv_bfloat16* KbH = Kb + ((size_t)h * Lseq) * KQ3;
    const __nv_bfloat16* VhH = Vth + ((size_t)h * HD) * Lseq;
    const __nv_bfloat16* VlH = Vtl + ((size_t)h * HD) * Lseq;

    auto ld_tile = [&](int kt, int s) {
        const int k0 = kt * 64;
        const uint32_t stB = smB + (uint32_t)s * A4B_SZ;
        const __nv_bfloat16* ks = KbH + (size_t)k0 * KQ3;
        for (int i = tid; i < 64 * 30; i += 256) {
            int r = i / 30, c = i % 30;
            cp_async16(stB + ((uint32_t)(r * KS_STR + c * 8) << 1), ks + r * KQ3 + c * 8);
        }
        for (int i = tid; i < 64 * 8; i += 256) {
            int d = i >> 3, c = i & 7;
            uint32_t off = (uint32_t)(d * VS_STR + c * 8) << 1;
            const size_t go = (size_t)d * Lseq + k0 + c * 8;
            cp_async16(stB + A4B_VH + off, VhH + go);
            cp_async16(stB + A4B_VL + off, VlH + go);
        }
    };

    ld_tile(0, 0);
    CP_COMMIT();
    {
        const uint4* src = (const uint4*)(Qb + ((size_t)h * Lseq + q0) * KQ3);
        for (int i = tid; i < 128 * 30; i += 256) {
            int r = i / 30, c = i % 30;
            *(uint4*)&Qs[r * QS_STR + c * 8] = src[r * 30 + c];
        }
    }
    CP_WAIT0();
    __syncthreads();

    uint32_t qf[15][4];
    {
        const uint32_t qsB = smem_u32(Qs);
#pragma unroll
        for (int ks = 0; ks < 15; ks++)
            ldsm_x4(qf[ks][0], qf[ks][1], qf[ks][2], qf[ks][3],
                    qsB + ((wm + a_row) * QS_STR + ks * 16 + a_koff) * 2);
    }

    float m_run0 = NEG_BIG, m_run1 = NEG_BIG;
    float l_run0 = 0.f, l_run1 = 0.f;
    float acc_o[8][4];
#pragma unroll
    for (int d = 0; d < 8; d++)
#pragma unroll
        for (int c = 0; c < 4; c++) acc_o[d][c] = 0.f;

    const int nkt = 2 * qt + 2;
    for (int kt = 0; kt < nkt; kt++) {
        const int k0 = kt * 64;
        const int cur = kt & 1;
        if (kt + 1 < nkt) {
            ld_tile(kt + 1, cur ^ 1);
            CP_COMMIT();
        }
        const uint32_t stB = smB + (uint32_t)cur * A4B_SZ;
        const uint32_t ksB = stB;
        const uint32_t vhB = stB + A4B_VH;
        const uint32_t vlB = stB + A4B_VL;

        float s[8][4];
#pragma unroll
        for (int nt = 0; nt < 8; nt++)
#pragma unroll
            for (int c = 0; c < 4; c++) s[nt][c] = 0.f;
#pragma unroll
        for (int ks = 0; ks < 15; ks++) {
            const int kk = ks * 16;
            uint32_t bf[4][4];
#pragma unroll
            for (int nt2 = 0; nt2 < 4; nt2++)
                ldsm_x4(bf[nt2][0], bf[nt2][1], bf[nt2][2], bf[nt2][3],
                        ksB + ((nt2 * 16 + b_row) * KS_STR + kk + b_koff) * 2);
#pragma unroll
            for (int nt = 0; nt < 8; nt++)
                mma_bf16(s[nt], qf[ks][0], qf[ks][1], qf[ks][2], qf[ks][3],
                         bf[nt >> 1][(nt & 1) * 2], bf[nt >> 1][(nt & 1) * 2 + 1]);
        }

        if (kt >= 2 * qt) {
            const int r0 = q0 + wm + er, r1 = r0 + 8;
#pragma unroll
            for (int nt = 0; nt < 8; nt++) {
                const int c0 = k0 + nt * 8 + ec;
                if (c0     > r0) s[nt][0] = NEG_BIG;
                if (c0 + 1 > r0) s[nt][1] = NEG_BIG;
                if (c0     > r1) s[nt][2] = NEG_BIG;
                if (c0 + 1 > r1) s[nt][3] = NEG_BIG;
            }
        }

        float mx0 = s[0][0], mx1 = s[0][2];
#pragma unroll
        for (int nt = 0; nt < 8; nt++) {
            mx0 = fmaxf(mx0, fmaxf(s[nt][0], s[nt][1]));
            mx1 = fmaxf(mx1, fmaxf(s[nt][2], s[nt][3]));
        }
        mx0 = fmaxf(mx0, __shfl_xor_sync(0xffffffffu, mx0, 1));
        mx0 = fmaxf(mx0, __shfl_xor_sync(0xffffffffu, mx0, 2));
        mx1 = fmaxf(mx1, __shfl_xor_sync(0xffffffffu, mx1, 1));
        mx1 = fmaxf(mx1, __shfl_xor_sync(0xffffffffu, mx1, 2));
        float mnew0 = fmaxf(m_run0, mx0);
        float mnew1 = fmaxf(m_run1, mx1);
        float scale0 = __expf(m_run0 - mnew0);
        float scale1 = __expf(m_run1 - mnew1);

        float sum0 = 0.f, sum1 = 0.f;
#pragma unroll
        for (int nt = 0; nt < 8; nt++) {
            s[nt][0] = __expf(s[nt][0] - mnew0); sum0 += s[nt][0];
            s[nt][1] = __expf(s[nt][1] - mnew0); sum0 += s[nt][1];
            s[nt][2] = __expf(s[nt][2] - mnew1); sum1 += s[nt][2];
            s[nt][3] = __expf(s[nt][3] - mnew1); sum1 += s[nt][3];
        }
        sum0 += __shfl_xor_sync(0xffffffffu, sum0, 1);
        sum0 += __shfl_xor_sync(0xffffffffu, sum0, 2);
        sum1 += __shfl_xor_sync(0xffffffffu, sum1, 1);
        sum1 += __shfl_xor_sync(0xffffffffu, sum1, 2);
        m_run0 = mnew0; m_run1 = mnew1;
        l_run0 = l_run0 * scale0 + sum0;
        l_run1 = l_run1 * scale1 + sum1;

#pragma unroll
        for (int d = 0; d < 8; d++) {
            acc_o[d][0] *= scale0; acc_o[d][1] *= scale0;
            acc_o[d][2] *= scale1; acc_o[d][3] *= scale1;
        }

#pragma unroll
        for (int kk = 0; kk < 4; kk++) {
            float p00 = s[2*kk][0],   p01 = s[2*kk][1];
            float p02 = s[2*kk][2],   p03 = s[2*kk][3];
            float p10 = s[2*kk+1][0], p11 = s[2*kk+1][1];
            float p12 = s[2*kk+1][2], p13 = s[2*kk+1][3];
            uint32_t ah0 = pack_bf16x2(p00, p01);
            uint32_t ah1 = pack_bf16x2(p02, p03);
            uint32_t ah2 = pack_bf16x2(p10, p11);
            uint32_t ah3 = pack_bf16x2(p12, p13);
            __nv_bfloat162* hv;
            hv = (__nv_bfloat162*)&ah0;
            uint32_t al0 = pack_bf16x2(p00 - __bfloat162float(hv->x), p01 - __bfloat162float(hv->y));
            hv = (__nv_bfloat162*)&ah1;
            uint32_t al1 = pack_bf16x2(p02 - __bfloat162float(hv->x), p03 - __bfloat162float(hv->y));
            hv = (__nv_bfloat162*)&ah2;
            uint32_t al2 = pack_bf16x2(p10 - __bfloat162float(hv->x), p11 - __bfloat162float(hv->y));
            hv = (__nv_bfloat162*)&ah3;
            uint32_t al3 = pack_bf16x2(p12 - __bfloat162float(hv->x), p13 - __bfloat162float(hv->y));

            const int kko = kk * 16;
            uint32_t bh[4][4], bl[4][4];
#pragma unroll
            for (int dt2 = 0; dt2 < 4; dt2++) {
                ldsm_x4(bh[dt2][0], bh[dt2][1], bh[dt2][2], bh[dt2][3],
                        vhB + ((dt2 * 16 + b_row) * VS_STR + kko + b_koff) * 2);
                ldsm_x4(bl[dt2][0], bl[dt2][1], bl[dt2][2], bl[dt2][3],
                        vlB + ((dt2 * 16 + b_row) * VS_STR + kko + b_koff) * 2);
            }
#pragma unroll
            for (int dt = 0; dt < 8; dt++) {
                uint32_t b0h = bh[dt >> 1][(dt & 1) * 2], b1h = bh[dt >> 1][(dt & 1) * 2 + 1];
                uint32_t b0l = bl[dt >> 1][(dt & 1) * 2], b1l = bl[dt >> 1][(dt & 1) * 2 + 1];
                mma_bf16(acc_o[dt], ah0, ah1, ah2, ah3, b0h, b1h);
                mma_bf16(acc_o[dt], al0, al1, al2, al3, b0h, b1h);
                mma_bf16(acc_o[dt], ah0, ah1, ah2, ah3, b0l, b1l);
            }
        }
        CP_WAIT0();
        __syncthreads();
    }

    // ---- epilogue: divide by l, emit AOb [hi|lo] directly ----
    const float inv0 = 1.f / l_run0;
    const float inv1 = 1.f / l_run1;
    const int row0 = q0 + wm + er;
#pragma unroll
    for (int dt = 0; dt < 8; dt++) {
        const int col = h * HD + dt * 8 + ec;
        {
            float o0 = acc_o[dt][0] * inv0, o1 = acc_o[dt][1] * inv0;
            uint32_t hi = pack_bf16x2(o0, o1);
            __nv_bfloat162 h2 = *(__nv_bfloat162*)&hi;
            uint32_t lo = pack_bf16x2(o0 - __bfloat162float(h2.x),
                                      o1 - __bfloat162float(h2.y));
            *(uint32_t*)&AOb[(size_t)row0 * K2 + col] = hi;
            *(uint32_t*)&AOb[(size_t)row0 * K2 + 1024 + col] = lo;
        }
        {
            float o0 = acc_o[dt][2] * inv1, o1 = acc_o[dt][3] * inv1;
            uint32_t hi = pack_bf16x2(o0, o1);
            __nv_bfloat162 h2 = *(__nv_bfloat162*)&hi;
            uint32_t lo = pack_bf16x2(o0 - __bfloat162float(h2.x),
                                      o1 - __bfloat162float(h2.y));
            *(uint32_t*)&AOb[(size_t)(row0 + 8) * K2 + col] = hi;
            *(uint32_t*)&AOb[(size_t)(row0 + 8) * K2 + 1024 + col] = lo;
        }
    }
}

// ---------------------------------------------------------------------------
__global__ __launch_bounds__(256)
void ln_kernel(const float* __restrict__ xr, const float* __restrict__ proj,
               const float* __restrict__ gamma, const float* __restrict__ beta,
               float* __restrict__ out) {
    const int row = blockIdx.x;
    const int tid = threadIdx.x;
    __shared__ float red[2][8];
    const float* a = xr + (long)row * Dm;
    const float* b = proj + (long)row * Dm;
    float s = 0.f, s2 = 0.f;
    for (int i = tid; i < Dm; i += 256) {
        float v = a[i] + b[i];
        s += v; s2 += v * v;
    }
#pragma unroll
    for (int o = 16; o; o >>= 1) {
        s  += __shfl_xor_sync(0xffffffffu, s,  o);
        s2 += __shfl_xor_sync(0xffffffffu, s2, o);
    }
    if ((tid & 31) == 0) { red[0][tid >> 5] = s; red[1][tid >> 5] = s2; }
    __syncthreads();
    if (tid < 32) {
        s  = (tid < 8) ? red[0][tid] : 0.f;
        s2 = (tid < 8) ? red[1][tid] : 0.f;
#pragma unroll
        for (int o = 4; o; o >>= 1) {
            s  += __shfl_xor_sync(0xffffffffu, s,  o);
            s2 += __shfl_xor_sync(0xffffffffu, s2, o);
        }
        if (tid == 0) { red[0][0] = s; red[1][0] = s2; }
    }
    __syncthreads();
    float mu = red[0][0] * (1.f / Dm);
    float var = red[1][0] * (1.f / Dm) - mu * mu;
    float rstd = rsqrtf(var + 1e-5f);
    for (int i = tid; i < Dm; i += 256) {
        float v = a[i] + b[i];
        out[(long)row * Dm + i] = (v - mu) * rstd * gamma[i] + beta[i];
    }
}

// ---------------------------------------------------------------------------
extern "C" void kernel_launch(void* const* d_in, const int* in_sizes, int n_in,
                              void* d_out, int out_size) {
    const float* x_real = (const float*)d_in[0];
    const float* x_imag = (const float*)d_in[1];
    const float* Wq     = (const float*)d_in[2];
    const float* Wk     = (const float*)d_in[3];
    const float* Wv     = (const float*)d_in[4];
    const float* Wqp    = (const float*)d_in[5];
    const float* bqp    = (const float*)d_in[6];
    const float* Wkp    = (const float*)d_in[7];
    const float* bkp    = (const float*)d_in[8];
    const float* Wo     = (const float*)d_in[9];
    const float* alogit = (const float*)d_in[10];
    const float* lng    = (const float*)d_in[11];
    const float* lnb    = (const float*)d_in[12];

    float *pQtKt, *pP2;
    __nv_bfloat16 *pAb, *pAib, *pAOb, *pBqkv, *pBp2, *pBo;
    __nv_bfloat16 *pQb, *pKb, *pVth, *pVtl;
    cudaGetSymbolAddress((void**)&pQtKt, g_QtKt);
    cudaGetSymbolAddress((void**)&pP2,   g_P2);
    cudaGetSymbolAddress((void**)&pAb,   g_Ab);
    cudaGetSymbolAddress((void**)&pAib,  g_Aib);
    cudaGetSymbolAddress((void**)&pAOb,  g_AOb);
    cudaGetSymbolAddress((void**)&pBqkv, g_Bqkv);
    cudaGetSymbolAddress((void**)&pBp2,  g_Bp2);
    cudaGetSymbolAddress((void**)&pBo,   g_Bo);
    cudaGetSymbolAddress((void**)&pQb,   g_Qb);
    cudaGetSymbolAddress((void**)&pKb,   g_Kb);
    cudaGetSymbolAddress((void**)&pVth,  g_Vth);
    cudaGetSymbolAddress((void**)&pVtl,  g_Vtl);

    cudaFuncSetAttribute(tgemm3<0>, cudaFuncAttributeMaxDynamicSharedMemorySize, TG3_SMEM);
    cudaFuncSetAttribute(tgemm3<1>, cudaFuncAttributeMaxDynamicSharedMemorySize, TG3_SMEM);
    cudaFuncSetAttribute(attn4, cudaFuncAttributeMaxDynamicSharedMemorySize, A4_TOT);

    dim3 cbg(Dm / 32, Dm / 32);
    dim3 cbp(Pp / 32, Dm / 32);

    conv_a2<<<(Lseq * Dm) / 256, 256>>>(x_real, pAb);
    conv_b2<<<cbg, 256>>>(Wq, pBqkv,                      Dm);
    conv_b2<<<cbg, 256>>>(Wk, pBqkv + (size_t)Dm * K2,    Dm);
    conv_b2<<<cbg, 256>>>(Wv, pBqkv + (size_t)2 * Dm * K2, Dm);
    conv_a2<<<(Lseq * Dm) / 256, 256>>>(x_imag, pAib);
    conv_b2<<<cbp, 256>>>(Wqp, pBp2,                  Pp);
    conv_b2<<<cbp, 256>>>(Wkp, pBp2 + (size_t)Pp * K2, Pp);
    conv_b2<<<cbg, 256>>>(Wo, pBo, Dm);

    // QKV GEMM with fused pack epilogue -> Qb/Kb (content dims) + Vth/Vtl
    tgemm3<1><<<dim3(3 * Dm / 128, Lseq / 128), 256, TG3_SMEM>>>(
        pAb, pBqkv, nullptr, 3 * Dm, alogit, pQb, pKb, pVth, pVtl);
    // phase GEMM (fp32 out) then phase dims of Qb/Kb
    tgemm3<0><<<dim3(2 * Pp / 128, Lseq / 128), 256, TG3_SMEM>>>(
        pAib, pBp2, pQtKt, 2 * Pp, nullptr, nullptr, nullptr, nullptr, nullptr);
    phase_pack<<<(Lseq * Pp) / 256, 256>>>(pQtKt, bqp, bkp, alogit, pQb, pKb);

    // attention with fused [hi|lo] output pack
    attn4<<<dim3(Lseq / 128, Hh), 256, A4_TOT>>>(pQb, pKb, pVth, pVtl, pAOb);

    tgemm3<0><<<dim3(Dm / 128, Lseq / 128), 256, TG3_SMEM>>>(
        pAOb, pBo, pP2, Dm, nullptr, nullptr, nullptr, nullptr, nullptr);
    ln_kernel<<<Lseq, 256>>>(x_real, pP2, lng, lnb, (float*)d_out);

    if (out_size >= 2 * Lseq * Dm) {
        cudaMemcpyAsync((float*)d_out + (long)Lseq * Dm, x_imag,
                        (size_t)Lseq * Dm * sizeof(float),
                        cudaMemcpyDeviceToDevice);
    }
}

// round 10
// speedup vs baseline: 2.6008x; 1.0291x over previous
#include <cuda_runtime.h>
#include <cuda_bf16.h>
#include <math.h>
#include <stdint.h>

#define Lseq 2048
#define Dm   1024
#define Hh   16
#define HD   64
#define Pp   128
#define PPH  8
#define DA   80
#define KQ3  240       // 3*80 packed augmented dim for attention S
#define K2   2048      // [hi|lo] packed K for projection GEMMs
#define CONTENT_SCALE 0.125f
#define PHASE_SCALE   0.35355339059327373f
#define NEG_BIG (-1e30f)

// ---------------- scratch (static device globals) ----------------
__device__ float g_QtKt[Lseq*2*Pp];
__device__ float g_P2[Lseq*Dm];
__device__ __nv_bfloat16 g_Ab  [Lseq*K2];
__device__ __nv_bfloat16 g_Aib [Lseq*K2];
__device__ __nv_bfloat16 g_AOb [Lseq*K2];
__device__ __nv_bfloat16 g_Bqkv[3*Dm*K2];
__device__ __nv_bfloat16 g_Bp2 [2*Pp*K2];
__device__ __nv_bfloat16 g_Bo  [Dm*K2];
__device__ __nv_bfloat16 g_Qb [Hh*Lseq*KQ3];
__device__ __nv_bfloat16 g_Kb [Hh*Lseq*KQ3];
__device__ __nv_bfloat16 g_Vth[Hh*HD*Lseq];
__device__ __nv_bfloat16 g_Vtl[Hh*HD*Lseq];

// ---------------- helpers ----------------
__device__ __forceinline__ uint32_t smem_u32(const void* p) {
    uint32_t a;
    asm("{ .reg .u64 t; cvta.to.shared.u64 t, %1; cvt.u32.u64 %0, t; }" : "=r"(a) : "l"(p));
    return a;
}
__device__ __forceinline__ void ldsm_x4(uint32_t& r0, uint32_t& r1, uint32_t& r2,
                                        uint32_t& r3, uint32_t addr) {
    asm volatile("ldmatrix.sync.aligned.m8n8.x4.shared.b16 {%0,%1,%2,%3}, [%4];"
                 : "=r"(r0), "=r"(r1), "=r"(r2), "=r"(r3) : "r"(addr));
}
__device__ __forceinline__ void mma_bf16(float* c, uint32_t a0, uint32_t a1,
                                         uint32_t a2, uint32_t a3,
                                         uint32_t b0, uint32_t b1) {
    asm volatile(
        "mma.sync.aligned.m16n8k16.row.col.f32.bf16.bf16.f32 "
        "{%0,%1,%2,%3}, {%4,%5,%6,%7}, {%8,%9}, {%0,%1,%2,%3};"
        : "+f"(c[0]), "+f"(c[1]), "+f"(c[2]), "+f"(c[3])
        : "r"(a0), "r"(a1), "r"(a2), "r"(a3), "r"(b0), "r"(b1));
}
__device__ __forceinline__ uint32_t pack_bf16x2(float a, float b) {
    __nv_bfloat162 h = __floats2bfloat162_rn(a, b);
    return *(uint32_t*)&h;
}
__device__ __forceinline__ void cp_async16(uint32_t dst, const void* src) {
    asm volatile("cp.async.cg.shared.global [%0], [%1], 16;" :: "r"(dst), "l"(src));
}
#define CP_COMMIT() asm volatile("cp.async.commit_group;" ::: "memory")
#define CP_WAIT0()  asm volatile("cp.async.wait_group 0;" ::: "memory")

// ---------------------------------------------------------------------------
// [hi|lo] pack of activation X[M][1024] -> out[M][2048], 4 elems/thread
// ---------------------------------------------------------------------------
__global__ __launch_bounds__(256)
void conv_a2(const float* __restrict__ X, __nv_bfloat16* __restrict__ out) {
    int idx = blockIdx.x * 256 + threadIdx.x;     // group of 4 elements
    if (idx >= (Lseq * Dm) / 4) return;
    int m = idx >> 8, k4 = (idx & 255) * 4;
    float4 v = *(const float4*)(X + (size_t)m * 1024 + k4);
    uint32_t h0 = pack_bf16x2(v.x, v.y);
    uint32_t h1 = pack_bf16x2(v.z, v.w);
    __nv_bfloat162 a = *(__nv_bfloat162*)&h0;
    __nv_bfloat162 b = *(__nv_bfloat162*)&h1;
    uint32_t l0 = pack_bf16x2(v.x - __bfloat162float(a.x), v.y - __bfloat162float(a.y));
    uint32_t l1 = pack_bf16x2(v.z - __bfloat162float(b.x), v.w - __bfloat162float(b.y));
    size_t r = (size_t)m * K2;
    *(uint2*)&out[r + k4]        = make_uint2(h0, h1);
    *(uint2*)&out[r + 1024 + k4] = make_uint2(l0, l1);
}
// ---------------------------------------------------------------------------
// [hi|lo] pack+transpose of weight W[1024][N] -> out[N][2048]
// ---------------------------------------------------------------------------
__global__ __launch_bounds__(256)
void conv_b2(const float* __restrict__ W, __nv_bfloat16* __restrict__ out, int N) {
    __shared__ float t[32][33];
    int k0 = blockIdx.y * 32, n0 = blockIdx.x * 32;
    int tx = threadIdx.x & 31, ty = threadIdx.x >> 5;
#pragma unroll
    for (int i = 0; i < 32; i += 8)
        t[ty + i][tx] = W[(size_t)(k0 + ty + i) * N + n0 + tx];
    __syncthreads();
#pragma unroll
    for (int i = 0; i < 32; i += 8) {
        float v = t[tx][ty + i];
        __nv_bfloat16 hi = __float2bfloat16(v);
        __nv_bfloat16 lo = __float2bfloat16(v - __bfloat162float(hi));
        size_t r = (size_t)(n0 + ty + i) * K2;
        out[r + k0 + tx] = hi;
        out[r + 1024 + k0 + tx] = lo;
    }
}

// ---------------------------------------------------------------------------
// Fused-epilogue store for the QKV GEMM
// ---------------------------------------------------------------------------
__device__ __forceinline__ void qkv_store(int row, int col, float v0, float v1,
        const float* __restrict__ alogit,
        __nv_bfloat16* __restrict__ Qb, __nv_bfloat16* __restrict__ Kb,
        __nv_bfloat16* __restrict__ Vth, __nv_bfloat16* __restrict__ Vtl) {
    if (col < 2048) {
        const bool isQ = (col < 1024);
        int c = col & 1023;
        int hh = c >> 6, d = c & 63;
        if (isQ) {
            float a = 1.f / (1.f + __expf(-alogit[hh]));
            float s = (1.f - a) * CONTENT_SCALE;
            v0 *= s; v1 *= s;
        }
        size_t base = ((size_t)hh * Lseq + row) * KQ3;
        uint32_t hi = pack_bf16x2(v0, v1);
        __nv_bfloat162 h2 = *(__nv_bfloat162*)&hi;
        uint32_t lo = pack_bf16x2(v0 - __bfloat162float(h2.x),
                                  v1 - __bfloat162float(h2.y));
        __nv_bfloat16* dst = isQ ? Qb : Kb;
        *(uint32_t*)&dst[base + d]       = hi;
        *(uint32_t*)&dst[base + 80 + d]  = isQ ? lo : hi;
        *(uint32_t*)&dst[base + 160 + d] = isQ ? hi : lo;
    } else {
        int c2 = col - 2048;
        __nv_bfloat16 h0 = __float2bfloat16(v0);
        __nv_bfloat16 h1 = __float2bfloat16(v1);
        Vth[(size_t)c2 * Lseq + row]       = h0;
        Vth[(size_t)(c2 + 1) * Lseq + row] = h1;
        Vtl[(size_t)c2 * Lseq + row]       = __float2bfloat16(v0 - __bfloat162float(h0));
        Vtl[(size_t)(c2 + 1) * Lseq + row] = __float2bfloat16(v1 - __bfloat162float(h1));
    }
}

// ---------------------------------------------------------------------------
// 3-pass split GEMM, cp.async pipelined, 2 CTAs/SM (reg-capped).
// ---------------------------------------------------------------------------
#define LDA 40
#define TG3_TILE (128*LDA)
#define TG3_BUF  (4*TG3_TILE)
#define TG3_SMEM (2*TG3_BUF*2)   // 81920 bytes
template<int EPI>
__global__ __launch_bounds__(256, 2)
void tgemm3(const __nv_bfloat16* __restrict__ A, const __nv_bfloat16* __restrict__ B,
            float* __restrict__ C, int N,
            const float* __restrict__ alogit,
            __nv_bfloat16* __restrict__ Qb, __nv_bfloat16* __restrict__ Kb,
            __nv_bfloat16* __restrict__ Vth, __nv_bfloat16* __restrict__ Vtl) {
    extern __shared__ __nv_bfloat16 sm3[];

    const int tid = threadIdx.x;
    const int wid = tid >> 5, lane = tid & 31;
    const int m0 = blockIdx.y * 128, n0 = blockIdx.x * 128;
    const int wm = (wid >> 2) * 64, wn = (wid & 3) * 32;

    const int lr = tid >> 1, lc = (tid & 1) * 16;
    const __nv_bfloat16* Agh = A + (size_t)(m0 + lr) * K2 + lc;
    const __nv_bfloat16* Agl = Agh + 1024;
    const __nv_bfloat16* Bgh = B + (size_t)(n0 + lr) * K2 + lc;
    const __nv_bfloat16* Bgl = Bgh + 1024;
    const uint32_t smB = smem_u32(sm3);
    const uint32_t so = (uint32_t)(lr * LDA + lc) * 2;

    float acc[4][4][4];
#pragma unroll
    for (int i = 0; i < 4; i++)
#pragma unroll
        for (int j = 0; j < 4; j++)
#pragma unroll
            for (int k = 0; k < 4; k++) acc[i][j][k] = 0.f;

    auto ld_chunk = [&](int kt, int buf) {
        const uint32_t d = smB + (uint32_t)buf * TG3_BUF * 2;
        const int off = kt * 32;
        cp_async16(d + so,                      Agh + off);
        cp_async16(d + so + 16,                 Agh + off + 8);
        cp_async16(d + TG3_TILE*2 + so,         Agl + off);
        cp_async16(d + TG3_TILE*2 + so + 16,    Agl + off + 8);
        cp_async16(d + 2*TG3_TILE*2 + so,       Bgh + off);
        cp_async16(d + 2*TG3_TILE*2 + so + 16,  Bgh + off + 8);
        cp_async16(d + 3*TG3_TILE*2 + so,       Bgl + off);
        cp_async16(d + 3*TG3_TILE*2 + so + 16,  Bgl + off + 8);
    };

    ld_chunk(0, 0);
    CP_COMMIT();
    CP_WAIT0();
    __syncthreads();

    const int a_row = (lane & 15);
    const int a_koff = (lane >> 4) * 8;
    const int b_row = (lane & 7) + ((lane & 16) >> 1);
    const int b_koff = ((lane >> 3) & 1) * 8;

    for (int kt = 0; kt < 32; kt++) {
        const int cur = kt & 1;
        if (kt < 31) {
            ld_chunk(kt + 1, cur ^ 1);
            CP_COMMIT();
        }
        const uint32_t base = smB + (uint32_t)cur * TG3_BUF * 2;
        const uint32_t ahB = base;
        const uint32_t alB = base + TG3_TILE * 2;
        const uint32_t bhB = base + 2 * TG3_TILE * 2;
        const uint32_t blB = base + 3 * TG3_TILE * 2;
#pragma unroll
        for (int ks = 0; ks < 2; ks++) {
            const int k0 = ks * 16;
            // load ALL fragments first (no mid-stream ldsm bubble)
            uint32_t ah[4][4], al[4][4];
#pragma unroll
            for (int mt = 0; mt < 4; mt++) {
                ldsm_x4(ah[mt][0], ah[mt][1], ah[mt][2], ah[mt][3],
                        ahB + ((wm + mt * 16 + a_row) * LDA + k0 + a_koff) * 2);
                ldsm_x4(al[mt][0], al[mt][1], al[mt][2], al[mt][3],
                        alB + ((wm + mt * 16 + a_row) * LDA + k0 + a_koff) * 2);
            }
            uint32_t bh[2][4], bl[2][4];
#pragma unroll
            for (int nt2 = 0; nt2 < 2; nt2++) {
                ldsm_x4(bh[nt2][0], bh[nt2][1], bh[nt2][2], bh[nt2][3],
                        bhB + ((wn + nt2 * 16 + b_row) * LDA + k0 + b_koff) * 2);
                ldsm_x4(bl[nt2][0], bl[nt2][1], bl[nt2][2], bl[nt2][3],
                        blB + ((wn + nt2 * 16 + b_row) * LDA + k0 + b_koff) * 2);
            }
#pragma unroll
            for (int mt = 0; mt < 4; mt++)
#pragma unroll
                for (int nt = 0; nt < 4; nt++) {
                    uint32_t b0h = bh[nt >> 1][(nt & 1) * 2], b1h = bh[nt >> 1][(nt & 1) * 2 + 1];
                    mma_bf16(acc[mt][nt], ah[mt][0], ah[mt][1], ah[mt][2], ah[mt][3],
                             b0h, b1h);
                    mma_bf16(acc[mt][nt], ah[mt][0], ah[mt][1], ah[mt][2], ah[mt][3],
                             bl[nt >> 1][(nt & 1) * 2], bl[nt >> 1][(nt & 1) * 2 + 1]);
                    mma_bf16(acc[mt][nt], al[mt][0], al[mt][1], al[mt][2], al[mt][3],
                             b0h, b1h);
                }
        }
        if (kt < 31) {
            CP_WAIT0();
            __syncthreads();
        }
    }

    const int er = lane >> 2, ec = (lane & 3) * 2;
#pragma unroll
    for (int mt = 0; mt < 4; mt++) {
        const int row = m0 + wm + mt * 16 + er;
#pragma unroll
        for (int nt = 0; nt < 4; nt++) {
            const int col = n0 + wn + nt * 8 + ec;
            if (EPI == 0) {
                *(float2*)&C[(size_t)row * N + col] =
                    make_float2(acc[mt][nt][0], acc[mt][nt][1]);
                *(float2*)&C[(size_t)(row + 8) * N + col] =
                    make_float2(acc[mt][nt][2], acc[mt][nt][3]);
            } else {
                qkv_store(row,     col, acc[mt][nt][0], acc[mt][nt][1],
                          alogit, Qb, Kb, Vth, Vtl);
                qkv_store(row + 8, col, acc[mt][nt][2], acc[mt][nt][3],
                          alogit, Qb, Kb, Vth, Vtl);
            }
        }
    }
}

// ---------------------------------------------------------------------------
// Phase dims (64..79) packed bf16x3
// ---------------------------------------------------------------------------
__global__ __launch_bounds__(256)
void phase_pack(const float* __restrict__ QtKt,
                const float* __restrict__ bqp, const float* __restrict__ bkp,
                const float* __restrict__ alogit,
                __nv_bfloat16* __restrict__ Qb, __nv_bfloat16* __restrict__ Kb) {
    int idx = blockIdx.x * blockDim.x + threadIdx.x;
    if (idx >= Lseq * Pp) return;
    int q = idx >> 7, j = idx & 127;
    int h = j / PPH, i = j % PPH;
    int f = j >> 1;
    double invf = exp(-(double)f / 64.0 * log(10000.0));
    float pos = (float)((double)q * invf);
    float tq = QtKt[(size_t)q * 256 + j] + bqp[j] + pos;
    float tk = QtKt[(size_t)q * 256 + 128 + j] + bkp[j] + pos;
    float alpha = 1.f / (1.f + expf(-alogit[h]));
    float aps = alpha * PHASE_SCALE;
    size_t base = ((size_t)h * Lseq + q) * KQ3;
    float qv[2] = {aps * cosf(tq), aps * sinf(tq)};
    float kv[2] = {cosf(tk), sinf(tk)};
#pragma unroll
    for (int s = 0; s < 2; s++) {
        int d = 64 + s * 8 + i;
        __nv_bfloat16 qh = __float2bfloat16(qv[s]);
        __nv_bfloat16 ql = __float2bfloat16(qv[s] - __bfloat162float(qh));
        Qb[base + d] = qh; Qb[base + 80 + d] = ql; Qb[base + 160 + d] = qh;
        __nv_bfloat16 kh = __float2bfloat16(kv[s]);
        __nv_bfloat16 kl = __float2bfloat16(kv[s] - __bfloat162float(kh));
        Kb[base + d] = kh; Kb[base + 80 + d] = kh; Kb[base + 160 + d] = kl;
    }
}

// ---------------------------------------------------------------------------
// Tensor-core flash attention v4 (unchanged R9)
// ---------------------------------------------------------------------------
#define QS_STR 248
#define KS_STR 248
#define VS_STR 72
#define A4B_VH (64*KS_STR*2)
#define A4B_VL (A4B_VH + 64*VS_STR*2)
#define A4B_SZ (A4B_VL + 64*VS_STR*2)
#define A4_QS  (2*A4B_SZ)
#define A4_TOT (A4_QS + 128*QS_STR*2)

__global__ __launch_bounds__(256)
void attn4(const __nv_bfloat16* __restrict__ Qb, const __nv_bfloat16* __restrict__ Kb,
           const __nv_bfloat16* __restrict__ Vth, const __nv_bfloat16* __restrict__ Vtl,
           __nv_bfloat16* __restrict__ AOb) {
    extern __shared__ char smraw[];
    const uint32_t smB = smem_u32(smraw);
    __nv_bfloat16* Qs = (__nv_bfloat16*)(smraw + A4_QS);

    const int tid = threadIdx.x;
    const int wid = tid >> 5, lane = tid & 31;
    const int h = blockIdx.y;
    const int qt = (int)gridDim.x - 1 - (int)blockIdx.x;
    const int q0 = qt * 128;
    const int wm = wid * 16;

    const int a_row = (lane & 15);
    const int a_koff = (lane >> 4) * 8;
    const int b_row = (lane & 7) + ((lane & 16) >> 1);
    const int b_koff = ((lane >> 3) & 1) * 8;
    const int er = lane >> 2, ec = (lane & 3) * 2;

    const __nv_bfloat16* KbH = Kb + ((size_t)h * Lseq) * KQ3;
    const __nv_bfloat16* VhH = Vth + ((size_t)h * HD) * Lseq;
    const __nv_bfloat16* VlH = Vtl + ((size_t)h * HD) * Lseq;

    auto ld_tile = [&](int kt, int s) {
        const int k0 = kt * 64;
        const uint32_t stB = smB + (uint32_t)s * A4B_SZ;
        const __nv_bfloat16* ks = KbH + (size_t)k0 * KQ3;
        for (int i = tid; i < 64 * 30; i += 256) {
            int r = i / 30, c = i % 30;
            cp_async16(stB + ((uint32_t)(r * KS_STR + c * 8) << 1), ks + r * KQ3 + c * 8);
        }
        for (int i = tid; i < 64 * 8; i += 256) {
            int d = i >> 3, c = i & 7;
            uint32_t off = (uint32_t)(d * VS_STR + c * 8) << 1;
            const size_t go = (size_t)d * Lseq + k0 + c * 8;
            cp_async16(stB + A4B_VH + off, VhH + go);
            cp_async16(stB + A4B_VL + off, VlH + go);
        }
    };

    ld_tile(0, 0);
    CP_COMMIT();
    {
        const uint4* src = (const uint4*)(Qb + ((size_t)h * Lseq + q0) * KQ3);
        for (int i = tid; i < 128 * 30; i += 256) {
            int r = i / 30, c = i % 30;
            *(uint4*)&Qs[r * QS_STR + c * 8] = src[r * 30 + c];
        }
    }
    CP_WAIT0();
    __syncthreads();

    uint32_t qf[15][4];
    {
        const uint32_t qsB = smem_u32(Qs);
#pragma unroll
        for (int ks = 0; ks < 15; ks++)
            ldsm_x4(qf[ks][0], qf[ks][1], qf[ks][2], qf[ks][3],
                    qsB + ((wm + a_row) * QS_STR + ks * 16 + a_koff) * 2);
    }

    float m_run0 = NEG_BIG, m_run1 = NEG_BIG;
    float l_run0 = 0.f, l_run1 = 0.f;
    float acc_o[8][4];
#pragma unroll
    for (int d = 0; d < 8; d++)
#pragma unroll
        for (int c = 0; c < 4; c++) acc_o[d][c] = 0.f;

    const int nkt = 2 * qt + 2;
    for (int kt = 0; kt < nkt; kt++) {
        const int k0 = kt * 64;
        const int cur = kt & 1;
        if (kt + 1 < nkt) {
            ld_tile(kt + 1, cur ^ 1);
            CP_COMMIT();
        }
        const uint32_t stB = smB + (uint32_t)cur * A4B_SZ;
        const uint32_t ksB = stB;
        const uint32_t vhB = stB + A4B_VH;
        const uint32_t vlB = stB + A4B_VL;

        float s[8][4];
#pragma unroll
        for (int nt = 0; nt < 8; nt++)
#pragma unroll
            for (int c = 0; c < 4; c++) s[nt][c] = 0.f;
#pragma unroll
        for (int ks = 0; ks < 15; ks++) {
            const int kk = ks * 16;
            uint32_t bf[4][4];
#pragma unroll
            for (int nt2 = 0; nt2 < 4; nt2++)
                ldsm_x4(bf[nt2][0], bf[nt2][1], bf[nt2][2], bf[nt2][3],
                        ksB + ((nt2 * 16 + b_row) * KS_STR + kk + b_koff) * 2);
#pragma unroll
            for (int nt = 0; nt < 8; nt++)
                mma_bf16(s[nt], qf[ks][0], qf[ks][1], qf[ks][2], qf[ks][3],
                         bf[nt >> 1][(nt & 1) * 2], bf[nt >> 1][(nt & 1) * 2 + 1]);
        }

        if (kt >= 2 * qt) {
            const int r0 = q0 + wm + er, r1 = r0 + 8;
#pragma unroll
            for (int nt = 0; nt < 8; nt++) {
                const int c0 = k0 + nt * 8 + ec;
                if (c0     > r0) s[nt][0] = NEG_BIG;
                if (c0 + 1 > r0) s[nt][1] = NEG_BIG;
                if (c0     > r1) s[nt][2] = NEG_BIG;
                if (c0 + 1 > r1) s[nt][3] = NEG_BIG;
            }
        }

        float mx0 = s[0][0], mx1 = s[0][2];
#pragma unroll
        for (int nt = 0; nt < 8; nt++) {
            mx0 = fmaxf(mx0, fmaxf(s[nt][0], s[nt][1]));
            mx1 = fmaxf(mx1, fmaxf(s[nt][2], s[nt][3]));
        }
        mx0 = fmaxf(mx0, __shfl_xor_sync(0xffffffffu, mx0, 1));
        mx0 = fmaxf(mx0, __shfl_xor_sync(0xffffffffu, mx0, 2));
        mx1 = fmaxf(mx1, __shfl_xor_sync(0xffffffffu, mx1, 1));
        mx1 = fmaxf(mx1, __shfl_xor_sync(0xffffffffu, mx1, 2));
        float mnew0 = fmaxf(m_run0, mx0);
        float mnew1 = fmaxf(m_run1, mx1);
        float scale0 = __expf(m_run0 - mnew0);
        float scale1 = __expf(m_run1 - mnew1);

        float sum0 = 0.f, sum1 = 0.f;
#pragma unroll
        for (int nt = 0; nt < 8; nt++) {
            s[nt][0] = __expf(s[nt][0] - mnew0); sum0 += s[nt][0];
            s[nt][1] = __expf(s[nt][1] - mnew0); sum0 += s[nt][1];
            s[nt][2] = __expf(s[nt][2] - mnew1); sum1 += s[nt][2];
            s[nt][3] = __expf(s[nt][3] - mnew1); sum1 += s[nt][3];
        }
        sum0 += __shfl_xor_sync(0xffffffffu, sum0, 1);
        sum0 += __shfl_xor_sync(0xffffffffu, sum0, 2);
        sum1 += __shfl_xor_sync(0xffffffffu, sum1, 1);
        sum1 += __shfl_xor_sync(0xffffffffu, sum1, 2);
        m_run0 = mnew0; m_run1 = mnew1;
        l_run0 = l_run0 * scale0 + sum0;
        l_run1 = l_run1 * scale1 + sum1;

#pragma unroll
        for (int d = 0; d < 8; d++) {
            acc_o[d][0] *= scale0; acc_o[d][1] *= scale0;
            acc_o[d][2] *= scale1; acc_o[d][3] *= scale1;
        }

#pragma unroll
        for (int kk = 0; kk < 4; kk++) {
            float p00 = s[2*kk][0],   p01 = s[2*kk][1];
            float p02 = s[2*kk][2],   p03 = s[2*kk][3];
            float p10 = s[2*kk+1][0], p11 = s[2*kk+1][1];
            float p12 = s[2*kk+1][2], p13 = s[2*kk+1][3];
            uint32_t ah0 = pack_bf16x2(p00, p01);
            uint32_t ah1 = pack_bf16x2(p02, p03);
            uint32_t ah2 = pack_bf16x2(p10, p11);
            uint32_t ah3 = pack_bf16x2(p12, p13);
            __nv_bfloat162* hv;
            hv = (__nv_bfloat162*)&ah0;
            uint32_t al0 = pack_bf16x2(p00 - __bfloat162float(hv->x), p01 - __bfloat162float(hv->y));
            hv = (__nv_bfloat162*)&ah1;
            uint32_t al1 = pack_bf16x2(p02 - __bfloat162float(hv->x), p03 - __bfloat162float(hv->y));
            hv = (__nv_bfloat162*)&ah2;
            uint32_t al2 = pack_bf16x2(p10 - __bfloat162float(hv->x), p11 - __bfloat162float(hv->y));
            hv = (__nv_bfloat162*)&ah3;
            uint32_t al3 = pack_bf16x2(p12 - __bfloat162float(hv->x), p13 - __bfloat162float(hv->y));

            const int kko = kk * 16;
            uint32_t bh[4][4], bl[4][4];
#pragma unroll
            for (int dt2 = 0; dt2 < 4; dt2++) {
                ldsm_x4(bh[dt2][0], bh[dt2][1], bh[dt2][2], bh[dt2][3],
                        vhB + ((dt2 * 16 + b_row) * VS_STR + kko + b_koff) * 2);
                ldsm_x4(bl[dt2][0], bl[dt2][1], bl[dt2][2], bl[dt2][3],
                        vlB + ((dt2 * 16 + b_row) * VS_STR + kko + b_koff) * 2);
            }
#pragma unroll
            for (int dt = 0; dt < 8; dt++) {
                uint32_t b0h = bh[dt >> 1][(dt & 1) * 2], b1h = bh[dt >> 1][(dt & 1) * 2 + 1];
                uint32_t b0l = bl[dt >> 1][(dt & 1) * 2], b1l = bl[dt >> 1][(dt & 1) * 2 + 1];
                mma_bf16(acc_o[dt], ah0, ah1, ah2, ah3, b0h, b1h);
                mma_bf16(acc_o[dt], al0, al1, al2, al3, b0h, b1h);
                mma_bf16(acc_o[dt], ah0, ah1, ah2, ah3, b0l, b1l);
            }
        }
        CP_WAIT0();
        __syncthreads();
    }

    const float inv0 = 1.f / l_run0;
    const float inv1 = 1.f / l_run1;
    const int row0 = q0 + wm + er;
#pragma unroll
    for (int dt = 0; dt < 8; dt++) {
        const int col = h * HD + dt * 8 + ec;
        {
            float o0 = acc_o[dt][0] * inv0, o1 = acc_o[dt][1] * inv0;
            uint32_t hi = pack_bf16x2(o0, o1);
            __nv_bfloat162 h2 = *(__nv_bfloat162*)&hi;
            uint32_t lo = pack_bf16x2(o0 - __bfloat162float(h2.x),
                                      o1 - __bfloat162float(h2.y));
            *(uint32_t*)&AOb[(size_t)row0 * K2 + col] = hi;
            *(uint32_t*)&AOb[(size_t)row0 * K2 + 1024 + col] = lo;
        }
        {
            float o0 = acc_o[dt][2] * inv1, o1 = acc_o[dt][3] * inv1;
            uint32_t hi = pack_bf16x2(o0, o1);
            __nv_bfloat162 h2 = *(__nv_bfloat162*)&hi;
            uint32_t lo = pack_bf16x2(o0 - __bfloat162float(h2.x),
                                      o1 - __bfloat162float(h2.y));
            *(uint32_t*)&AOb[(size_t)(row0 + 8) * K2 + col] = hi;
            *(uint32_t*)&AOb[(size_t)(row0 + 8) * K2 + 1024 + col] = lo;
        }
    }
}

// ---------------------------------------------------------------------------
__global__ __launch_bounds__(256)
void ln_kernel(const float* __restrict__ xr, const float* __restrict__ proj,
               const float* __restrict__ gamma, const float* __restrict__ beta,
               float* __restrict__ out) {
    const int row = blockIdx.x;
    const int tid = threadIdx.x;
    __shared__ float red[2][8];
    const float* a = xr + (long)row * Dm;
    const float* b = proj + (long)row * Dm;
    float s = 0.f, s2 = 0.f;
    for (int i = tid; i < Dm; i += 256) {
        float v = a[i] + b[i];
        s += v; s2 += v * v;
    }
#pragma unroll
    for (int o = 16; o; o >>= 1) {
        s  += __shfl_xor_sync(0xffffffffu, s,  o);
        s2 += __shfl_xor_sync(0xffffffffu, s2, o);
    }
    if ((tid & 31) == 0) { red[0][tid >> 5] = s; red[1][tid >> 5] = s2; }
    __syncthreads();
    if (tid < 32) {
        s  = (tid < 8) ? red[0][tid] : 0.f;
        s2 = (tid < 8) ? red[1][tid] : 0.f;
#pragma unroll
        for (int o = 4; o; o >>= 1) {
            s  += __shfl_xor_sync(0xffffffffu, s,  o);
            s2 += __shfl_xor_sync(0xffffffffu, s2, o);
        }
        if (tid == 0) { red[0][0] = s; red[1][0] = s2; }
    }
    __syncthreads();
    float mu = red[0][0] * (1.f / Dm);
    float var = red[1][0] * (1.f / Dm) - mu * mu;
    float rstd = rsqrtf(var + 1e-5f);
    for (int i = tid; i < Dm; i += 256) {
        float v = a[i] + b[i];
        out[(long)row * Dm + i] = (v - mu) * rstd * gamma[i] + beta[i];
    }
}

// ---------------------------------------------------------------------------
extern "C" void kernel_launch(void* const* d_in, const int* in_sizes, int n_in,
                              void* d_out, int out_size) {
    const float* x_real = (const float*)d_in[0];
    const float* x_imag = (const float*)d_in[1];
    const float* Wq     = (const float*)d_in[2];
    const float* Wk     = (const float*)d_in[3];
    const float* Wv     = (const float*)d_in[4];
    const float* Wqp    = (const float*)d_in[5];
    const float* bqp    = (const float*)d_in[6];
    const float* Wkp    = (const float*)d_in[7];
    const float* bkp    = (const float*)d_in[8];
    const float* Wo     = (const float*)d_in[9];
    const float* alogit = (const float*)d_in[10];
    const float* lng    = (const float*)d_in[11];
    const float* lnb    = (const float*)d_in[12];

    float *pQtKt, *pP2;
    __nv_bfloat16 *pAb, *pAib, *pAOb, *pBqkv, *pBp2, *pBo;
    __nv_bfloat16 *pQb, *pKb, *pVth, *pVtl;
    cudaGetSymbolAddress((void**)&pQtKt, g_QtKt);
    cudaGetSymbolAddress((void**)&pP2,   g_P2);
    cudaGetSymbolAddress((void**)&pAb,   g_Ab);
    cudaGetSymbolAddress((void**)&pAib,  g_Aib);
    cudaGetSymbolAddress((void**)&pAOb,  g_AOb);
    cudaGetSymbolAddress((void**)&pBqkv, g_Bqkv);
    cudaGetSymbolAddress((void**)&pBp2,  g_Bp2);
    cudaGetSymbolAddress((void**)&pBo,   g_Bo);
    cudaGetSymbolAddress((void**)&pQb,   g_Qb);
    cudaGetSymbolAddress((void**)&pKb,   g_Kb);
    cudaGetSymbolAddress((void**)&pVth,  g_Vth);
    cudaGetSymbolAddress((void**)&pVtl,  g_Vtl);

    cudaFuncSetAttribute(tgemm3<0>, cudaFuncAttributeMaxDynamicSharedMemorySize, TG3_SMEM);
    cudaFuncSetAttribute(tgemm3<1>, cudaFuncAttributeMaxDynamicSharedMemorySize, TG3_SMEM);
    cudaFuncSetAttribute(attn4, cudaFuncAttributeMaxDynamicSharedMemorySize, A4_TOT);

    dim3 cbg(Dm / 32, Dm / 32);
    dim3 cbp(Pp / 32, Dm / 32);

    conv_a2<<<(Lseq * Dm) / 1024, 256>>>(x_real, pAb);
    conv_b2<<<cbg, 256>>>(Wq, pBqkv,                      Dm);
    conv_b2<<<cbg, 256>>>(Wk, pBqkv + (size_t)Dm * K2,    Dm);
    conv_b2<<<cbg, 256>>>(Wv, pBqkv + (size_t)2 * Dm * K2, Dm);
    conv_a2<<<(Lseq * Dm) / 1024, 256>>>(x_imag, pAib);
    conv_b2<<<cbp, 256>>>(Wqp, pBp2,                  Pp);
    conv_b2<<<cbp, 256>>>(Wkp, pBp2 + (size_t)Pp * K2, Pp);
    conv_b2<<<cbg, 256>>>(Wo, pBo, Dm);

    // QKV GEMM with fused pack epilogue -> Qb/Kb (content dims) + Vth/Vtl
    tgemm3<1><<<dim3(3 * Dm / 128, Lseq / 128), 256, TG3_SMEM>>>(
        pAb, pBqkv, nullptr, 3 * Dm, alogit, pQb, pKb, pVth, pVtl);
    // phase GEMM (fp32 out) then phase dims of Qb/Kb
    tgemm3<0><<<dim3(2 * Pp / 128, Lseq / 128), 256, TG3_SMEM>>>(
        pAib, pBp2, pQtKt, 2 * Pp, nullptr, nullptr, nullptr, nullptr, nullptr);
    phase_pack<<<(Lseq * Pp) / 256, 256>>>(pQtKt, bqp, bkp, alogit, pQb, pKb);

    // attention with fused [hi|lo] output pack
    attn4<<<dim3(Lseq / 128, Hh), 256, A4_TOT>>>(pQb, pKb, pVth, pVtl, pAOb);

    tgemm3<0><<<dim3(Dm / 128, Lseq / 128), 256, TG3_SMEM>>>(
        pAOb, pBo, pP2, Dm, nullptr, nullptr, nullptr, nullptr, nullptr);
    ln_kernel<<<Lseq, 256>>>(x_real, pP2, lng, lnb, (float*)d_out);

    if (out_size >= 2 * Lseq * Dm) {
        cudaMemcpyAsync((float*)d_out + (long)Lseq * Dm, x_imag,
                        (size_t)Lseq * Dm * sizeof(float),
                        cudaMemcpyDeviceToDevice);
    }
}